// round 5
// baseline (speedup 1.0000x reference)
#include <cuda_runtime.h>
#include <cstdint>
#include <cstddef>

#define BHX    48
#define NTOK   8192
#define DIMX   64
#define MSEL   128
#define NSPLIT 64
#define PITCH  132   // smem pitch (multiple of 4 for float4, odd*4 banks on transpose stores)

// ------------------------- scratch (static device memory; no allocs) -------------------------
__device__ float d_nc [BHX*MSEL*DIMX];
__device__ float d_nr [BHX*MSEL*DIMX];
__device__ float d_K2m[BHX*MSEL*MSEL];
__device__ float d_KVm[BHX*MSEL*MSEL];
__device__ float d_Tm [BHX*MSEL*MSEL];
__device__ float d_Em [BHX*MSEL*MSEL];
__device__ float d_Vm0[BHX*MSEL*MSEL];
__device__ float d_Vm1[BHX*MSEL*MSEL];
__device__ float d_Zm [BHX*MSEL*DIMX];
__device__ float d_Wm [BHX*MSEL*DIMX];
__device__ unsigned int d_gmax_bits;
__device__ float d_pmax[BHX*NSPLIT*MSEL];
__device__ float d_psum[BHX*NSPLIT*MSEL];
__device__ float d_pZ  [(size_t)BHX*NSPLIT*MSEL*DIMX];   // ~100 MB

// ------------------------- helpers -------------------------
__device__ __forceinline__ float grp_max(float v) {
    v = fmaxf(v, __shfl_xor_sync(0xffffffffu, v, 8));
    v = fmaxf(v, __shfl_xor_sync(0xffffffffu, v, 4));
    v = fmaxf(v, __shfl_xor_sync(0xffffffffu, v, 2));
    v = fmaxf(v, __shfl_xor_sync(0xffffffffu, v, 1));
    return v;
}
__device__ __forceinline__ float grp_sum(float v) {
    v += __shfl_xor_sync(0xffffffffu, v, 8);
    v += __shfl_xor_sync(0xffffffffu, v, 4);
    v += __shfl_xor_sync(0xffffffffu, v, 2);
    v += __shfl_xor_sync(0xffffffffu, v, 1);
    return v;
}

// stage a [128 x 64] row-major gmem tile transposed into smem: dst[k*PITCH + m] = g[m*64+k]
__device__ __forceinline__ void load_tileT(float* dst, const float* __restrict__ g, int tid) {
    for (int i = tid; i < MSEL*DIMX; i += 256) {
        int m = i >> 6, k = i & 63;
        dst[k*PITCH + m] = g[i];
    }
}

// acc[8][8] += A(128x64) @ B(128x64)^T tile product; As/Bs are k-major transposed tiles
__device__ __forceinline__ void mm128(const float* As, const float* Bs,
                                      float acc[8][8], int ty, int tx) {
#pragma unroll 8
    for (int k = 0; k < DIMX; k++) {
        float4 a0 = *reinterpret_cast<const float4*>(&As[k*PITCH + ty*8]);
        float4 a1 = *reinterpret_cast<const float4*>(&As[k*PITCH + ty*8 + 4]);
        float4 b0 = *reinterpret_cast<const float4*>(&Bs[k*PITCH + tx*8]);
        float4 b1 = *reinterpret_cast<const float4*>(&Bs[k*PITCH + tx*8 + 4]);
        float a[8] = {a0.x,a0.y,a0.z,a0.w,a1.x,a1.y,a1.z,a1.w};
        float b[8] = {b0.x,b0.y,b0.z,b0.w,b1.x,b1.y,b1.z,b1.w};
#pragma unroll
        for (int i = 0; i < 8; i++)
#pragma unroll
            for (int j = 0; j < 8; j++)
                acc[i][j] += a[i] * b[j];
    }
}

// ------------------------- kernel 1: top-k select + sort + gather -------------------------
// grid (48, 2): y==0 -> K -> d_nc ; y==1 -> Q -> d_nr. 256 threads.
__global__ __launch_bounds__(256) void topk_gather(const float* __restrict__ Qg,
                                                   const float* __restrict__ Kg) {
    __shared__ float vals[NTOK];
    __shared__ int   sel[MSEL];
    __shared__ int   sorted[MSEL];
    __shared__ float wmax[8];
    __shared__ int   widx[8];
    int hh = blockIdx.x, which = blockIdx.y, tid = threadIdx.x;
    const float* src = (which == 0 ? Kg : Qg) + (size_t)hh * NTOK * DIMX;

    if (hh == 0 && which == 0 && tid == 0) d_gmax_bits = 0u;  // reset global max each launch

    for (int i = tid; i < NTOK; i += 256) vals[i] = src[(size_t)i * DIMX];
    if (tid == 0) vals[0] = -3.402823466e38f;   // index 0 excluded from top-k, added back later
    __syncthreads();

    for (int r = 0; r < MSEL - 1; r++) {
        float bv = -3.402823466e38f; int bi = NTOK;
        for (int k = tid; k < NTOK; k += 256) {
            float v = vals[k];
            if (v > bv) { bv = v; bi = k; }
        }
#pragma unroll
        for (int o = 16; o > 0; o >>= 1) {
            float ov = __shfl_down_sync(0xffffffffu, bv, o);
            int   oi = __shfl_down_sync(0xffffffffu, bi, o);
            if (ov > bv || (ov == bv && oi < bi)) { bv = ov; bi = oi; }
        }
        if ((tid & 31) == 0) { wmax[tid >> 5] = bv; widx[tid >> 5] = bi; }
        __syncthreads();
        if (tid == 0) {
            for (int w = 1; w < 8; w++)
                if (wmax[w] > bv || (wmax[w] == bv && widx[w] < bi)) { bv = wmax[w]; bi = widx[w]; }
            sel[r] = bi;
            vals[bi] = -3.402823466e38f;
        }
        __syncthreads();
    }
    if (tid == 0) sel[MSEL - 1] = 0;
    __syncthreads();

    if (tid < MSEL) {                       // rank sort (all indices distinct)
        int my = sel[tid], rank = 0;
        for (int j = 0; j < MSEL; j++) rank += (sel[j] < my);
        sorted[rank] = my;
    }
    __syncthreads();

    float* dst = (which == 0 ? d_nc : d_nr) + (size_t)hh * MSEL * DIMX;
    for (int i = tid; i < MSEL * DIMX; i += 256) {
        int p = i >> 6, d = i & 63;
        dst[i] = src[(size_t)sorted[p] * DIMX + d];
    }
}

// ------------------------- kernel 2: kernel_2 = softmax(nr @ nc^T), colsum -> global max ----
__global__ __launch_bounds__(256) void mker() {
    extern __shared__ float sm[];
    float* As = sm;
    float* Bs = sm + DIMX * PITCH;
    float* cs = sm + 2 * DIMX * PITCH;     // 128 column sums
    int hh = blockIdx.x, tid = threadIdx.x;
    int ty = tid >> 4, tx = tid & 15;
    load_tileT(As, d_nr + (size_t)hh * MSEL * DIMX, tid);
    load_tileT(Bs, d_nc + (size_t)hh * MSEL * DIMX, tid);
    if (tid < MSEL) cs[tid] = 0.f;
    __syncthreads();

    float acc[8][8] = {};
    mm128(As, Bs, acc, ty, tx);

    float* K2h = d_K2m + (size_t)hh * MSEL * MSEL;
    float colp[8] = {};
#pragma unroll
    for (int i = 0; i < 8; i++) {
        float mx = acc[i][0];
#pragma unroll
        for (int j = 1; j < 8; j++) mx = fmaxf(mx, acc[i][j]);
        mx = grp_max(mx);
        float s = 0.f;
#pragma unroll
        for (int j = 0; j < 8; j++) { acc[i][j] = __expf(acc[i][j] - mx); s += acc[i][j]; }
        s = grp_sum(s);
        float inv = 1.f / s;
#pragma unroll
        for (int j = 0; j < 8; j++) {
            float p = acc[i][j] * inv;
            K2h[(ty*8 + i) * MSEL + tx*8 + j] = p;
            colp[j] += p;
        }
    }
#pragma unroll
    for (int j = 0; j < 8; j++) atomicAdd(&cs[tx*8 + j], colp[j]);
    __syncthreads();
    if (tid < MSEL) atomicMax(&d_gmax_bits, __float_as_uint(cs[tid]));  // colsums > 0
}

// ------------------------- kernel 3: split-K flash for kernel_3 @ V -------------------------
// grid (48, 64): each CTA does 128 nr-rows x 128-key chunk, stores partial max/sum/Z.
__global__ __launch_bounds__(256) void r1ker(const float* __restrict__ Kg,
                                             const float* __restrict__ Vg) {
    extern __shared__ float sm[];
    float* As = sm;
    float* Bs = sm + DIMX * PITCH;
    float* Pt = sm;                         // aliases As+Bs (2*64*132 == 128*132)
    float* Vs = sm + MSEL * PITCH;          // 128 x 64
    int hh = blockIdx.x, s = blockIdx.y, tid = threadIdx.x;
    int ty = tid >> 4, tx = tid & 15;
    const float* Kc = Kg + ((size_t)hh * NTOK + s * MSEL) * DIMX;
    const float* Vc = Vg + ((size_t)hh * NTOK + s * MSEL) * DIMX;
    load_tileT(As, d_nr + (size_t)hh * MSEL * DIMX, tid);
    load_tileT(Bs, Kc, tid);
    for (int i = tid; i < MSEL * DIMX; i += 256) Vs[i] = Vc[i];
    __syncthreads();

    float acc[8][8] = {};
    mm128(As, Bs, acc, ty, tx);

    float rmax[8], rsum[8];
#pragma unroll
    for (int i = 0; i < 8; i++) {
        float mx = acc[i][0];
#pragma unroll
        for (int j = 1; j < 8; j++) mx = fmaxf(mx, acc[i][j]);
        mx = grp_max(mx);
        float su = 0.f;
#pragma unroll
        for (int j = 0; j < 8; j++) { acc[i][j] = __expf(acc[i][j] - mx); su += acc[i][j]; }
        su = grp_sum(su);
        rmax[i] = mx; rsum[i] = su;
    }
    __syncthreads();                         // done reading As/Bs
#pragma unroll
    for (int i = 0; i < 8; i++) {            // Pt[m][k] layout, float4 stores
        *reinterpret_cast<float4*>(&Pt[(ty*8 + i) * PITCH + tx*8]) =
            make_float4(acc[i][0], acc[i][1], acc[i][2], acc[i][3]);
        *reinterpret_cast<float4*>(&Pt[(ty*8 + i) * PITCH + tx*8 + 4]) =
            make_float4(acc[i][4], acc[i][5], acc[i][6], acc[i][7]);
    }
    __syncthreads();

    float acc2[8][4] = {};
#pragma unroll 4
    for (int k = 0; k < MSEL; k++) {
        float4 b = *reinterpret_cast<const float4*>(&Vs[k * DIMX + tx*4]);
#pragma unroll
        for (int i = 0; i < 8; i++) {
            float a = Pt[(ty*8 + i) * PITCH + k];
            acc2[i][0] += a * b.x; acc2[i][1] += a * b.y;
            acc2[i][2] += a * b.z; acc2[i][3] += a * b.w;
        }
    }
    size_t base = (size_t)(hh * NSPLIT + s) * MSEL;
    if (tx == 0) {
#pragma unroll
        for (int i = 0; i < 8; i++) {
            d_pmax[base + ty*8 + i] = rmax[i];
            d_psum[base + ty*8 + i] = rsum[i];
        }
    }
#pragma unroll
    for (int i = 0; i < 8; i++)
        *reinterpret_cast<float4*>(&d_pZ[(base + ty*8 + i) * DIMX + tx*4]) =
            make_float4(acc2[i][0], acc2[i][1], acc2[i][2], acc2[i][3]);
}

// ------------------------- kernel 4: combine splits -> Z = kernel_3 @ V -------------------
__global__ void combiner() {
    int hh = blockIdx.x;
    int r  = blockIdx.y * 16 + threadIdx.y;
    int d  = threadIdx.x * 4;
    const float* pm = d_pmax + (size_t)hh * NSPLIT * MSEL;
    const float* ps = d_psum + (size_t)hh * NSPLIT * MSEL;
    float M = -3.402823466e38f;
    for (int s = 0; s < NSPLIT; s++) M = fmaxf(M, pm[s * MSEL + r]);
    float l = 0.f;
    float4 z = make_float4(0.f, 0.f, 0.f, 0.f);
    for (int s = 0; s < NSPLIT; s++) {
        float w = __expf(pm[s * MSEL + r] - M);
        l += ps[s * MSEL + r] * w;
        float4 pz = *reinterpret_cast<const float4*>(
            &d_pZ[((size_t)(hh * NSPLIT + s) * MSEL + r) * DIMX + d]);
        z.x += w * pz.x; z.y += w * pz.y; z.z += w * pz.z; z.w += w * pz.w;
    }
    float inv = 1.f / l;
    *reinterpret_cast<float4*>(&d_Zm[((size_t)hh * MSEL + r) * DIMX + d]) =
        make_float4(z.x * inv, z.y * inv, z.z * inv, z.w * inv);
}

// ------------------------- Newton-Schulz machinery -------------------------
__device__ __forceinline__ float* mat_ptr(int s) {
    switch (s) {
        case 0: return d_K2m; case 1: return d_KVm; case 2: return d_Tm;
        case 3: return d_Em;  case 4: return d_Vm0; default: return d_Vm1;
    }
}

__global__ __launch_bounds__(256) void vminit() {     // Vm0 = K2^T / global_max
    int hh = blockIdx.x;
    float inv = 1.f / __uint_as_float(d_gmax_bits);
    const float* K2h = d_K2m + (size_t)hh * MSEL * MSEL;
    float* Vh = d_Vm0 + (size_t)hh * MSEL * MSEL;
    for (int i = threadIdx.x; i < MSEL * MSEL; i += 256) {
        int r = i >> 7, c = i & 127;
        Vh[i] = K2h[c * MSEL + r] * inv;
    }
}

// C = c0*I + c1*(A@B) + c2*A  on [128x128] per head; grid (48, 2, 2), 64x64 tiles
__global__ __launch_bounds__(256) void nmm(int selA, int selB, int selC,
                                           float c0, float c1, float c2) {
    __shared__ float As[32][65];
    __shared__ float Bs[32][65];
    int hh = blockIdx.x;
    const float* A = mat_ptr(selA) + (size_t)hh * MSEL * MSEL;
    const float* B = mat_ptr(selB) + (size_t)hh * MSEL * MSEL;
    float* C = mat_ptr(selC) + (size_t)hh * MSEL * MSEL;
    int r0 = blockIdx.y * 64, cc = blockIdx.z * 64;
    int tid = threadIdx.x, ty = tid >> 4, tx = tid & 15;
    float acc[4][4] = {};
    for (int kc = 0; kc < MSEL; kc += 32) {
        for (int i = tid; i < 2048; i += 256) {
            int m = i >> 5, k = i & 31;
            As[k][m] = A[(r0 + m) * MSEL + kc + k];
        }
        for (int i = tid; i < 2048; i += 256) {
            int k = i >> 6, n = i & 63;
            Bs[k][n] = B[(kc + k) * MSEL + cc + n];
        }
        __syncthreads();
#pragma unroll 8
        for (int k = 0; k < 32; k++) {
            float a[4], b[4];
#pragma unroll
            for (int i = 0; i < 4; i++) a[i] = As[k][ty*4 + i];
#pragma unroll
            for (int j = 0; j < 4; j++) b[j] = Bs[k][tx*4 + j];
#pragma unroll
            for (int i = 0; i < 4; i++)
#pragma unroll
                for (int j = 0; j < 4; j++)
                    acc[i][j] += a[i] * b[j];
        }
        __syncthreads();
    }
#pragma unroll
    for (int i = 0; i < 4; i++)
#pragma unroll
        for (int j = 0; j < 4; j++) {
            int gr = r0 + ty*4 + i, gc = cc + tx*4 + j;
            float v = c1 * acc[i][j] + c2 * A[gr * MSEL + gc];
            if (gr == gc) v += c0;
            C[gr * MSEL + gc] = v;
        }
}

// W = Vm_final @ Z  (128x64), grid (48, 2)
__global__ __launch_bounds__(256) void wker(int selVm) {
    __shared__ float As[32][65];
    __shared__ float Bs[32][65];
    int hh = blockIdx.x;
    const float* Vm = mat_ptr(selVm) + (size_t)hh * MSEL * MSEL;
    const float* Z  = d_Zm + (size_t)hh * MSEL * DIMX;
    int r0 = blockIdx.y * 64;
    int tid = threadIdx.x, ty = tid >> 4, tx = tid & 15;
    float acc[4][4] = {};
    for (int kc = 0; kc < MSEL; kc += 32) {
        for (int i = tid; i < 2048; i += 256) {
            int m = i >> 5, k = i & 31;
            As[k][m] = Vm[(r0 + m) * MSEL + kc + k];
        }
        for (int i = tid; i < 2048; i += 256) {
            int k = i >> 6, n = i & 63;
            Bs[k][n] = Z[(kc + k) * DIMX + n];
        }
        __syncthreads();
#pragma unroll 8
        for (int k = 0; k < 32; k++) {
            float a[4], b[4];
#pragma unroll
            for (int i = 0; i < 4; i++) a[i] = As[k][ty*4 + i];
#pragma unroll
            for (int j = 0; j < 4; j++) b[j] = Bs[k][tx*4 + j];
#pragma unroll
            for (int i = 0; i < 4; i++)
#pragma unroll
                for (int j = 0; j < 4; j++)
                    acc[i][j] += a[i] * b[j];
        }
        __syncthreads();
    }
#pragma unroll
    for (int i = 0; i < 4; i++)
#pragma unroll
        for (int j = 0; j < 4; j++)
            d_Wm[(size_t)hh * MSEL * DIMX + (r0 + ty*4 + i) * DIMX + tx*4 + j] = acc[i][j];
}

// ------------------------- final: X = softmax(Q @ nc^T) @ W -------------------------
// grid (48, 64): 128 Q-rows per CTA; softmax is complete (128 cols total)
__global__ __launch_bounds__(256) void eker(const float* __restrict__ Qg,
                                            float* __restrict__ Xg) {
    extern __shared__ float sm[];
    float* As = sm;
    float* Bs = sm + DIMX * PITCH;
    float* Pt = sm;
    float* Ws = sm + MSEL * PITCH;
    int hh = blockIdx.x, q0 = blockIdx.y * MSEL, tid = threadIdx.x;
    int ty = tid >> 4, tx = tid & 15;
    load_tileT(As, Qg + ((size_t)hh * NTOK + q0) * DIMX, tid);
    load_tileT(Bs, d_nc + (size_t)hh * MSEL * DIMX, tid);
    for (int i = tid; i < MSEL * DIMX; i += 256) Ws[i] = d_Wm[(size_t)hh * MSEL * DIMX + i];
    __syncthreads();

    float acc[8][8] = {};
    mm128(As, Bs, acc, ty, tx);

    float rinv[8];
#pragma unroll
    for (int i = 0; i < 8; i++) {
        float mx = acc[i][0];
#pragma unroll
        for (int j = 1; j < 8; j++) mx = fmaxf(mx, acc[i][j]);
        mx = grp_max(mx);
        float su = 0.f;
#pragma unroll
        for (int j = 0; j < 8; j++) { acc[i][j] = __expf(acc[i][j] - mx); su += acc[i][j]; }
        su = grp_sum(su);
        rinv[i] = 1.f / su;
    }
    __syncthreads();
#pragma unroll
    for (int i = 0; i < 8; i++) {
        *reinterpret_cast<float4*>(&Pt[(ty*8 + i) * PITCH + tx*8]) =
            make_float4(acc[i][0], acc[i][1], acc[i][2], acc[i][3]);
        *reinterpret_cast<float4*>(&Pt[(ty*8 + i) * PITCH + tx*8 + 4]) =
            make_float4(acc[i][4], acc[i][5], acc[i][6], acc[i][7]);
    }
    __syncthreads();

    float acc2[8][4] = {};
#pragma unroll 4
    for (int k = 0; k < MSEL; k++) {
        float4 b = *reinterpret_cast<const float4*>(&Ws[k * DIMX + tx*4]);
#pragma unroll
        for (int i = 0; i < 8; i++) {
            float a = Pt[(ty*8 + i) * PITCH + k];
            acc2[i][0] += a * b.x; acc2[i][1] += a * b.y;
            acc2[i][2] += a * b.z; acc2[i][3] += a * b.w;
        }
    }
#pragma unroll
    for (int i = 0; i < 8; i++) {
        size_t o = ((size_t)hh * NTOK + q0 + ty*8 + i) * DIMX + tx*4;
        *reinterpret_cast<float4*>(&Xg[o]) =
            make_float4(acc2[i][0] * rinv[i], acc2[i][1] * rinv[i],
                        acc2[i][2] * rinv[i], acc2[i][3] * rinv[i]);
    }
}

// ------------------------- launch -------------------------
extern "C" void kernel_launch(void* const* d_in, const int* in_sizes, int n_in,
                              void* d_out, int out_size) {
    const float* Q = (const float*)d_in[0];
    const float* K = (const float*)d_in[1];
    const float* V = (const float*)d_in[2];
    float* X = (float*)d_out;

    const int SMEM_MK  = (2 * DIMX * PITCH + MSEL) * 4;       // 68096 B
    const int SMEM_BIG = (MSEL * PITCH + MSEL * DIMX) * 4;    // 100352 B
    cudaFuncSetAttribute(mker,  cudaFuncAttributeMaxDynamicSharedMemorySize, SMEM_MK);
    cudaFuncSetAttribute(r1ker, cudaFuncAttributeMaxDynamicSharedMemorySize, SMEM_BIG);
    cudaFuncSetAttribute(eker,  cudaFuncAttributeMaxDynamicSharedMemorySize, SMEM_BIG);

    topk_gather<<<dim3(BHX, 2), 256>>>(Q, K);
    mker<<<BHX, 256, SMEM_MK>>>();
    r1ker<<<dim3(BHX, NSPLIT), 256, SMEM_BIG>>>(K, V);
    combiner<<<dim3(BHX, 8), dim3(16, 16)>>>();
    vminit<<<BHX, 256>>>();

    // Newton-Schulz: Vm <- 0.25*Vm@(13I - KV@(15I - KV@(7I - KV))), KV = Km@Vm
    int cur = 4, nxt = 5;
    for (int it = 0; it < 6; it++) {
        nmm<<<dim3(BHX, 2, 2), 256>>>(0,  cur, 1,  0.f,  1.f,   0.f);  // KV = Km@Vm
        nmm<<<dim3(BHX, 2, 2), 256>>>(1,  1,   2, 15.f,  1.f,  -7.f);  // T  = 15I + KV@KV - 7KV
        nmm<<<dim3(BHX, 2, 2), 256>>>(1,  2,   3, 13.f, -1.f,   0.f);  // E  = 13I - KV@T
        nmm<<<dim3(BHX, 2, 2), 256>>>(cur, 3, nxt, 0.f,  0.25f, 0.f);  // Vm = 0.25*Vm@E
        int t = cur; cur = nxt; nxt = t;
    }

    wker<<<dim3(BHX, 2), 256>>>(cur);                       // W = Vm @ Z
    eker<<<dim3(BHX, NTOK / MSEL), 256, SMEM_BIG>>>(Q, X);  // X = softmax(Q@nc^T) @ W
}

// round 7
// speedup vs baseline: 1.1432x; 1.1432x over previous
#include <cuda_runtime.h>
#include <cuda_bf16.h>
#include <cstdint>
#include <cstddef>

#define BHX    48
#define NTOK   8192
#define DIMX   64
#define MSEL   128
#define NSPLIT 64
#define PITCH  132

// ======================= mma.sync / ldmatrix helpers =======================
__device__ __forceinline__ uint32_t smem_to_u32(const void* p) {
    uint32_t a;
    asm("{ .reg .u64 t; cvta.to.shared.u64 t, %1; cvt.u32.u64 %0, t; }" : "=r"(a) : "l"(p));
    return a;
}
#define LDSM_X4(r0, r1, r2, r3, addr) \
    asm volatile("ldmatrix.sync.aligned.m8n8.x4.shared.b16 {%0,%1,%2,%3}, [%4];" \
                 : "=r"(r0), "=r"(r1), "=r"(r2), "=r"(r3) : "r"(addr))
#define LDSM_X4_T(r0, r1, r2, r3, addr) \
    asm volatile("ldmatrix.sync.aligned.m8n8.x4.trans.shared.b16 {%0,%1,%2,%3}, [%4];" \
                 : "=r"(r0), "=r"(r1), "=r"(r2), "=r"(r3) : "r"(addr))
__device__ __forceinline__ void mma_bf16(float* c, uint32_t a0, uint32_t a1, uint32_t a2, uint32_t a3,
                                         uint32_t b0, uint32_t b1) {
    asm volatile("mma.sync.aligned.m16n8k16.row.col.f32.bf16.bf16.f32 "
                 "{%0,%1,%2,%3}, {%4,%5,%6,%7}, {%8,%9}, {%0,%1,%2,%3};"
                 : "+f"(c[0]), "+f"(c[1]), "+f"(c[2]), "+f"(c[3])
                 : "r"(a0), "r"(a1), "r"(a2), "r"(a3), "r"(b0), "r"(b1));
}
__device__ __forceinline__ void bf16split(float v, __nv_bfloat16& h, __nv_bfloat16& l) {
    h = __float2bfloat16(v);
    l = __float2bfloat16(v - __bfloat162float(h));
}

// smem regions (bytes). bf16 tiles: A/B/V [128 rows x 72 halves] (144B pitch).
// P tiles [128 x 136 halves] (272B pitch) alias the dead A+B regions.
#define OFF_AH   0
#define OFF_AL   18432
#define OFF_BH   36864
#define OFF_BL   55296
#define OFF_VH   73728
#define OFF_VL   92160
#define SMEM_TC  110592
#define OFF_PH   0
#define OFF_PL   36864

// ======================= scratch =======================
__device__ float d_nc [BHX*MSEL*DIMX];
__device__ float d_nr [BHX*MSEL*DIMX];
__device__ float d_K2m[BHX*MSEL*MSEL];
__device__ float d_KVm[BHX*MSEL*MSEL];
__device__ float d_Tm [BHX*MSEL*MSEL];
__device__ float d_Em [BHX*MSEL*MSEL];
__device__ float d_Vm0[BHX*MSEL*MSEL];
__device__ float d_Vm1[BHX*MSEL*MSEL];
__device__ float d_Zm [BHX*MSEL*DIMX];
__device__ float d_Wm [BHX*MSEL*DIMX];
__device__ unsigned int d_gmax_bits;
__device__ float d_pmax[BHX*NSPLIT*MSEL];
__device__ float d_psum[BHX*NSPLIT*MSEL];
__device__ float d_pZ  [(size_t)BHX*NSPLIT*MSEL*DIMX];

// ======================= SIMT helpers =======================
__device__ __forceinline__ float grp_max(float v) {
    v = fmaxf(v, __shfl_xor_sync(0xffffffffu, v, 8));
    v = fmaxf(v, __shfl_xor_sync(0xffffffffu, v, 4));
    v = fmaxf(v, __shfl_xor_sync(0xffffffffu, v, 2));
    v = fmaxf(v, __shfl_xor_sync(0xffffffffu, v, 1));
    return v;
}
__device__ __forceinline__ float grp_sum(float v) {
    v += __shfl_xor_sync(0xffffffffu, v, 8);
    v += __shfl_xor_sync(0xffffffffu, v, 4);
    v += __shfl_xor_sync(0xffffffffu, v, 2);
    v += __shfl_xor_sync(0xffffffffu, v, 1);
    return v;
}
__device__ __forceinline__ void load_tileT(float* dst, const float* __restrict__ g, int tid) {
    for (int i = tid; i < MSEL*DIMX; i += 256) {
        int m = i >> 6, k = i & 63;
        dst[k*PITCH + m] = g[i];
    }
}
__device__ __forceinline__ void mm128(const float* As, const float* Bs,
                                      float acc[8][8], int ty, int tx) {
#pragma unroll 8
    for (int k = 0; k < DIMX; k++) {
        float4 a0 = *reinterpret_cast<const float4*>(&As[k*PITCH + ty*8]);
        float4 a1 = *reinterpret_cast<const float4*>(&As[k*PITCH + ty*8 + 4]);
        float4 b0 = *reinterpret_cast<const float4*>(&Bs[k*PITCH + tx*8]);
        float4 b1 = *reinterpret_cast<const float4*>(&Bs[k*PITCH + tx*8 + 4]);
        float a[8] = {a0.x,a0.y,a0.z,a0.w,a1.x,a1.y,a1.z,a1.w};
        float b[8] = {b0.x,b0.y,b0.z,b0.w,b1.x,b1.y,b1.z,b1.w};
#pragma unroll
        for (int i = 0; i < 8; i++)
#pragma unroll
            for (int j = 0; j < 8; j++)
                acc[i][j] += a[i] * b[j];
    }
}

// stage [128x64] fp32 -> split bf16 padded tile (pitch 72 halves)
__device__ __forceinline__ void stage_split(char* smem, int offH, int offL,
                                            const float* __restrict__ g, int tid) {
    for (int i = tid; i < 4096; i += 256) {
        int r = i >> 5, c2 = (i & 31) * 2;
        float2 v = *reinterpret_cast<const float2*>(&g[r*64 + c2]);
        __nv_bfloat16 h0, l0, h1, l1;
        bf16split(v.x, h0, l0); bf16split(v.y, h1, l1);
        int ob = r*144 + c2*2;
        *(__nv_bfloat162*)(smem + offH + ob) = __halves2bfloat162(h0, h1);
        *(__nv_bfloat162*)(smem + offL + ob) = __halves2bfloat162(l0, l1);
    }
}

// ======================= kernel 1: top-k select + sort + gather =======================
__global__ __launch_bounds__(256) void topk_gather(const float* __restrict__ Qg,
                                                   const float* __restrict__ Kg) {
    __shared__ float vals[NTOK];
    __shared__ int   sel[MSEL];
    __shared__ int   sorted[MSEL];
    __shared__ float wmax[8];
    __shared__ int   widx[8];
    int hh = blockIdx.x, which = blockIdx.y, tid = threadIdx.x;
    const float* src = (which == 0 ? Kg : Qg) + (size_t)hh * NTOK * DIMX;

    if (hh == 0 && which == 0 && tid == 0) d_gmax_bits = 0u;

    for (int i = tid; i < NTOK; i += 256) vals[i] = src[(size_t)i * DIMX];
    if (tid == 0) vals[0] = -3.402823466e38f;
    __syncthreads();

    for (int r = 0; r < MSEL - 1; r++) {
        float bv = -3.402823466e38f; int bi = NTOK;
        for (int k = tid; k < NTOK; k += 256) {
            float v = vals[k];
            if (v > bv) { bv = v; bi = k; }
        }
#pragma unroll
        for (int o = 16; o > 0; o >>= 1) {
            float ov = __shfl_down_sync(0xffffffffu, bv, o);
            int   oi = __shfl_down_sync(0xffffffffu, bi, o);
            if (ov > bv || (ov == bv && oi < bi)) { bv = ov; bi = oi; }
        }
        if ((tid & 31) == 0) { wmax[tid >> 5] = bv; widx[tid >> 5] = bi; }
        __syncthreads();
        if (tid == 0) {
            for (int w = 1; w < 8; w++)
                if (wmax[w] > bv || (wmax[w] == bv && widx[w] < bi)) { bv = wmax[w]; bi = widx[w]; }
            sel[r] = bi;
            vals[bi] = -3.402823466e38f;
        }
        __syncthreads();
    }
    if (tid == 0) sel[MSEL - 1] = 0;
    __syncthreads();

    if (tid < MSEL) {
        int my = sel[tid], rank = 0;
        for (int j = 0; j < MSEL; j++) rank += (sel[j] < my);
        sorted[rank] = my;
    }
    __syncthreads();

    float* dst = (which == 0 ? d_nc : d_nr) + (size_t)hh * MSEL * DIMX;
    for (int i = tid; i < MSEL * DIMX; i += 256) {
        int p = i >> 6, d = i & 63;
        dst[i] = src[(size_t)sorted[p] * DIMX + d];
    }
}

// ======================= kernel 2: kernel_2 = softmax(nr @ nc^T), colsum max =======================
__global__ __launch_bounds__(256) void mker() {
    extern __shared__ float sm[];
    float* As = sm;
    float* Bs = sm + DIMX * PITCH;
    float* cs = sm + 2 * DIMX * PITCH;
    int hh = blockIdx.x, tid = threadIdx.x;
    int ty = tid >> 4, tx = tid & 15;
    load_tileT(As, d_nr + (size_t)hh * MSEL * DIMX, tid);
    load_tileT(Bs, d_nc + (size_t)hh * MSEL * DIMX, tid);
    if (tid < MSEL) cs[tid] = 0.f;
    __syncthreads();

    float acc[8][8] = {};
    mm128(As, Bs, acc, ty, tx);

    float* K2h = d_K2m + (size_t)hh * MSEL * MSEL;
    float colp[8] = {};
#pragma unroll
    for (int i = 0; i < 8; i++) {
        float mx = acc[i][0];
#pragma unroll
        for (int j = 1; j < 8; j++) mx = fmaxf(mx, acc[i][j]);
        mx = grp_max(mx);
        float s = 0.f;
#pragma unroll
        for (int j = 0; j < 8; j++) { acc[i][j] = __expf(acc[i][j] - mx); s += acc[i][j]; }
        s = grp_sum(s);
        float inv = 1.f / s;
#pragma unroll
        for (int j = 0; j < 8; j++) {
            float p = acc[i][j] * inv;
            K2h[(ty*8 + i) * MSEL + tx*8 + j] = p;
            colp[j] += p;
        }
    }
#pragma unroll
    for (int j = 0; j < 8; j++) atomicAdd(&cs[tx*8 + j], colp[j]);
    __syncthreads();
    if (tid < MSEL) atomicMax(&d_gmax_bits, __float_as_uint(cs[tid]));
}

// ======================= tensor-core attention tile body =======================
// MMA1: D1[128x128] = A[128x64] @ B[128x64]^T   (3-way bf16 split)
// per-warp: rows wid*16..+15, softmax-exp in registers, split-P to aliased smem
// MMA2: D2[128x64]  = P[128x128] @ V[128x64]
// C1[16][4], C2[8][4] per thread; su/mx per thread rows (lane>>2) and +8.
struct TileOut { float su0, su1, mx0, mx1; };

__device__ __forceinline__ TileOut attn_tile(char* smem, uint32_t sb, int wid, int lane,
                                             float C2[8][4]) {
    float C1[16][4] = {};
    uint32_t aBaseH = sb + OFF_AH + (wid*16 + (lane & 15))*144 + ((lane >> 4) << 4);
    uint32_t aBaseL = aBaseH + 18432;
    int bRow = (lane & 7) + ((lane >> 4) << 3);
    uint32_t bBaseH = sb + OFF_BH + bRow*144 + (((lane >> 3) & 1) << 4);
    uint32_t bBaseL = bBaseH + 18432;

#pragma unroll
    for (int ks = 0; ks < 4; ks++) {
        uint32_t ah0, ah1, ah2, ah3, al0, al1, al2, al3;
        LDSM_X4(ah0, ah1, ah2, ah3, aBaseH + ks*32);
        LDSM_X4(al0, al1, al2, al3, aBaseL + ks*32);
#pragma unroll
        for (int p = 0; p < 8; p++) {
            uint32_t bh0, bh1, bh2, bh3, bl0, bl1, bl2, bl3;
            LDSM_X4(bh0, bh1, bh2, bh3, bBaseH + p*2304 + ks*32);
            LDSM_X4(bl0, bl1, bl2, bl3, bBaseL + p*2304 + ks*32);
            mma_bf16(C1[2*p],   ah0, ah1, ah2, ah3, bh0, bh1);
            mma_bf16(C1[2*p+1], ah0, ah1, ah2, ah3, bh2, bh3);
            mma_bf16(C1[2*p],   ah0, ah1, ah2, ah3, bl0, bl1);
            mma_bf16(C1[2*p+1], ah0, ah1, ah2, ah3, bl2, bl3);
            mma_bf16(C1[2*p],   al0, al1, al2, al3, bh0, bh1);
            mma_bf16(C1[2*p+1], al0, al1, al2, al3, bh2, bh3);
        }
    }

    // warp-local softmax over 128 cols: rows (lane>>2) and (lane>>2)+8, col-group = lane&3
    float mx0 = -3.402823466e38f, mx1 = -3.402823466e38f;
#pragma unroll
    for (int t = 0; t < 16; t++) {
        mx0 = fmaxf(mx0, fmaxf(C1[t][0], C1[t][1]));
        mx1 = fmaxf(mx1, fmaxf(C1[t][2], C1[t][3]));
    }
    mx0 = fmaxf(mx0, __shfl_xor_sync(0xffffffffu, mx0, 1));
    mx0 = fmaxf(mx0, __shfl_xor_sync(0xffffffffu, mx0, 2));
    mx1 = fmaxf(mx1, __shfl_xor_sync(0xffffffffu, mx1, 1));
    mx1 = fmaxf(mx1, __shfl_xor_sync(0xffffffffu, mx1, 2));
    float su0 = 0.f, su1 = 0.f;
#pragma unroll
    for (int t = 0; t < 16; t++) {
        C1[t][0] = __expf(C1[t][0] - mx0); C1[t][1] = __expf(C1[t][1] - mx0);
        C1[t][2] = __expf(C1[t][2] - mx1); C1[t][3] = __expf(C1[t][3] - mx1);
        su0 += C1[t][0] + C1[t][1];
        su1 += C1[t][2] + C1[t][3];
    }
    su0 += __shfl_xor_sync(0xffffffffu, su0, 1);
    su0 += __shfl_xor_sync(0xffffffffu, su0, 2);
    su1 += __shfl_xor_sync(0xffffffffu, su1, 1);
    su1 += __shfl_xor_sync(0xffffffffu, su1, 2);

    __syncthreads();                        // everyone done reading A/B before P aliases them
    int prow0 = wid*16 + (lane >> 2);
    int pcol  = (lane & 3) * 2;
#pragma unroll
    for (int t = 0; t < 16; t++) {
        int cb = (t*8 + pcol) * 2;
        __nv_bfloat16 h0, l0, h1, l1;
        bf16split(C1[t][0], h0, l0); bf16split(C1[t][1], h1, l1);
        *(__nv_bfloat162*)(smem + OFF_PH + prow0*272 + cb) = __halves2bfloat162(h0, h1);
        *(__nv_bfloat162*)(smem + OFF_PL + prow0*272 + cb) = __halves2bfloat162(l0, l1);
        bf16split(C1[t][2], h0, l0); bf16split(C1[t][3], h1, l1);
        *(__nv_bfloat162*)(smem + OFF_PH + (prow0+8)*272 + cb) = __halves2bfloat162(h0, h1);
        *(__nv_bfloat162*)(smem + OFF_PL + (prow0+8)*272 + cb) = __halves2bfloat162(l0, l1);
    }
    __syncthreads();

    uint32_t pBaseH = sb + OFF_PH + (wid*16 + (lane & 15))*272 + ((lane >> 4) << 4);
    uint32_t pBaseL = pBaseH + (OFF_PL - OFF_PH);
    uint32_t vBaseH = sb + OFF_VH + (lane & 15)*144 + ((lane >> 4) << 4);
    uint32_t vBaseL = vBaseH + 18432;
#pragma unroll
    for (int ks = 0; ks < 8; ks++) {
        uint32_t ph0, ph1, ph2, ph3, pl0, pl1, pl2, pl3;
        LDSM_X4(ph0, ph1, ph2, ph3, pBaseH + ks*32);
        LDSM_X4(pl0, pl1, pl2, pl3, pBaseL + ks*32);
#pragma unroll
        for (int p = 0; p < 4; p++) {
            uint32_t vh0, vh1, vh2, vh3, vl0, vl1, vl2, vl3;
            LDSM_X4_T(vh0, vh1, vh2, vh3, vBaseH + ks*2304 + p*32);
            LDSM_X4_T(vl0, vl1, vl2, vl3, vBaseL + ks*2304 + p*32);
            mma_bf16(C2[2*p],   ph0, ph1, ph2, ph3, vh0, vh1);
            mma_bf16(C2[2*p+1], ph0, ph1, ph2, ph3, vh2, vh3);
            mma_bf16(C2[2*p],   ph0, ph1, ph2, ph3, vl0, vl1);
            mma_bf16(C2[2*p+1], ph0, ph1, ph2, ph3, vl2, vl3);
            mma_bf16(C2[2*p],   pl0, pl1, pl2, pl3, vh0, vh1);
            mma_bf16(C2[2*p+1], pl0, pl1, pl2, pl3, vh2, vh3);
        }
    }
    TileOut o; o.su0 = su0; o.su1 = su1; o.mx0 = mx0; o.mx1 = mx1;
    return o;
}

// ======================= kernel 3: split-K flash (kernel_3 @ V), tensor cores ==========
__global__ __launch_bounds__(256) void r1ker(const float* __restrict__ Kg,
                                             const float* __restrict__ Vg) {
    extern __shared__ char smem[];
    uint32_t sb = smem_to_u32(smem);
    int hh = blockIdx.x, s = blockIdx.y, tid = threadIdx.x;
    int wid = tid >> 5, lane = tid & 31;

    stage_split(smem, OFF_AH, OFF_AL, d_nr + (size_t)hh * MSEL * DIMX, tid);
    stage_split(smem, OFF_BH, OFF_BL, Kg + ((size_t)hh * NTOK + s * MSEL) * DIMX, tid);
    stage_split(smem, OFF_VH, OFF_VL, Vg + ((size_t)hh * NTOK + s * MSEL) * DIMX, tid);
    __syncthreads();

    float C2[8][4] = {};
    TileOut o = attn_tile(smem, sb, wid, lane, C2);

    size_t base = (size_t)(hh * NSPLIT + s) * MSEL;
    int grow0 = wid*16 + (lane >> 2);
    int pcol = (lane & 3) * 2;
    if ((lane & 3) == 0) {
        d_pmax[base + grow0]     = o.mx0;  d_psum[base + grow0]     = o.su0;
        d_pmax[base + grow0 + 8] = o.mx1;  d_psum[base + grow0 + 8] = o.su1;
    }
    float* z0 = d_pZ + (base + grow0) * DIMX;
    float* z1 = z0 + 8 * DIMX;
#pragma unroll
    for (int t = 0; t < 8; t++) {
        *reinterpret_cast<float2*>(&z0[t*8 + pcol]) = make_float2(C2[t][0], C2[t][1]);
        *reinterpret_cast<float2*>(&z1[t*8 + pcol]) = make_float2(C2[t][2], C2[t][3]);
    }
}

// ======================= kernel 4: combine splits =======================
__global__ void combiner() {
    int hh = blockIdx.x;
    int r  = blockIdx.y * 16 + threadIdx.y;
    int d  = threadIdx.x * 4;
    const float* pm = d_pmax + (size_t)hh * NSPLIT * MSEL;
    const float* ps = d_psum + (size_t)hh * NSPLIT * MSEL;
    float M = -3.402823466e38f;
#pragma unroll 8
    for (int s = 0; s < NSPLIT; s++) M = fmaxf(M, pm[s * MSEL + r]);
    float l = 0.f;
    float4 z = make_float4(0.f, 0.f, 0.f, 0.f);
#pragma unroll 4
    for (int s = 0; s < NSPLIT; s++) {
        float w = __expf(pm[s * MSEL + r] - M);
        l += ps[s * MSEL + r] * w;
        float4 pz = *reinterpret_cast<const float4*>(
            &d_pZ[((size_t)(hh * NSPLIT + s) * MSEL + r) * DIMX + d]);
        z.x += w * pz.x; z.y += w * pz.y; z.z += w * pz.z; z.w += w * pz.w;
    }
    float inv = 1.f / l;
    *reinterpret_cast<float4*>(&d_Zm[((size_t)hh * MSEL + r) * DIMX + d]) =
        make_float4(z.x * inv, z.y * inv, z.z * inv, z.w * inv);
}

// ======================= Newton-Schulz =======================
__device__ __forceinline__ float* mat_ptr(int s) {
    switch (s) {
        case 0: return d_K2m; case 1: return d_KVm; case 2: return d_Tm;
        case 3: return d_Em;  case 4: return d_Vm0; default: return d_Vm1;
    }
}

__global__ __launch_bounds__(256) void vminit() {
    int hh = blockIdx.x;
    float inv = 1.f / __uint_as_float(d_gmax_bits);
    const float* K2h = d_K2m + (size_t)hh * MSEL * MSEL;
    float* Vh = d_Vm0 + (size_t)hh * MSEL * MSEL;
    for (int i = threadIdx.x; i < MSEL * MSEL; i += 256) {
        int r = i >> 7, c = i & 127;
        Vh[i] = K2h[c * MSEL + r] * inv;
    }
}

__global__ __launch_bounds__(256) void nmm(int selA, int selB, int selC,
                                           float c0, float c1, float c2) {
    __shared__ float As[32][65];
    __shared__ float Bs[32][65];
    int hh = blockIdx.x;
    const float* A = mat_ptr(selA) + (size_t)hh * MSEL * MSEL;
    const float* B = mat_ptr(selB) + (size_t)hh * MSEL * MSEL;
    float* C = mat_ptr(selC) + (size_t)hh * MSEL * MSEL;
    int r0 = blockIdx.y * 64, cc = blockIdx.z * 64;
    int tid = threadIdx.x, ty = tid >> 4, tx = tid & 15;
    float acc[4][4] = {};
    for (int kc = 0; kc < MSEL; kc += 32) {
        for (int i = tid; i < 2048; i += 256) {
            int m = i >> 5, k = i & 31;
            As[k][m] = A[(r0 + m) * MSEL + kc + k];
        }
        for (int i = tid; i < 2048; i += 256) {
            int k = i >> 6, n = i & 63;
            Bs[k][n] = B[(kc + k) * MSEL + cc + n];
        }
        __syncthreads();
#pragma unroll 8
        for (int k = 0; k < 32; k++) {
            float a[4], b[4];
#pragma unroll
            for (int i = 0; i < 4; i++) a[i] = As[k][ty*4 + i];
#pragma unroll
            for (int j = 0; j < 4; j++) b[j] = Bs[k][tx*4 + j];
#pragma unroll
            for (int i = 0; i < 4; i++)
#pragma unroll
                for (int j = 0; j < 4; j++)
                    acc[i][j] += a[i] * b[j];
        }
        __syncthreads();
    }
#pragma unroll
    for (int i = 0; i < 4; i++)
#pragma unroll
        for (int j = 0; j < 4; j++) {
            int gr = r0 + ty*4 + i, gc = cc + tx*4 + j;
            float v = c1 * acc[i][j] + c2 * A[gr * MSEL + gc];
            if (gr == gc) v += c0;
            C[gr * MSEL + gc] = v;
        }
}

// W = Vm_final @ Z  (128x64), grid (48, 2)
__global__ __launch_bounds__(256) void wker(int selVm) {
    __shared__ float As[32][65];
    __shared__ float Bs[32][65];
    int hh = blockIdx.x;
    const float* Vm = mat_ptr(selVm) + (size_t)hh * MSEL * MSEL;
    const float* Z  = d_Zm + (size_t)hh * MSEL * DIMX;
    int r0 = blockIdx.y * 64;
    int tid = threadIdx.x, ty = tid >> 4, tx = tid & 15;
    float acc[4][4] = {};
    for (int kc = 0; kc < MSEL; kc += 32) {
        for (int i = tid; i < 2048; i += 256) {
            int m = i >> 5, k = i & 31;
            As[k][m] = Vm[(r0 + m) * MSEL + kc + k];
        }
        for (int i = tid; i < 2048; i += 256) {
            int k = i >> 6, n = i & 63;
            Bs[k][n] = Z[(kc + k) * DIMX + n];
        }
        __syncthreads();
#pragma unroll 8
        for (int k = 0; k < 32; k++) {
            float a[4], b[4];
#pragma unroll
            for (int i = 0; i < 4; i++) a[i] = As[k][ty*4 + i];
#pragma unroll
            for (int j = 0; j < 4; j++) b[j] = Bs[k][tx*4 + j];
#pragma unroll
            for (int i = 0; i < 4; i++)
#pragma unroll
                for (int j = 0; j < 4; j++)
                    acc[i][j] += a[i] * b[j];
        }
        __syncthreads();
    }
#pragma unroll
    for (int i = 0; i < 4; i++)
#pragma unroll
        for (int j = 0; j < 4; j++)
            d_Wm[(size_t)hh * MSEL * DIMX + (r0 + ty*4 + i) * DIMX + tx*4 + j] = acc[i][j];
}

// ======================= final: X = softmax(Q @ nc^T) @ W, tensor cores ==========
__global__ __launch_bounds__(256) void eker(const float* __restrict__ Qg,
                                            float* __restrict__ Xg) {
    extern __shared__ char smem[];
    uint32_t sb = smem_to_u32(smem);
    int hh = blockIdx.x, q0 = blockIdx.y * MSEL, tid = threadIdx.x;
    int wid = tid >> 5, lane = tid & 31;

    stage_split(smem, OFF_AH, OFF_AL, Qg + ((size_t)hh * NTOK + q0) * DIMX, tid);
    stage_split(smem, OFF_BH, OFF_BL, d_nc + (size_t)hh * MSEL * DIMX, tid);
    stage_split(smem, OFF_VH, OFF_VL, d_Wm + (size_t)hh * MSEL * DIMX, tid);
    __syncthreads();

    float C2[8][4] = {};
    TileOut o = attn_tile(smem, sb, wid, lane, C2);

    float rinv0 = 1.f / o.su0, rinv1 = 1.f / o.su1;
    int grow0 = wid*16 + (lane >> 2);
    int pcol = (lane & 3) * 2;
    float* x0 = Xg + ((size_t)hh * NTOK + q0 + grow0) * DIMX;
    float* x1 = x0 + 8 * DIMX;
#pragma unroll
    for (int t = 0; t < 8; t++) {
        *reinterpret_cast<float2*>(&x0[t*8 + pcol]) =
            make_float2(C2[t][0] * rinv0, C2[t][1] * rinv0);
        *reinterpret_cast<float2*>(&x1[t*8 + pcol]) =
            make_float2(C2[t][2] * rinv1, C2[t][3] * rinv1);
    }
}

// ======================= launch =======================
extern "C" void kernel_launch(void* const* d_in, const int* in_sizes, int n_in,
                              void* d_out, int out_size) {
    const float* Q = (const float*)d_in[0];
    const float* K = (const float*)d_in[1];
    const float* V = (const float*)d_in[2];
    float* X = (float*)d_out;

    const int SMEM_MK = (2 * DIMX * PITCH + MSEL) * 4;
    cudaFuncSetAttribute(mker,  cudaFuncAttributeMaxDynamicSharedMemorySize, SMEM_MK);
    cudaFuncSetAttribute(r1ker, cudaFuncAttributeMaxDynamicSharedMemorySize, SMEM_TC);
    cudaFuncSetAttribute(eker,  cudaFuncAttributeMaxDynamicSharedMemorySize, SMEM_TC);

    topk_gather<<<dim3(BHX, 2), 256>>>(Q, K);
    mker<<<BHX, 256, SMEM_MK>>>();
    r1ker<<<dim3(BHX, NSPLIT), 256, SMEM_TC>>>(K, V);
    combiner<<<dim3(BHX, 8), dim3(16, 16)>>>();
    vminit<<<BHX, 256>>>();

    int cur = 4, nxt = 5;
    for (int it = 0; it < 6; it++) {
        nmm<<<dim3(BHX, 2, 2), 256>>>(0,  cur, 1,  0.f,  1.f,   0.f);  // KV = Km@Vm
        nmm<<<dim3(BHX, 2, 2), 256>>>(1,  1,   2, 15.f,  1.f,  -7.f);  // T  = 15I + KV@KV - 7KV
        nmm<<<dim3(BHX, 2, 2), 256>>>(1,  2,   3, 13.f, -1.f,   0.f);  // E  = 13I - KV@T
        nmm<<<dim3(BHX, 2, 2), 256>>>(cur, 3, nxt, 0.f,  0.25f, 0.f);  // Vm = 0.25*Vm@E
        int t = cur; cur = nxt; nxt = t;
    }

    wker<<<dim3(BHX, 2), 256>>>(cur);
    eker<<<dim3(BHX, NTOK / MSEL), 256, SMEM_TC>>>(Q, X);
}

// round 8
// speedup vs baseline: 1.7321x; 1.5151x over previous
#include <cuda_runtime.h>
#include <cuda_bf16.h>
#include <cstdint>
#include <cstddef>

#define BHX    48
#define NTOK   8192
#define DIMX   64
#define MSEL   128
#define SPLITS 16
#define CHUNKS 4          // key chunks of 128 per split CTA
#define PITCH  132

// ======================= mma.sync / ldmatrix helpers =======================
__device__ __forceinline__ uint32_t smem_to_u32(const void* p) {
    uint32_t a;
    asm("{ .reg .u64 t; cvta.to.shared.u64 t, %1; cvt.u32.u64 %0, t; }" : "=r"(a) : "l"(p));
    return a;
}
#define LDSM_X4(r0, r1, r2, r3, addr) \
    asm volatile("ldmatrix.sync.aligned.m8n8.x4.shared.b16 {%0,%1,%2,%3}, [%4];" \
                 : "=r"(r0), "=r"(r1), "=r"(r2), "=r"(r3) : "r"(addr))
#define LDSM_X4_T(r0, r1, r2, r3, addr) \
    asm volatile("ldmatrix.sync.aligned.m8n8.x4.trans.shared.b16 {%0,%1,%2,%3}, [%4];" \
                 : "=r"(r0), "=r"(r1), "=r"(r2), "=r"(r3) : "r"(addr))
__device__ __forceinline__ void mma_bf16(float* c, uint32_t a0, uint32_t a1, uint32_t a2, uint32_t a3,
                                         uint32_t b0, uint32_t b1) {
    asm volatile("mma.sync.aligned.m16n8k16.row.col.f32.bf16.bf16.f32 "
                 "{%0,%1,%2,%3}, {%4,%5,%6,%7}, {%8,%9}, {%0,%1,%2,%3};"
                 : "+f"(c[0]), "+f"(c[1]), "+f"(c[2]), "+f"(c[3])
                 : "r"(a0), "r"(a1), "r"(a2), "r"(a3), "r"(b0), "r"(b1));
}
__device__ __forceinline__ void bf16split(float v, __nv_bfloat16& h, __nv_bfloat16& l) {
    h = __float2bfloat16(v);
    l = __float2bfloat16(v - __bfloat162float(h));
}

// attention-kernel smem: A/B/V [128 x 72 halves] (144B pitch), P [128 x 136] (272B) aliases A+B
#define OFF_AH   0
#define OFF_AL   18432
#define OFF_BH   36864
#define OFF_BL   55296
#define OFF_VH   73728
#define OFF_VL   92160
#define SMEM_TC  110592
#define OFF_PH   0
#define OFF_PL   36864

// newton smem: 3 matrices [128 x 136 halves] (272B pitch), hi half then lo half (+34816)
#define NB_K   0
#define NB_V   69632
#define NB_T   139264
#define NB_SZ  208896

// ======================= scratch =======================
__device__ float d_nc [BHX*MSEL*DIMX];
__device__ float d_nr [BHX*MSEL*DIMX];
__device__ float d_K2m[BHX*MSEL*MSEL];
__device__ float d_Vm0[BHX*MSEL*MSEL];
__device__ float d_Zm [BHX*MSEL*DIMX];
__device__ float d_Wm [BHX*MSEL*DIMX];
__device__ unsigned int d_gmax_bits;
__device__ float d_pmax[BHX*SPLITS*MSEL];
__device__ float d_psum[BHX*SPLITS*MSEL];
__device__ float d_pZ  [(size_t)BHX*SPLITS*MSEL*DIMX];

// ======================= SIMT helpers =======================
__device__ __forceinline__ float grp_max(float v) {
    v = fmaxf(v, __shfl_xor_sync(0xffffffffu, v, 8));
    v = fmaxf(v, __shfl_xor_sync(0xffffffffu, v, 4));
    v = fmaxf(v, __shfl_xor_sync(0xffffffffu, v, 2));
    v = fmaxf(v, __shfl_xor_sync(0xffffffffu, v, 1));
    return v;
}
__device__ __forceinline__ float grp_sum(float v) {
    v += __shfl_xor_sync(0xffffffffu, v, 8);
    v += __shfl_xor_sync(0xffffffffu, v, 4);
    v += __shfl_xor_sync(0xffffffffu, v, 2);
    v += __shfl_xor_sync(0xffffffffu, v, 1);
    return v;
}
__device__ __forceinline__ void load_tileT(float* dst, const float* __restrict__ g, int tid) {
    for (int i = tid; i < MSEL*DIMX; i += 256) {
        int m = i >> 6, k = i & 63;
        dst[k*PITCH + m] = g[i];
    }
}
__device__ __forceinline__ void mm128(const float* As, const float* Bs,
                                      float acc[8][8], int ty, int tx) {
#pragma unroll 8
    for (int k = 0; k < DIMX; k++) {
        float4 a0 = *reinterpret_cast<const float4*>(&As[k*PITCH + ty*8]);
        float4 a1 = *reinterpret_cast<const float4*>(&As[k*PITCH + ty*8 + 4]);
        float4 b0 = *reinterpret_cast<const float4*>(&Bs[k*PITCH + tx*8]);
        float4 b1 = *reinterpret_cast<const float4*>(&Bs[k*PITCH + tx*8 + 4]);
        float a[8] = {a0.x,a0.y,a0.z,a0.w,a1.x,a1.y,a1.z,a1.w};
        float b[8] = {b0.x,b0.y,b0.z,b0.w,b1.x,b1.y,b1.z,b1.w};
#pragma unroll
        for (int i = 0; i < 8; i++)
#pragma unroll
            for (int j = 0; j < 8; j++)
                acc[i][j] += a[i] * b[j];
    }
}

// stage [128x64] fp32 -> split bf16 padded tile (pitch 72 halves)
__device__ __forceinline__ void stage_split(char* smem, int offH, int offL,
                                            const float* __restrict__ g, int tid) {
    for (int i = tid; i < 4096; i += 256) {
        int r = i >> 5, c2 = (i & 31) * 2;
        float2 v = *reinterpret_cast<const float2*>(&g[r*64 + c2]);
        __nv_bfloat16 h0, l0, h1, l1;
        bf16split(v.x, h0, l0); bf16split(v.y, h1, l1);
        int ob = r*144 + c2*2;
        *(__nv_bfloat162*)(smem + offH + ob) = __halves2bfloat162(h0, h1);
        *(__nv_bfloat162*)(smem + offL + ob) = __halves2bfloat162(l0, l1);
    }
}

// ======================= kernel 1: top-k select + sort + gather =======================
__global__ __launch_bounds__(256) void topk_gather(const float* __restrict__ Qg,
                                                   const float* __restrict__ Kg) {
    __shared__ float vals[NTOK];
    __shared__ int   sel[MSEL];
    __shared__ int   sorted[MSEL];
    __shared__ float wmax[8];
    __shared__ int   widx[8];
    int hh = blockIdx.x, which = blockIdx.y, tid = threadIdx.x;
    const float* src = (which == 0 ? Kg : Qg) + (size_t)hh * NTOK * DIMX;

    if (hh == 0 && which == 0 && tid == 0) d_gmax_bits = 0u;

    for (int i = tid; i < NTOK; i += 256) vals[i] = src[(size_t)i * DIMX];
    if (tid == 0) vals[0] = -3.402823466e38f;
    __syncthreads();

    for (int r = 0; r < MSEL - 1; r++) {
        float bv = -3.402823466e38f; int bi = NTOK;
        for (int k = tid; k < NTOK; k += 256) {
            float v = vals[k];
            if (v > bv) { bv = v; bi = k; }
        }
#pragma unroll
        for (int o = 16; o > 0; o >>= 1) {
            float ov = __shfl_down_sync(0xffffffffu, bv, o);
            int   oi = __shfl_down_sync(0xffffffffu, bi, o);
            if (ov > bv || (ov == bv && oi < bi)) { bv = ov; bi = oi; }
        }
        if ((tid & 31) == 0) { wmax[tid >> 5] = bv; widx[tid >> 5] = bi; }
        __syncthreads();
        if (tid == 0) {
            for (int w = 1; w < 8; w++)
                if (wmax[w] > bv || (wmax[w] == bv && widx[w] < bi)) { bv = wmax[w]; bi = widx[w]; }
            sel[r] = bi;
            vals[bi] = -3.402823466e38f;
        }
        __syncthreads();
    }
    if (tid == 0) sel[MSEL - 1] = 0;
    __syncthreads();

    if (tid < MSEL) {
        int my = sel[tid], rank = 0;
        for (int j = 0; j < MSEL; j++) rank += (sel[j] < my);
        sorted[rank] = my;
    }
    __syncthreads();

    float* dst = (which == 0 ? d_nc : d_nr) + (size_t)hh * MSEL * DIMX;
    for (int i = tid; i < MSEL * DIMX; i += 256) {
        int p = i >> 6, d = i & 63;
        dst[i] = src[(size_t)sorted[p] * DIMX + d];
    }
}

// ======================= kernel 2: kernel_2 = softmax(nr @ nc^T), colsum max =======================
__global__ __launch_bounds__(256) void mker() {
    extern __shared__ float sm[];
    float* As = sm;
    float* Bs = sm + DIMX * PITCH;
    float* cs = sm + 2 * DIMX * PITCH;
    int hh = blockIdx.x, tid = threadIdx.x;
    int ty = tid >> 4, tx = tid & 15;
    load_tileT(As, d_nr + (size_t)hh * MSEL * DIMX, tid);
    load_tileT(Bs, d_nc + (size_t)hh * MSEL * DIMX, tid);
    if (tid < MSEL) cs[tid] = 0.f;
    __syncthreads();

    float acc[8][8] = {};
    mm128(As, Bs, acc, ty, tx);

    float* K2h = d_K2m + (size_t)hh * MSEL * MSEL;
    float colp[8] = {};
#pragma unroll
    for (int i = 0; i < 8; i++) {
        float mx = acc[i][0];
#pragma unroll
        for (int j = 1; j < 8; j++) mx = fmaxf(mx, acc[i][j]);
        mx = grp_max(mx);
        float s = 0.f;
#pragma unroll
        for (int j = 0; j < 8; j++) { acc[i][j] = __expf(acc[i][j] - mx); s += acc[i][j]; }
        s = grp_sum(s);
        float inv = 1.f / s;
#pragma unroll
        for (int j = 0; j < 8; j++) {
            float p = acc[i][j] * inv;
            K2h[(ty*8 + i) * MSEL + tx*8 + j] = p;
            colp[j] += p;
        }
    }
#pragma unroll
    for (int j = 0; j < 8; j++) atomicAdd(&cs[tx*8 + j], colp[j]);
    __syncthreads();
    if (tid < MSEL) atomicMax(&d_gmax_bits, __float_as_uint(cs[tid]));
}

// ======================= shared MMA1 + softmax(+online) + MMA2 tile body =======================
// MMA1: C1[128x128] = A[128x64] @ B[128x64]^T ; per-warp rows wid*16..+15
// online rescale of (m,s,C2), split-P to aliased smem, MMA2 accumulate C2 += P@V
__device__ __forceinline__ void attn_tile_online(char* smem, uint32_t sb, int wid, int lane,
                                                 float C2[8][4],
                                                 float& m0, float& m1, float& s0, float& s1) {
    float C1[16][4] = {};
    uint32_t aBaseH = sb + OFF_AH + (wid*16 + (lane & 15))*144 + ((lane >> 4) << 4);
    uint32_t aBaseL = aBaseH + 18432;
    int bRow = (lane & 7) + ((lane >> 4) << 3);
    uint32_t bBaseH = sb + OFF_BH + bRow*144 + (((lane >> 3) & 1) << 4);
    uint32_t bBaseL = bBaseH + 18432;

#pragma unroll
    for (int ks = 0; ks < 4; ks++) {
        uint32_t ah0, ah1, ah2, ah3, al0, al1, al2, al3;
        LDSM_X4(ah0, ah1, ah2, ah3, aBaseH + ks*32);
        LDSM_X4(al0, al1, al2, al3, aBaseL + ks*32);
#pragma unroll
        for (int p = 0; p < 8; p++) {
            uint32_t bh0, bh1, bh2, bh3, bl0, bl1, bl2, bl3;
            LDSM_X4(bh0, bh1, bh2, bh3, bBaseH + p*2304 + ks*32);
            LDSM_X4(bl0, bl1, bl2, bl3, bBaseL + p*2304 + ks*32);
            mma_bf16(C1[2*p],   ah0, ah1, ah2, ah3, bh0, bh1);
            mma_bf16(C1[2*p+1], ah0, ah1, ah2, ah3, bh2, bh3);
            mma_bf16(C1[2*p],   ah0, ah1, ah2, ah3, bl0, bl1);
            mma_bf16(C1[2*p+1], ah0, ah1, ah2, ah3, bl2, bl3);
            mma_bf16(C1[2*p],   al0, al1, al2, al3, bh0, bh1);
            mma_bf16(C1[2*p+1], al0, al1, al2, al3, bh2, bh3);
        }
    }

    // warp-local chunk max
    float cx0 = -3.402823466e38f, cx1 = -3.402823466e38f;
#pragma unroll
    for (int t = 0; t < 16; t++) {
        cx0 = fmaxf(cx0, fmaxf(C1[t][0], C1[t][1]));
        cx1 = fmaxf(cx1, fmaxf(C1[t][2], C1[t][3]));
    }
    cx0 = fmaxf(cx0, __shfl_xor_sync(0xffffffffu, cx0, 1));
    cx0 = fmaxf(cx0, __shfl_xor_sync(0xffffffffu, cx0, 2));
    cx1 = fmaxf(cx1, __shfl_xor_sync(0xffffffffu, cx1, 1));
    cx1 = fmaxf(cx1, __shfl_xor_sync(0xffffffffu, cx1, 2));

    float mn0 = fmaxf(m0, cx0), mn1 = fmaxf(m1, cx1);
    float f0 = __expf(m0 - mn0), f1 = __expf(m1 - mn1);
    float su0 = 0.f, su1 = 0.f;
#pragma unroll
    for (int t = 0; t < 16; t++) {
        C1[t][0] = __expf(C1[t][0] - mn0); C1[t][1] = __expf(C1[t][1] - mn0);
        C1[t][2] = __expf(C1[t][2] - mn1); C1[t][3] = __expf(C1[t][3] - mn1);
        su0 += C1[t][0] + C1[t][1];
        su1 += C1[t][2] + C1[t][3];
    }
    su0 += __shfl_xor_sync(0xffffffffu, su0, 1);
    su0 += __shfl_xor_sync(0xffffffffu, su0, 2);
    su1 += __shfl_xor_sync(0xffffffffu, su1, 1);
    su1 += __shfl_xor_sync(0xffffffffu, su1, 2);
    s0 = s0 * f0 + su0;  s1 = s1 * f1 + su1;
    m0 = mn0;            m1 = mn1;
#pragma unroll
    for (int t = 0; t < 8; t++) {
        C2[t][0] *= f0; C2[t][1] *= f0;
        C2[t][2] *= f1; C2[t][3] *= f1;
    }

    __syncthreads();                        // A/B reads done before P aliases them
    int prow0 = wid*16 + (lane >> 2);
    int pcol  = (lane & 3) * 2;
#pragma unroll
    for (int t = 0; t < 16; t++) {
        int cb = (t*8 + pcol) * 2;
        __nv_bfloat16 h0, l0, h1, l1;
        bf16split(C1[t][0], h0, l0); bf16split(C1[t][1], h1, l1);
        *(__nv_bfloat162*)(smem + OFF_PH + prow0*272 + cb) = __halves2bfloat162(h0, h1);
        *(__nv_bfloat162*)(smem + OFF_PL + prow0*272 + cb) = __halves2bfloat162(l0, l1);
        bf16split(C1[t][2], h0, l0); bf16split(C1[t][3], h1, l1);
        *(__nv_bfloat162*)(smem + OFF_PH + (prow0+8)*272 + cb) = __halves2bfloat162(h0, h1);
        *(__nv_bfloat162*)(smem + OFF_PL + (prow0+8)*272 + cb) = __halves2bfloat162(l0, l1);
    }
    __syncthreads();

    uint32_t pBaseH = sb + OFF_PH + (wid*16 + (lane & 15))*272 + ((lane >> 4) << 4);
    uint32_t pBaseL = pBaseH + (OFF_PL - OFF_PH);
    uint32_t vBaseH = sb + OFF_VH + (lane & 15)*144 + ((lane >> 4) << 4);
    uint32_t vBaseL = vBaseH + 18432;
#pragma unroll
    for (int ks = 0; ks < 8; ks++) {
        uint32_t ph0, ph1, ph2, ph3, pl0, pl1, pl2, pl3;
        LDSM_X4(ph0, ph1, ph2, ph3, pBaseH + ks*32);
        LDSM_X4(pl0, pl1, pl2, pl3, pBaseL + ks*32);
#pragma unroll
        for (int p = 0; p < 4; p++) {
            uint32_t vh0, vh1, vh2, vh3, vl0, vl1, vl2, vl3;
            LDSM_X4_T(vh0, vh1, vh2, vh3, vBaseH + ks*2304 + p*32);
            LDSM_X4_T(vl0, vl1, vl2, vl3, vBaseL + ks*2304 + p*32);
            mma_bf16(C2[2*p],   ph0, ph1, ph2, ph3, vh0, vh1);
            mma_bf16(C2[2*p+1], ph0, ph1, ph2, ph3, vh2, vh3);
            mma_bf16(C2[2*p],   ph0, ph1, ph2, ph3, vl0, vl1);
            mma_bf16(C2[2*p+1], ph0, ph1, ph2, ph3, vl2, vl3);
            mma_bf16(C2[2*p],   pl0, pl1, pl2, pl3, vh0, vh1);
            mma_bf16(C2[2*p+1], pl0, pl1, pl2, pl3, vh2, vh3);
        }
    }
    __syncthreads();                        // P/V reads done before next-chunk staging
}

// ======================= kernel 3: flash over 4 chunks (kernel_3 @ V) ==========
__global__ __launch_bounds__(256) void r1ker(const float* __restrict__ Kg,
                                             const float* __restrict__ Vg) {
    extern __shared__ char smem[];
    uint32_t sb = smem_to_u32(smem);
    int hh = blockIdx.x, s = blockIdx.y, tid = threadIdx.x;
    int wid = tid >> 5, lane = tid & 31;

    float C2[8][4] = {};
    float m0 = -3.402823466e38f, m1 = -3.402823466e38f, s0 = 0.f, s1 = 0.f;

    for (int c = 0; c < CHUNKS; c++) {
        int kc = s * CHUNKS + c;
        stage_split(smem, OFF_AH, OFF_AL, d_nr + (size_t)hh * MSEL * DIMX, tid);
        stage_split(smem, OFF_BH, OFF_BL, Kg + ((size_t)hh * NTOK + kc * MSEL) * DIMX, tid);
        stage_split(smem, OFF_VH, OFF_VL, Vg + ((size_t)hh * NTOK + kc * MSEL) * DIMX, tid);
        __syncthreads();
        attn_tile_online(smem, sb, wid, lane, C2, m0, m1, s0, s1);
    }

    size_t base = (size_t)(hh * SPLITS + s) * MSEL;
    int grow0 = wid*16 + (lane >> 2);
    int pcol = (lane & 3) * 2;
    if ((lane & 3) == 0) {
        d_pmax[base + grow0]     = m0;  d_psum[base + grow0]     = s0;
        d_pmax[base + grow0 + 8] = m1;  d_psum[base + grow0 + 8] = s1;
    }
    float* z0 = d_pZ + (base + grow0) * DIMX;
    float* z1 = z0 + 8 * DIMX;
#pragma unroll
    for (int t = 0; t < 8; t++) {
        *reinterpret_cast<float2*>(&z0[t*8 + pcol]) = make_float2(C2[t][0], C2[t][1]);
        *reinterpret_cast<float2*>(&z1[t*8 + pcol]) = make_float2(C2[t][2], C2[t][3]);
    }
}

// ======================= kernel 4: combine splits =======================
__global__ void combiner() {
    int hh = blockIdx.x;
    int r  = blockIdx.y * 16 + threadIdx.y;
    int d  = threadIdx.x * 4;
    const float* pm = d_pmax + (size_t)hh * SPLITS * MSEL;
    const float* ps = d_psum + (size_t)hh * SPLITS * MSEL;
    float M = -3.402823466e38f;
#pragma unroll
    for (int s = 0; s < SPLITS; s++) M = fmaxf(M, pm[s * MSEL + r]);
    float l = 0.f;
    float4 z = make_float4(0.f, 0.f, 0.f, 0.f);
#pragma unroll
    for (int s = 0; s < SPLITS; s++) {
        float w = __expf(pm[s * MSEL + r] - M);
        l += ps[s * MSEL + r] * w;
        float4 pz = *reinterpret_cast<const float4*>(
            &d_pZ[((size_t)(hh * SPLITS + s) * MSEL + r) * DIMX + d]);
        z.x += w * pz.x; z.y += w * pz.y; z.z += w * pz.z; z.w += w * pz.w;
    }
    float inv = 1.f / l;
    *reinterpret_cast<float4*>(&d_Zm[((size_t)hh * MSEL + r) * DIMX + d]) =
        make_float4(z.x * inv, z.y * inv, z.z * inv, z.w * inv);
}

// ======================= Newton-Schulz: fused per-iteration TC kernel =======================
__global__ __launch_bounds__(256) void vminit() {
    int hh = blockIdx.x;
    float inv = 1.f / __uint_as_float(d_gmax_bits);
    const float* K2h = d_K2m + (size_t)hh * MSEL * MSEL;
    float* Vh = d_Vm0 + (size_t)hh * MSEL * MSEL;
    for (int i = threadIdx.x; i < MSEL * MSEL; i += 256) {
        int r = i >> 7, c = i & 127;
        Vh[i] = K2h[c * MSEL + r] * inv;
    }
}

// stage [128x128] fp32 -> split bf16 tile (pitch 136 halves = 272B), hi at off, lo at off+34816
__device__ __forceinline__ void stage_split128(char* smem, int off,
                                               const float* __restrict__ g, int tid) {
    for (int i = tid; i < 8192; i += 256) {
        int r = i >> 6, c2 = (i & 63) * 2;
        float2 v = *reinterpret_cast<const float2*>(&g[r*128 + c2]);
        __nv_bfloat16 h0, l0, h1, l1;
        bf16split(v.x, h0, l0); bf16split(v.y, h1, l1);
        int ob = r*272 + c2*2;
        *(__nv_bfloat162*)(smem + off + ob)         = __halves2bfloat162(h0, h1);
        *(__nv_bfloat162*)(smem + off + 34816 + ob) = __halves2bfloat162(l0, l1);
    }
}

// C[128x128] = A @ B (both split-bf16 in smem, 3-product); per-warp rows wid*16..+15
__device__ __forceinline__ void mm_tc(uint32_t sb, int offA, int offB,
                                      int wid, int lane, float C[16][4]) {
#pragma unroll
    for (int t = 0; t < 16; t++) { C[t][0] = 0.f; C[t][1] = 0.f; C[t][2] = 0.f; C[t][3] = 0.f; }
    uint32_t aH = sb + offA + (wid*16 + (lane & 15))*272 + ((lane >> 4) << 4);
    uint32_t aL = aH + 34816;
    uint32_t bH = sb + offB + (lane & 15)*272 + ((lane >> 4) << 4);
    uint32_t bL = bH + 34816;
#pragma unroll
    for (int ks = 0; ks < 8; ks++) {
        uint32_t ah0, ah1, ah2, ah3, al0, al1, al2, al3;
        LDSM_X4(ah0, ah1, ah2, ah3, aH + ks*32);
        LDSM_X4(al0, al1, al2, al3, aL + ks*32);
#pragma unroll
        for (int p = 0; p < 8; p++) {
            uint32_t bh0, bh1, bh2, bh3, bl0, bl1, bl2, bl3;
            LDSM_X4_T(bh0, bh1, bh2, bh3, bH + ks*4352 + p*32);
            LDSM_X4_T(bl0, bl1, bl2, bl3, bL + ks*4352 + p*32);
            mma_bf16(C[2*p],   ah0, ah1, ah2, ah3, bh0, bh1);
            mma_bf16(C[2*p+1], ah0, ah1, ah2, ah3, bh2, bh3);
            mma_bf16(C[2*p],   ah0, ah1, ah2, ah3, bl0, bl1);
            mma_bf16(C[2*p+1], ah0, ah1, ah2, ah3, bl2, bl3);
            mma_bf16(C[2*p],   al0, al1, al2, al3, bh0, bh1);
            mma_bf16(C[2*p+1], al0, al1, al2, al3, bh2, bh3);
        }
    }
}

// write per-warp C fragments as split-bf16 into buffer at off
__device__ __forceinline__ void store_split(char* smem, int off, int wid, int lane,
                                            const float C[16][4]) {
    int r0 = wid*16 + (lane >> 2);
    int cb0 = (lane & 3) * 2;
#pragma unroll
    for (int t = 0; t < 16; t++) {
        int cb = (t*8 + cb0) * 2;
        __nv_bfloat16 h0, l0, h1, l1;
        bf16split(C[t][0], h0, l0); bf16split(C[t][1], h1, l1);
        *(__nv_bfloat162*)(smem + off + r0*272 + cb)         = __halves2bfloat162(h0, h1);
        *(__nv_bfloat162*)(smem + off + 34816 + r0*272 + cb) = __halves2bfloat162(l0, l1);
        bf16split(C[t][2], h0, l0); bf16split(C[t][3], h1, l1);
        *(__nv_bfloat162*)(smem + off + (r0+8)*272 + cb)         = __halves2bfloat162(h0, h1);
        *(__nv_bfloat162*)(smem + off + 34816 + (r0+8)*272 + cb) = __halves2bfloat162(l0, l1);
    }
}
__device__ __forceinline__ float read_split(const char* smem, int off, int r, int c) {
    float h = __bfloat162float(*(const __nv_bfloat16*)(smem + off + r*272 + c*2));
    float l = __bfloat162float(*(const __nv_bfloat16*)(smem + off + 34816 + r*272 + c*2));
    return h + l;
}

// one Newton iteration: Vm <- 0.25*Vm@(13I -15KV +7KV^2 -KV^3), KV = Km@Vm. 1 CTA/head.
__global__ __launch_bounds__(256) void newton_iter() {
    extern __shared__ char smem[];
    uint32_t sb = smem_to_u32(smem);
    int hh = blockIdx.x, tid = threadIdx.x;
    int wid = tid >> 5, lane = tid & 31;
    float R[16][4];

    stage_split128(smem, NB_K, d_K2m + (size_t)hh * MSEL * MSEL, tid);
    stage_split128(smem, NB_V, d_Vm0 + (size_t)hh * MSEL * MSEL, tid);
    __syncthreads();

    mm_tc(sb, NB_K, NB_V, wid, lane, R);          // KV = Km @ Vm
    __syncthreads();
    store_split(smem, NB_K, wid, lane, R);        // BK <- KV (Km dead)
    __syncthreads();

    mm_tc(sb, NB_K, NB_K, wid, lane, R);          // P2 = KV @ KV
    __syncthreads();
    store_split(smem, NB_T, wid, lane, R);        // BT <- P2
    __syncthreads();

    mm_tc(sb, NB_K, NB_T, wid, lane, R);          // P3 = KV @ P2
    {                                              // E = 13I -15KV +7P2 -P3 (in regs)
        int r0 = wid*16 + (lane >> 2);
        int cb0 = (lane & 3) * 2;
#pragma unroll
        for (int t = 0; t < 16; t++) {
            int c = t*8 + cb0;
#pragma unroll
            for (int j = 0; j < 4; j++) {
                int rr = r0 + ((j >> 1) << 3);
                int cc = c + (j & 1);
                float kv = read_split(smem, NB_K, rr, cc);
                float p2 = read_split(smem, NB_T, rr, cc);
                float e = -15.f*kv + 7.f*p2 - R[t][j];
                if (rr == cc) e += 13.f;
                R[t][j] = e;
            }
        }
    }
    __syncthreads();
    store_split(smem, NB_T, wid, lane, R);        // BT <- E
    __syncthreads();

    mm_tc(sb, NB_V, NB_T, wid, lane, R);          // Vm @ E
    {
        float* out = d_Vm0 + (size_t)hh * MSEL * MSEL;
        int r0 = wid*16 + (lane >> 2);
        int cb0 = (lane & 3) * 2;
#pragma unroll
        for (int t = 0; t < 16; t++) {
            int c = t*8 + cb0;
            *reinterpret_cast<float2*>(&out[r0*128 + c]) =
                make_float2(0.25f*R[t][0], 0.25f*R[t][1]);
            *reinterpret_cast<float2*>(&out[(r0+8)*128 + c]) =
                make_float2(0.25f*R[t][2], 0.25f*R[t][3]);
        }
    }
}

// W = Vm_final @ Z  (128x64), grid (48, 2)
__global__ __launch_bounds__(256) void wker() {
    __shared__ float As[32][65];
    __shared__ float Bs[32][65];
    int hh = blockIdx.x;
    const float* Vm = d_Vm0 + (size_t)hh * MSEL * MSEL;
    const float* Z  = d_Zm + (size_t)hh * MSEL * DIMX;
    int r0 = blockIdx.y * 64;
    int tid = threadIdx.x, ty = tid >> 4, tx = tid & 15;
    float acc[4][4] = {};
    for (int kc = 0; kc < MSEL; kc += 32) {
        for (int i = tid; i < 2048; i += 256) {
            int m = i >> 5, k = i & 31;
            As[k][m] = Vm[(r0 + m) * MSEL + kc + k];
        }
        for (int i = tid; i < 2048; i += 256) {
            int k = i >> 6, n = i & 63;
            Bs[k][n] = Z[(kc + k) * DIMX + n];
        }
        __syncthreads();
#pragma unroll 8
        for (int k = 0; k < 32; k++) {
            float a[4], b[4];
#pragma unroll
            for (int i = 0; i < 4; i++) a[i] = As[k][ty*4 + i];
#pragma unroll
            for (int j = 0; j < 4; j++) b[j] = Bs[k][tx*4 + j];
#pragma unroll
            for (int i = 0; i < 4; i++)
#pragma unroll
                for (int j = 0; j < 4; j++)
                    acc[i][j] += a[i] * b[j];
        }
        __syncthreads();
    }
#pragma unroll
    for (int i = 0; i < 4; i++)
#pragma unroll
        for (int j = 0; j < 4; j++)
            d_Wm[(size_t)hh * MSEL * DIMX + (r0 + ty*4 + i) * DIMX + tx*4 + j] = acc[i][j];
}

// ======================= final: X = softmax(Q @ nc^T) @ W, tensor cores ==========
__global__ __launch_bounds__(256) void eker(const float* __restrict__ Qg,
                                            float* __restrict__ Xg) {
    extern __shared__ char smem[];
    uint32_t sb = smem_to_u32(smem);
    int hh = blockIdx.x, q0 = blockIdx.y * MSEL, tid = threadIdx.x;
    int wid = tid >> 5, lane = tid & 31;

    stage_split(smem, OFF_AH, OFF_AL, Qg + ((size_t)hh * NTOK + q0) * DIMX, tid);
    stage_split(smem, OFF_BH, OFF_BL, d_nc + (size_t)hh * MSEL * DIMX, tid);
    stage_split(smem, OFF_VH, OFF_VL, d_Wm + (size_t)hh * MSEL * DIMX, tid);
    __syncthreads();

    float C2[8][4] = {};
    float m0 = -3.402823466e38f, m1 = -3.402823466e38f, s0 = 0.f, s1 = 0.f;
    attn_tile_online(smem, sb, wid, lane, C2, m0, m1, s0, s1);

    float rinv0 = 1.f / s0, rinv1 = 1.f / s1;
    int grow0 = wid*16 + (lane >> 2);
    int pcol = (lane & 3) * 2;
    float* x0 = Xg + ((size_t)hh * NTOK + q0 + grow0) * DIMX;
    float* x1 = x0 + 8 * DIMX;
#pragma unroll
    for (int t = 0; t < 8; t++) {
        *reinterpret_cast<float2*>(&x0[t*8 + pcol]) =
            make_float2(C2[t][0] * rinv0, C2[t][1] * rinv0);
        *reinterpret_cast<float2*>(&x1[t*8 + pcol]) =
            make_float2(C2[t][2] * rinv1, C2[t][3] * rinv1);
    }
}

// ======================= launch =======================
extern "C" void kernel_launch(void* const* d_in, const int* in_sizes, int n_in,
                              void* d_out, int out_size) {
    const float* Q = (const float*)d_in[0];
    const float* K = (const float*)d_in[1];
    const float* V = (const float*)d_in[2];
    float* X = (float*)d_out;

    const int SMEM_MK = (2 * DIMX * PITCH + MSEL) * 4;
    cudaFuncSetAttribute(mker,        cudaFuncAttributeMaxDynamicSharedMemorySize, SMEM_MK);
    cudaFuncSetAttribute(r1ker,       cudaFuncAttributeMaxDynamicSharedMemorySize, SMEM_TC);
    cudaFuncSetAttribute(eker,        cudaFuncAttributeMaxDynamicSharedMemorySize, SMEM_TC);
    cudaFuncSetAttribute(newton_iter, cudaFuncAttributeMaxDynamicSharedMemorySize, NB_SZ);

    topk_gather<<<dim3(BHX, 2), 256>>>(Q, K);
    mker<<<BHX, 256, SMEM_MK>>>();
    r1ker<<<dim3(BHX, SPLITS), 256, SMEM_TC>>>(K, V);
    combiner<<<dim3(BHX, 8), dim3(16, 16)>>>();
    vminit<<<BHX, 256>>>();

    for (int it = 0; it < 6; it++)
        newton_iter<<<BHX, 256, NB_SZ>>>();

    wker<<<dim3(BHX, 2), 256>>>();
    eker<<<dim3(BHX, NTOK / MSEL), 256, SMEM_TC>>>(Q, X);
}

// round 9
// speedup vs baseline: 1.7951x; 1.0364x over previous
#include <cuda_runtime.h>
#include <cuda_bf16.h>
#include <cstdint>
#include <cstddef>

#define BHX    48
#define NTOK   8192
#define DIMX   64
#define MSEL   128
#define SPLITS 8
#define CHUNKS 8          // key chunks of 128 per r1ker CTA
#define EQC    8          // Q chunks per eker CTA
#define PITCH  132

// ======================= mma.sync / ldmatrix helpers =======================
__device__ __forceinline__ uint32_t smem_to_u32(const void* p) {
    uint32_t a;
    asm("{ .reg .u64 t; cvta.to.shared.u64 t, %1; cvt.u32.u64 %0, t; }" : "=r"(a) : "l"(p));
    return a;
}
#define LDSM_X4(r0, r1, r2, r3, addr) \
    asm volatile("ldmatrix.sync.aligned.m8n8.x4.shared.b16 {%0,%1,%2,%3}, [%4];" \
                 : "=r"(r0), "=r"(r1), "=r"(r2), "=r"(r3) : "r"(addr))
#define LDSM_X4_T(r0, r1, r2, r3, addr) \
    asm volatile("ldmatrix.sync.aligned.m8n8.x4.trans.shared.b16 {%0,%1,%2,%3}, [%4];" \
                 : "=r"(r0), "=r"(r1), "=r"(r2), "=r"(r3) : "r"(addr))
__device__ __forceinline__ void mma_bf16(float* c, uint32_t a0, uint32_t a1, uint32_t a2, uint32_t a3,
                                         uint32_t b0, uint32_t b1) {
    asm volatile("mma.sync.aligned.m16n8k16.row.col.f32.bf16.bf16.f32 "
                 "{%0,%1,%2,%3}, {%4,%5,%6,%7}, {%8,%9}, {%0,%1,%2,%3};"
                 : "+f"(c[0]), "+f"(c[1]), "+f"(c[2]), "+f"(c[3])
                 : "r"(a0), "r"(a1), "r"(a2), "r"(a3), "r"(b0), "r"(b1));
}
__device__ __forceinline__ void bf16split(float v, __nv_bfloat16& h, __nv_bfloat16& l) {
    h = __float2bfloat16(v);
    l = __float2bfloat16(v - __bfloat162float(h));
}

// attention smem: A/B/V [128 x 72 halves] (144B pitch) + dedicated P [128 x 136] (272B pitch)
#define OFF_AH   0
#define OFF_AL   18432
#define OFF_BH   36864
#define OFF_BL   55296
#define OFF_VH   73728
#define OFF_VL   92160
#define OFF_PH   110592
#define OFF_PL   145408
#define SMEM_TC  180224

// newton smem: 3 matrices [128 x 136 halves] (272B pitch), hi half then lo half (+34816)
#define NB_K   0
#define NB_V   69632
#define NB_T   139264
#define NB_SZ  208896

// ======================= scratch =======================
__device__ float d_nc [BHX*MSEL*DIMX];
__device__ float d_nr [BHX*MSEL*DIMX];
__device__ float d_K2m[BHX*MSEL*MSEL];
__device__ float d_Vm0[BHX*MSEL*MSEL];
__device__ float d_Zm [BHX*MSEL*DIMX];
__device__ float d_Wm [BHX*MSEL*DIMX];
__device__ unsigned int d_gmax_bits;
__device__ float d_pmax[BHX*SPLITS*MSEL];
__device__ float d_psum[BHX*SPLITS*MSEL];
__device__ float d_pZ  [(size_t)BHX*SPLITS*MSEL*DIMX];

// ======================= SIMT helpers =======================
__device__ __forceinline__ float grp_max(float v) {
    v = fmaxf(v, __shfl_xor_sync(0xffffffffu, v, 8));
    v = fmaxf(v, __shfl_xor_sync(0xffffffffu, v, 4));
    v = fmaxf(v, __shfl_xor_sync(0xffffffffu, v, 2));
    v = fmaxf(v, __shfl_xor_sync(0xffffffffu, v, 1));
    return v;
}
__device__ __forceinline__ float grp_sum(float v) {
    v += __shfl_xor_sync(0xffffffffu, v, 8);
    v += __shfl_xor_sync(0xffffffffu, v, 4);
    v += __shfl_xor_sync(0xffffffffu, v, 2);
    v += __shfl_xor_sync(0xffffffffu, v, 1);
    return v;
}
__device__ __forceinline__ void load_tileT(float* dst, const float* __restrict__ g, int tid) {
    for (int i = tid; i < MSEL*DIMX; i += 256) {
        int m = i >> 6, k = i & 63;
        dst[k*PITCH + m] = g[i];
    }
}
__device__ __forceinline__ void mm128(const float* As, const float* Bs,
                                      float acc[8][8], int ty, int tx) {
#pragma unroll 8
    for (int k = 0; k < DIMX; k++) {
        float4 a0 = *reinterpret_cast<const float4*>(&As[k*PITCH + ty*8]);
        float4 a1 = *reinterpret_cast<const float4*>(&As[k*PITCH + ty*8 + 4]);
        float4 b0 = *reinterpret_cast<const float4*>(&Bs[k*PITCH + tx*8]);
        float4 b1 = *reinterpret_cast<const float4*>(&Bs[k*PITCH + tx*8 + 4]);
        float a[8] = {a0.x,a0.y,a0.z,a0.w,a1.x,a1.y,a1.z,a1.w};
        float b[8] = {b0.x,b0.y,b0.z,b0.w,b1.x,b1.y,b1.z,b1.w};
#pragma unroll
        for (int i = 0; i < 8; i++)
#pragma unroll
            for (int j = 0; j < 8; j++)
                acc[i][j] += a[i] * b[j];
    }
}

// stage [128x64] fp32 -> split bf16 padded tile (pitch 72 halves)
__device__ __forceinline__ void stage_split(char* smem, int offH, int offL,
                                            const float* __restrict__ g, int tid) {
    for (int i = tid; i < 4096; i += 256) {
        int r = i >> 5, c2 = (i & 31) * 2;
        float2 v = *reinterpret_cast<const float2*>(&g[r*64 + c2]);
        __nv_bfloat16 h0, l0, h1, l1;
        bf16split(v.x, h0, l0); bf16split(v.y, h1, l1);
        int ob = r*144 + c2*2;
        *(__nv_bfloat162*)(smem + offH + ob) = __halves2bfloat162(h0, h1);
        *(__nv_bfloat162*)(smem + offL + ob) = __halves2bfloat162(l0, l1);
    }
}

// ======================= kernel 1: segmented top-k + sort + gather =======================
__global__ __launch_bounds__(256) void topk_gather(const float* __restrict__ Qg,
                                                   const float* __restrict__ Kg) {
    __shared__ float vals[NTOK];
    __shared__ float pmax[256];
    __shared__ int   pidx[256];
    __shared__ int   sel[MSEL];
    __shared__ int   sorted[MSEL];
    __shared__ int   bcast;
    int hh = blockIdx.x, which = blockIdx.y, tid = threadIdx.x;
    const float* src = (which == 0 ? Kg : Qg) + (size_t)hh * NTOK * DIMX;

    if (hh == 0 && which == 0 && tid == 0) d_gmax_bits = 0u;

    for (int i = tid; i < NTOK; i += 256) vals[i] = src[(size_t)i * DIMX];
    if (tid == 0) vals[0] = -3.402823466e38f;   // idx 0 excluded, re-added later
    __syncthreads();

    {   // per-thread segment maxima (32 contiguous elems each); first-max semantics
        float bv = -3.402823466e38f; int bi = tid * 32;
        for (int j = 0; j < 32; j++) {
            float v = vals[tid*32 + j];
            if (v > bv) { bv = v; bi = tid*32 + j; }
        }
        pmax[tid] = bv; pidx[tid] = bi;
    }
    __syncthreads();

    for (int r = 0; r < MSEL - 1; r++) {
        if (tid < 32) {
            float bv = -3.402823466e38f; int bi = NTOK;
            for (int k = tid; k < 256; k += 32) {
                float v = pmax[k]; int ix = pidx[k];
                if (v > bv || (v == bv && ix < bi)) { bv = v; bi = ix; }
            }
#pragma unroll
            for (int o = 16; o > 0; o >>= 1) {
                float ov = __shfl_down_sync(0xffffffffu, bv, o);
                int   oi = __shfl_down_sync(0xffffffffu, bi, o);
                if (ov > bv || (ov == bv && oi < bi)) { bv = ov; bi = oi; }
            }
            if (tid == 0) { sel[r] = bi; vals[bi] = -3.402823466e38f; bcast = bi; }
        }
        __syncthreads();
        int win = bcast;
        if (tid == (win >> 5)) {        // only the winner's segment owner rescans
            float bv = -3.402823466e38f; int bi = tid * 32;
            for (int j = 0; j < 32; j++) {
                float v = vals[tid*32 + j];
                if (v > bv) { bv = v; bi = tid*32 + j; }
            }
            pmax[tid] = bv; pidx[tid] = bi;
        }
        __syncthreads();
    }
    if (tid == 0) sel[MSEL - 1] = 0;
    __syncthreads();

    if (tid < MSEL) {                   // rank sort (indices distinct)
        int my = sel[tid], rank = 0;
        for (int j = 0; j < MSEL; j++) rank += (sel[j] < my);
        sorted[rank] = my;
    }
    __syncthreads();

    float* dst = (which == 0 ? d_nc : d_nr) + (size_t)hh * MSEL * DIMX;
    for (int i = tid; i < MSEL * DIMX; i += 256) {
        int p = i >> 6, d = i & 63;
        dst[i] = src[(size_t)sorted[p] * DIMX + d];
    }
}

// ======================= kernel 2: kernel_2 = softmax(nr @ nc^T), colsum max =======================
__global__ __launch_bounds__(256) void mker() {
    extern __shared__ float sm[];
    float* As = sm;
    float* Bs = sm + DIMX * PITCH;
    float* cs = sm + 2 * DIMX * PITCH;
    int hh = blockIdx.x, tid = threadIdx.x;
    int ty = tid >> 4, tx = tid & 15;
    load_tileT(As, d_nr + (size_t)hh * MSEL * DIMX, tid);
    load_tileT(Bs, d_nc + (size_t)hh * MSEL * DIMX, tid);
    if (tid < MSEL) cs[tid] = 0.f;
    __syncthreads();

    float acc[8][8] = {};
    mm128(As, Bs, acc, ty, tx);

    float* K2h = d_K2m + (size_t)hh * MSEL * MSEL;
    float colp[8] = {};
#pragma unroll
    for (int i = 0; i < 8; i++) {
        float mx = acc[i][0];
#pragma unroll
        for (int j = 1; j < 8; j++) mx = fmaxf(mx, acc[i][j]);
        mx = grp_max(mx);
        float s = 0.f;
#pragma unroll
        for (int j = 0; j < 8; j++) { acc[i][j] = __expf(acc[i][j] - mx); s += acc[i][j]; }
        s = grp_sum(s);
        float inv = 1.f / s;
#pragma unroll
        for (int j = 0; j < 8; j++) {
            float p = acc[i][j] * inv;
            K2h[(ty*8 + i) * MSEL + tx*8 + j] = p;
            colp[j] += p;
        }
    }
#pragma unroll
    for (int j = 0; j < 8; j++) atomicAdd(&cs[tx*8 + j], colp[j]);
    __syncthreads();
    if (tid < MSEL) atomicMax(&d_gmax_bits, __float_as_uint(cs[tid]));
}

// ======================= MMA1 + online softmax + MMA2 tile body (no aliasing) =======================
// caller guarantees A/B/V staged + __syncthreads before entry; no trailing barrier.
__device__ __forceinline__ void attn_tile_online(char* smem, uint32_t sb, int wid, int lane,
                                                 float C2[8][4],
                                                 float& m0, float& m1, float& s0, float& s1) {
    float C1[16][4] = {};
    uint32_t aBaseH = sb + OFF_AH + (wid*16 + (lane & 15))*144 + ((lane >> 4) << 4);
    uint32_t aBaseL = aBaseH + 18432;
    int bRow = (lane & 7) + ((lane >> 4) << 3);
    uint32_t bBaseH = sb + OFF_BH + bRow*144 + (((lane >> 3) & 1) << 4);
    uint32_t bBaseL = bBaseH + 18432;

#pragma unroll
    for (int ks = 0; ks < 4; ks++) {
        uint32_t ah0, ah1, ah2, ah3, al0, al1, al2, al3;
        LDSM_X4(ah0, ah1, ah2, ah3, aBaseH + ks*32);
        LDSM_X4(al0, al1, al2, al3, aBaseL + ks*32);
#pragma unroll
        for (int p = 0; p < 8; p++) {
            uint32_t bh0, bh1, bh2, bh3, bl0, bl1, bl2, bl3;
            LDSM_X4(bh0, bh1, bh2, bh3, bBaseH + p*2304 + ks*32);
            LDSM_X4(bl0, bl1, bl2, bl3, bBaseL + p*2304 + ks*32);
            mma_bf16(C1[2*p],   ah0, ah1, ah2, ah3, bh0, bh1);
            mma_bf16(C1[2*p+1], ah0, ah1, ah2, ah3, bh2, bh3);
            mma_bf16(C1[2*p],   ah0, ah1, ah2, ah3, bl0, bl1);
            mma_bf16(C1[2*p+1], ah0, ah1, ah2, ah3, bl2, bl3);
            mma_bf16(C1[2*p],   al0, al1, al2, al3, bh0, bh1);
            mma_bf16(C1[2*p+1], al0, al1, al2, al3, bh2, bh3);
        }
    }

    float cx0 = -3.402823466e38f, cx1 = -3.402823466e38f;
#pragma unroll
    for (int t = 0; t < 16; t++) {
        cx0 = fmaxf(cx0, fmaxf(C1[t][0], C1[t][1]));
        cx1 = fmaxf(cx1, fmaxf(C1[t][2], C1[t][3]));
    }
    cx0 = fmaxf(cx0, __shfl_xor_sync(0xffffffffu, cx0, 1));
    cx0 = fmaxf(cx0, __shfl_xor_sync(0xffffffffu, cx0, 2));
    cx1 = fmaxf(cx1, __shfl_xor_sync(0xffffffffu, cx1, 1));
    cx1 = fmaxf(cx1, __shfl_xor_sync(0xffffffffu, cx1, 2));

    float mn0 = fmaxf(m0, cx0), mn1 = fmaxf(m1, cx1);
    float f0 = __expf(m0 - mn0), f1 = __expf(m1 - mn1);
    float su0 = 0.f, su1 = 0.f;
#pragma unroll
    for (int t = 0; t < 16; t++) {
        C1[t][0] = __expf(C1[t][0] - mn0); C1[t][1] = __expf(C1[t][1] - mn0);
        C1[t][2] = __expf(C1[t][2] - mn1); C1[t][3] = __expf(C1[t][3] - mn1);
        su0 += C1[t][0] + C1[t][1];
        su1 += C1[t][2] + C1[t][3];
    }
    su0 += __shfl_xor_sync(0xffffffffu, su0, 1);
    su0 += __shfl_xor_sync(0xffffffffu, su0, 2);
    su1 += __shfl_xor_sync(0xffffffffu, su1, 1);
    su1 += __shfl_xor_sync(0xffffffffu, su1, 2);
    s0 = s0 * f0 + su0;  s1 = s1 * f1 + su1;
    m0 = mn0;            m1 = mn1;
#pragma unroll
    for (int t = 0; t < 8; t++) {
        C2[t][0] *= f0; C2[t][1] *= f0;
        C2[t][2] *= f1; C2[t][3] *= f1;
    }

    // P rows wid*16..+15 are produced AND consumed by warp wid only -> warp-local sync
    int prow0 = wid*16 + (lane >> 2);
    int pcol  = (lane & 3) * 2;
#pragma unroll
    for (int t = 0; t < 16; t++) {
        int cb = (t*8 + pcol) * 2;
        __nv_bfloat16 h0, l0, h1, l1;
        bf16split(C1[t][0], h0, l0); bf16split(C1[t][1], h1, l1);
        *(__nv_bfloat162*)(smem + OFF_PH + prow0*272 + cb) = __halves2bfloat162(h0, h1);
        *(__nv_bfloat162*)(smem + OFF_PL + prow0*272 + cb) = __halves2bfloat162(l0, l1);
        bf16split(C1[t][2], h0, l0); bf16split(C1[t][3], h1, l1);
        *(__nv_bfloat162*)(smem + OFF_PH + (prow0+8)*272 + cb) = __halves2bfloat162(h0, h1);
        *(__nv_bfloat162*)(smem + OFF_PL + (prow0+8)*272 + cb) = __halves2bfloat162(l0, l1);
    }
    __syncwarp();

    uint32_t pBaseH = sb + OFF_PH + (wid*16 + (lane & 15))*272 + ((lane >> 4) << 4);
    uint32_t pBaseL = pBaseH + (OFF_PL - OFF_PH);
    uint32_t vBaseH = sb + OFF_VH + (lane & 15)*144 + ((lane >> 4) << 4);
    uint32_t vBaseL = vBaseH + 18432;
#pragma unroll
    for (int ks = 0; ks < 8; ks++) {
        uint32_t ph0, ph1, ph2, ph3, pl0, pl1, pl2, pl3;
        LDSM_X4(ph0, ph1, ph2, ph3, pBaseH + ks*32);
        LDSM_X4(pl0, pl1, pl2, pl3, pBaseL + ks*32);
#pragma unroll
        for (int p = 0; p < 4; p++) {
            uint32_t vh0, vh1, vh2, vh3, vl0, vl1, vl2, vl3;
            LDSM_X4_T(vh0, vh1, vh2, vh3, vBaseH + ks*2304 + p*32);
            LDSM_X4_T(vl0, vl1, vl2, vl3, vBaseL + ks*2304 + p*32);
            mma_bf16(C2[2*p],   ph0, ph1, ph2, ph3, vh0, vh1);
            mma_bf16(C2[2*p+1], ph0, ph1, ph2, ph3, vh2, vh3);
            mma_bf16(C2[2*p],   ph0, ph1, ph2, ph3, vl0, vl1);
            mma_bf16(C2[2*p+1], ph0, ph1, ph2, ph3, vl2, vl3);
            mma_bf16(C2[2*p],   pl0, pl1, pl2, pl3, vh0, vh1);
            mma_bf16(C2[2*p+1], pl0, pl1, pl2, pl3, vh2, vh3);
        }
    }
}

// ======================= kernel 3: flash over 8 chunks (kernel_3 @ V) ==========
__global__ __launch_bounds__(256) void r1ker(const float* __restrict__ Kg,
                                             const float* __restrict__ Vg) {
    extern __shared__ char smem[];
    uint32_t sb = smem_to_u32(smem);
    int hh = blockIdx.x, s = blockIdx.y, tid = threadIdx.x;
    int wid = tid >> 5, lane = tid & 31;

    stage_split(smem, OFF_AH, OFF_AL, d_nr + (size_t)hh * MSEL * DIMX, tid);  // once

    float C2[8][4] = {};
    float m0 = -3.402823466e38f, m1 = -3.402823466e38f, s0 = 0.f, s1 = 0.f;

    for (int c = 0; c < CHUNKS; c++) {
        int kc = s * CHUNKS + c;
        __syncthreads();   // prior chunk's B/V reads (and A staging on c==0) complete
        stage_split(smem, OFF_BH, OFF_BL, Kg + ((size_t)hh * NTOK + kc * MSEL) * DIMX, tid);
        stage_split(smem, OFF_VH, OFF_VL, Vg + ((size_t)hh * NTOK + kc * MSEL) * DIMX, tid);
        __syncthreads();
        attn_tile_online(smem, sb, wid, lane, C2, m0, m1, s0, s1);
    }

    size_t base = (size_t)(hh * SPLITS + s) * MSEL;
    int grow0 = wid*16 + (lane >> 2);
    int pcol = (lane & 3) * 2;
    if ((lane & 3) == 0) {
        d_pmax[base + grow0]     = m0;  d_psum[base + grow0]     = s0;
        d_pmax[base + grow0 + 8] = m1;  d_psum[base + grow0 + 8] = s1;
    }
    float* z0 = d_pZ + (base + grow0) * DIMX;
    float* z1 = z0 + 8 * DIMX;
#pragma unroll
    for (int t = 0; t < 8; t++) {
        *reinterpret_cast<float2*>(&z0[t*8 + pcol]) = make_float2(C2[t][0], C2[t][1]);
        *reinterpret_cast<float2*>(&z1[t*8 + pcol]) = make_float2(C2[t][2], C2[t][3]);
    }
}

// ======================= kernel 4: combine splits =======================
__global__ void combiner() {
    int hh = blockIdx.x;
    int r  = blockIdx.y * 16 + threadIdx.y;
    int d  = threadIdx.x * 4;
    const float* pm = d_pmax + (size_t)hh * SPLITS * MSEL;
    const float* ps = d_psum + (size_t)hh * SPLITS * MSEL;
    float M = -3.402823466e38f;
#pragma unroll
    for (int s = 0; s < SPLITS; s++) M = fmaxf(M, pm[s * MSEL + r]);
    float l = 0.f;
    float4 z = make_float4(0.f, 0.f, 0.f, 0.f);
#pragma unroll
    for (int s = 0; s < SPLITS; s++) {
        float w = __expf(pm[s * MSEL + r] - M);
        l += ps[s * MSEL + r] * w;
        float4 pz = *reinterpret_cast<const float4*>(
            &d_pZ[((size_t)(hh * SPLITS + s) * MSEL + r) * DIMX + d]);
        z.x += w * pz.x; z.y += w * pz.y; z.z += w * pz.z; z.w += w * pz.w;
    }
    float inv = 1.f / l;
    *reinterpret_cast<float4*>(&d_Zm[((size_t)hh * MSEL + r) * DIMX + d]) =
        make_float4(z.x * inv, z.y * inv, z.z * inv, z.w * inv);
}

// ======================= Newton-Schulz: fused per-iteration TC kernel =======================
__global__ __launch_bounds__(256) void vminit() {
    int hh = blockIdx.x;
    float inv = 1.f / __uint_as_float(d_gmax_bits);
    const float* K2h = d_K2m + (size_t)hh * MSEL * MSEL;
    float* Vh = d_Vm0 + (size_t)hh * MSEL * MSEL;
    for (int i = threadIdx.x; i < MSEL * MSEL; i += 256) {
        int r = i >> 7, c = i & 127;
        Vh[i] = K2h[c * MSEL + r] * inv;
    }
}

__device__ __forceinline__ void stage_split128(char* smem, int off,
                                               const float* __restrict__ g, int tid) {
    for (int i = tid; i < 8192; i += 256) {
        int r = i >> 6, c2 = (i & 63) * 2;
        float2 v = *reinterpret_cast<const float2*>(&g[r*128 + c2]);
        __nv_bfloat16 h0, l0, h1, l1;
        bf16split(v.x, h0, l0); bf16split(v.y, h1, l1);
        int ob = r*272 + c2*2;
        *(__nv_bfloat162*)(smem + off + ob)         = __halves2bfloat162(h0, h1);
        *(__nv_bfloat162*)(smem + off + 34816 + ob) = __halves2bfloat162(l0, l1);
    }
}

__device__ __forceinline__ void mm_tc(uint32_t sb, int offA, int offB,
                                      int wid, int lane, float C[16][4]) {
#pragma unroll
    for (int t = 0; t < 16; t++) { C[t][0] = 0.f; C[t][1] = 0.f; C[t][2] = 0.f; C[t][3] = 0.f; }
    uint32_t aH = sb + offA + (wid*16 + (lane & 15))*272 + ((lane >> 4) << 4);
    uint32_t aL = aH + 34816;
    uint32_t bH = sb + offB + (lane & 15)*272 + ((lane >> 4) << 4);
    uint32_t bL = bH + 34816;
#pragma unroll
    for (int ks = 0; ks < 8; ks++) {
        uint32_t ah0, ah1, ah2, ah3, al0, al1, al2, al3;
        LDSM_X4(ah0, ah1, ah2, ah3, aH + ks*32);
        LDSM_X4(al0, al1, al2, al3, aL + ks*32);
#pragma unroll
        for (int p = 0; p < 8; p++) {
            uint32_t bh0, bh1, bh2, bh3, bl0, bl1, bl2, bl3;
            LDSM_X4_T(bh0, bh1, bh2, bh3, bH + ks*4352 + p*32);
            LDSM_X4_T(bl0, bl1, bl2, bl3, bL + ks*4352 + p*32);
            mma_bf16(C[2*p],   ah0, ah1, ah2, ah3, bh0, bh1);
            mma_bf16(C[2*p+1], ah0, ah1, ah2, ah3, bh2, bh3);
            mma_bf16(C[2*p],   ah0, ah1, ah2, ah3, bl0, bl1);
            mma_bf16(C[2*p+1], ah0, ah1, ah2, ah3, bl2, bl3);
            mma_bf16(C[2*p],   al0, al1, al2, al3, bh0, bh1);
            mma_bf16(C[2*p+1], al0, al1, al2, al3, bh2, bh3);
        }
    }
}

__device__ __forceinline__ void store_split(char* smem, int off, int wid, int lane,
                                            const float C[16][4]) {
    int r0 = wid*16 + (lane >> 2);
    int cb0 = (lane & 3) * 2;
#pragma unroll
    for (int t = 0; t < 16; t++) {
        int cb = (t*8 + cb0) * 2;
        __nv_bfloat16 h0, l0, h1, l1;
        bf16split(C[t][0], h0, l0); bf16split(C[t][1], h1, l1);
        *(__nv_bfloat162*)(smem + off + r0*272 + cb)         = __halves2bfloat162(h0, h1);
        *(__nv_bfloat162*)(smem + off + 34816 + r0*272 + cb) = __halves2bfloat162(l0, l1);
        bf16split(C[t][2], h0, l0); bf16split(C[t][3], h1, l1);
        *(__nv_bfloat162*)(smem + off + (r0+8)*272 + cb)         = __halves2bfloat162(h0, h1);
        *(__nv_bfloat162*)(smem + off + 34816 + (r0+8)*272 + cb) = __halves2bfloat162(l0, l1);
    }
}
__device__ __forceinline__ float read_split(const char* smem, int off, int r, int c) {
    float h = __bfloat162float(*(const __nv_bfloat16*)(smem + off + r*272 + c*2));
    float l = __bfloat162float(*(const __nv_bfloat16*)(smem + off + 34816 + r*272 + c*2));
    return h + l;
}

__global__ __launch_bounds__(256) void newton_iter() {
    extern __shared__ char smem[];
    uint32_t sb = smem_to_u32(smem);
    int hh = blockIdx.x, tid = threadIdx.x;
    int wid = tid >> 5, lane = tid & 31;
    float R[16][4];

    stage_split128(smem, NB_K, d_K2m + (size_t)hh * MSEL * MSEL, tid);
    stage_split128(smem, NB_V, d_Vm0 + (size_t)hh * MSEL * MSEL, tid);
    __syncthreads();

    mm_tc(sb, NB_K, NB_V, wid, lane, R);          // KV = Km @ Vm
    __syncthreads();
    store_split(smem, NB_K, wid, lane, R);        // BK <- KV
    __syncthreads();

    mm_tc(sb, NB_K, NB_K, wid, lane, R);          // P2 = KV @ KV
    __syncthreads();
    store_split(smem, NB_T, wid, lane, R);        // BT <- P2
    __syncthreads();

    mm_tc(sb, NB_K, NB_T, wid, lane, R);          // P3 = KV @ P2
    {                                              // E = 13I -15KV +7P2 -P3
        int r0 = wid*16 + (lane >> 2);
        int cb0 = (lane & 3) * 2;
#pragma unroll
        for (int t = 0; t < 16; t++) {
            int c = t*8 + cb0;
#pragma unroll
            for (int j = 0; j < 4; j++) {
                int rr = r0 + ((j >> 1) << 3);
                int cc = c + (j & 1);
                float kv = read_split(smem, NB_K, rr, cc);
                float p2 = read_split(smem, NB_T, rr, cc);
                float e = -15.f*kv + 7.f*p2 - R[t][j];
                if (rr == cc) e += 13.f;
                R[t][j] = e;
            }
        }
    }
    __syncthreads();
    store_split(smem, NB_T, wid, lane, R);        // BT <- E
    __syncthreads();

    mm_tc(sb, NB_V, NB_T, wid, lane, R);          // Vm @ E
    {
        float* out = d_Vm0 + (size_t)hh * MSEL * MSEL;
        int r0 = wid*16 + (lane >> 2);
        int cb0 = (lane & 3) * 2;
#pragma unroll
        for (int t = 0; t < 16; t++) {
            int c = t*8 + cb0;
            *reinterpret_cast<float2*>(&out[r0*128 + c]) =
                make_float2(0.25f*R[t][0], 0.25f*R[t][1]);
            *reinterpret_cast<float2*>(&out[(r0+8)*128 + c]) =
                make_float2(0.25f*R[t][2], 0.25f*R[t][3]);
        }
    }
}

// W = Vm_final @ Z  (128x64), grid (48, 2)
__global__ __launch_bounds__(256) void wker() {
    __shared__ float As[32][65];
    __shared__ float Bs[32][65];
    int hh = blockIdx.x;
    const float* Vm = d_Vm0 + (size_t)hh * MSEL * MSEL;
    const float* Z  = d_Zm + (size_t)hh * MSEL * DIMX;
    int r0 = blockIdx.y * 64;
    int tid = threadIdx.x, ty = tid >> 4, tx = tid & 15;
    float acc[4][4] = {};
    for (int kc = 0; kc < MSEL; kc += 32) {
        for (int i = tid; i < 2048; i += 256) {
            int m = i >> 5, k = i & 31;
            As[k][m] = Vm[(r0 + m) * MSEL + kc + k];
        }
        for (int i = tid; i < 2048; i += 256) {
            int k = i >> 6, n = i & 63;
            Bs[k][n] = Z[(kc + k) * DIMX + n];
        }
        __syncthreads();
#pragma unroll 8
        for (int k = 0; k < 32; k++) {
            float a[4], b[4];
#pragma unroll
            for (int i = 0; i < 4; i++) a[i] = As[k][ty*4 + i];
#pragma unroll
            for (int j = 0; j < 4; j++) b[j] = Bs[k][tx*4 + j];
#pragma unroll
            for (int i = 0; i < 4; i++)
#pragma unroll
                for (int j = 0; j < 4; j++)
                    acc[i][j] += a[i] * b[j];
        }
        __syncthreads();
    }
#pragma unroll
    for (int i = 0; i < 4; i++)
#pragma unroll
        for (int j = 0; j < 4; j++)
            d_Wm[(size_t)hh * MSEL * DIMX + (r0 + ty*4 + i) * DIMX + tx*4 + j] = acc[i][j];
}

// ======================= final: X = softmax(Q @ nc^T) @ W, 8 chunks/CTA ==========
__global__ __launch_bounds__(256) void eker(const float* __restrict__ Qg,
                                            float* __restrict__ Xg) {
    extern __shared__ char smem[];
    uint32_t sb = smem_to_u32(smem);
    int hh = blockIdx.x, tid = threadIdx.x;
    int wid = tid >> 5, lane = tid & 31;

    stage_split(smem, OFF_BH, OFF_BL, d_nc + (size_t)hh * MSEL * DIMX, tid);  // once
    stage_split(smem, OFF_VH, OFF_VL, d_Wm + (size_t)hh * MSEL * DIMX, tid);  // once

    int grow0 = wid*16 + (lane >> 2);
    int pcol = (lane & 3) * 2;

    for (int c = 0; c < EQC; c++) {
        int q0 = (blockIdx.y * EQC + c) * MSEL;
        __syncthreads();   // prior chunk's A reads complete (c==0: orders B/V staging too)
        stage_split(smem, OFF_AH, OFF_AL, Qg + ((size_t)hh * NTOK + q0) * DIMX, tid);
        __syncthreads();

        float C2[8][4] = {};
        float m0 = -3.402823466e38f, m1 = -3.402823466e38f, s0 = 0.f, s1 = 0.f;
        attn_tile_online(smem, sb, wid, lane, C2, m0, m1, s0, s1);

        float rinv0 = 1.f / s0, rinv1 = 1.f / s1;
        float* x0 = Xg + ((size_t)hh * NTOK + q0 + grow0) * DIMX;
        float* x1 = x0 + 8 * DIMX;
#pragma unroll
        for (int t = 0; t < 8; t++) {
            *reinterpret_cast<float2*>(&x0[t*8 + pcol]) =
                make_float2(C2[t][0] * rinv0, C2[t][1] * rinv0);
            *reinterpret_cast<float2*>(&x1[t*8 + pcol]) =
                make_float2(C2[t][2] * rinv1, C2[t][3] * rinv1);
        }
    }
}

// ======================= launch =======================
extern "C" void kernel_launch(void* const* d_in, const int* in_sizes, int n_in,
                              void* d_out, int out_size) {
    const float* Q = (const float*)d_in[0];
    const float* K = (const float*)d_in[1];
    const float* V = (const float*)d_in[2];
    float* X = (float*)d_out;

    const int SMEM_MK = (2 * DIMX * PITCH + MSEL) * 4;
    cudaFuncSetAttribute(mker,        cudaFuncAttributeMaxDynamicSharedMemorySize, SMEM_MK);
    cudaFuncSetAttribute(r1ker,       cudaFuncAttributeMaxDynamicSharedMemorySize, SMEM_TC);
    cudaFuncSetAttribute(eker,        cudaFuncAttributeMaxDynamicSharedMemorySize, SMEM_TC);
    cudaFuncSetAttribute(newton_iter, cudaFuncAttributeMaxDynamicSharedMemorySize, NB_SZ);

    topk_gather<<<dim3(BHX, 2), 256>>>(Q, K);
    mker<<<BHX, 256, SMEM_MK>>>();
    r1ker<<<dim3(BHX, SPLITS), 256, SMEM_TC>>>(K, V);
    combiner<<<dim3(BHX, 8), dim3(16, 16)>>>();
    vminit<<<BHX, 256>>>();

    for (int it = 0; it < 6; it++)
        newton_iter<<<BHX, 256, NB_SZ>>>();

    wker<<<dim3(BHX, 2), 256>>>();
    eker<<<dim3(BHX, EQC), 256, SMEM_TC>>>(Q, X);
}

// round 10
// speedup vs baseline: 2.3912x; 1.3321x over previous
#include <cuda_runtime.h>
#include <cuda_bf16.h>
#include <cstdint>
#include <cstddef>

#define BHX    48
#define NTOK   8192
#define DIMX   64
#define MSEL   128
#define SPLITS 8
#define CHUNKS 8
#define EQC    8
#define PITCH  132

// ======================= mma.sync / ldmatrix helpers =======================
__device__ __forceinline__ uint32_t smem_to_u32(const void* p) {
    uint32_t a;
    asm("{ .reg .u64 t; cvta.to.shared.u64 t, %1; cvt.u32.u64 %0, t; }" : "=r"(a) : "l"(p));
    return a;
}
#define LDSM_X4(r0, r1, r2, r3, addr) \
    asm volatile("ldmatrix.sync.aligned.m8n8.x4.shared.b16 {%0,%1,%2,%3}, [%4];" \
                 : "=r"(r0), "=r"(r1), "=r"(r2), "=r"(r3) : "r"(addr))
#define LDSM_X4_T(r0, r1, r2, r3, addr) \
    asm volatile("ldmatrix.sync.aligned.m8n8.x4.trans.shared.b16 {%0,%1,%2,%3}, [%4];" \
                 : "=r"(r0), "=r"(r1), "=r"(r2), "=r"(r3) : "r"(addr))
__device__ __forceinline__ void mma_bf16(float* c, uint32_t a0, uint32_t a1, uint32_t a2, uint32_t a3,
                                         uint32_t b0, uint32_t b1) {
    asm volatile("mma.sync.aligned.m16n8k16.row.col.f32.bf16.bf16.f32 "
                 "{%0,%1,%2,%3}, {%4,%5,%6,%7}, {%8,%9}, {%0,%1,%2,%3};"
                 : "+f"(c[0]), "+f"(c[1]), "+f"(c[2]), "+f"(c[3])
                 : "r"(a0), "r"(a1), "r"(a2), "r"(a3), "r"(b0), "r"(b1));
}
__device__ __forceinline__ void bf16split(float v, __nv_bfloat16& h, __nv_bfloat16& l) {
    h = __float2bfloat16(v);
    l = __float2bfloat16(v - __bfloat162float(h));
}

// ---- swizzled (pad-free) layouts ----
// A/B/V tile: 128 rows x 128B (64 halves); 8 quads of 16B per row, quad ^= (row&7).
// lo-plane at +16384. P tile: 128 rows x 256B (128 halves), 16 quads, quad ^= (row&7); lo at +32768.

// r1ker smem map (229376 B total)
#define R_A    0
#define R_B0   32768
#define R_B1   65536
#define R_V0   98304
#define R_V1   131072
#define R_P    163840
#define R_SMEM 229376
// eker smem map (196608 B total)
#define E_B    0
#define E_V    32768
#define E_A0   65536
#define E_A1   98304
#define E_P    131072
#define E_SMEM 196608

// newton smem: 3 matrices [128 x 136 halves] (272B pitch), hi then lo (+34816)
#define NB_K   0
#define NB_V   69632
#define NB_T   139264
#define NB_SZ  208896

// ======================= scratch =======================
__device__ float d_nc [BHX*MSEL*DIMX];
__device__ float d_nr [BHX*MSEL*DIMX];
__device__ float d_K2m[BHX*MSEL*MSEL];
__device__ float d_Vm0[BHX*MSEL*MSEL];
__device__ float d_Zm [BHX*MSEL*DIMX];
__device__ float d_Wm [BHX*MSEL*DIMX];
__device__ unsigned int d_gmax_bits;
__device__ float d_pmax[BHX*SPLITS*MSEL];
__device__ float d_psum[BHX*SPLITS*MSEL];
__device__ float d_pZ  [(size_t)BHX*SPLITS*MSEL*DIMX];

// ======================= streams/events (created at load, before capture) ==========
static cudaStream_t g_s2;
static cudaEvent_t  g_eA, g_eB;
static bool g_streams_ok = false;
namespace {
struct StreamInit {
    StreamInit() {
        g_streams_ok =
            (cudaStreamCreateWithFlags(&g_s2, cudaStreamNonBlocking) == cudaSuccess) &&
            (cudaEventCreateWithFlags(&g_eA, cudaEventDisableTiming) == cudaSuccess) &&
            (cudaEventCreateWithFlags(&g_eB, cudaEventDisableTiming) == cudaSuccess);
    }
};
static StreamInit g_stream_init;
}

// ======================= SIMT helpers =======================
__device__ __forceinline__ float grp_max(float v) {
    v = fmaxf(v, __shfl_xor_sync(0xffffffffu, v, 8));
    v = fmaxf(v, __shfl_xor_sync(0xffffffffu, v, 4));
    v = fmaxf(v, __shfl_xor_sync(0xffffffffu, v, 2));
    v = fmaxf(v, __shfl_xor_sync(0xffffffffu, v, 1));
    return v;
}
__device__ __forceinline__ float grp_sum(float v) {
    v += __shfl_xor_sync(0xffffffffu, v, 8);
    v += __shfl_xor_sync(0xffffffffu, v, 4);
    v += __shfl_xor_sync(0xffffffffu, v, 2);
    v += __shfl_xor_sync(0xffffffffu, v, 1);
    return v;
}
__device__ __forceinline__ void load_tileT(float* dst, const float* __restrict__ g, int tid) {
    for (int i = tid; i < MSEL*DIMX; i += 256) {
        int m = i >> 6, k = i & 63;
        dst[k*PITCH + m] = g[i];
    }
}
__device__ __forceinline__ void mm128(const float* As, const float* Bs,
                                      float acc[8][8], int ty, int tx) {
#pragma unroll 8
    for (int k = 0; k < DIMX; k++) {
        float4 a0 = *reinterpret_cast<const float4*>(&As[k*PITCH + ty*8]);
        float4 a1 = *reinterpret_cast<const float4*>(&As[k*PITCH + ty*8 + 4]);
        float4 b0 = *reinterpret_cast<const float4*>(&Bs[k*PITCH + tx*8]);
        float4 b1 = *reinterpret_cast<const float4*>(&Bs[k*PITCH + tx*8 + 4]);
        float a[8] = {a0.x,a0.y,a0.z,a0.w,a1.x,a1.y,a1.z,a1.w};
        float b[8] = {b0.x,b0.y,b0.z,b0.w,b1.x,b1.y,b1.z,b1.w};
#pragma unroll
        for (int i = 0; i < 8; i++)
#pragma unroll
            for (int j = 0; j < 8; j++)
                acc[i][j] += a[i] * b[j];
    }
}

// stage [128x64] fp32 -> split bf16 swizzled tile (128B rows, lo at +16384)
__device__ __forceinline__ void stage_sw(char* smem, int offH,
                                         const float* __restrict__ g, int tid) {
#pragma unroll
    for (int k = 0; k < 16; k++) {
        int i = tid + k * 256;
        int r = i >> 5, j = i & 31;                  // j = float2 index in row
        float2 v = *reinterpret_cast<const float2*>(&g[r*64 + j*2]);
        __nv_bfloat16 h0, l0, h1, l1;
        bf16split(v.x, h0, l0); bf16split(v.y, h1, l1);
        uint32_t b = (uint32_t)(r*128) + (uint32_t)(((((j>>2) ^ (r&7)) << 4)) + ((j&3) << 2));
        *(__nv_bfloat162*)(smem + offH + b)         = __halves2bfloat162(h0, h1);
        *(__nv_bfloat162*)(smem + offH + 16384 + b) = __halves2bfloat162(l0, l1);
    }
}

// ======================= kernel 1: segmented top-k + sort + gather =======================
__global__ __launch_bounds__(256) void topk_gather(const float* __restrict__ Qg,
                                                   const float* __restrict__ Kg) {
    __shared__ float vals[NTOK];
    __shared__ float pmax[256];
    __shared__ int   pidx[256];
    __shared__ int   sel[MSEL];
    __shared__ int   sorted[MSEL];
    __shared__ int   bcast;
    int hh = blockIdx.x, which = blockIdx.y, tid = threadIdx.x;
    const float* src = (which == 0 ? Kg : Qg) + (size_t)hh * NTOK * DIMX;

    if (hh == 0 && which == 0 && tid == 0) d_gmax_bits = 0u;

    for (int i = tid; i < NTOK; i += 256) vals[i] = src[(size_t)i * DIMX];
    if (tid == 0) vals[0] = -3.402823466e38f;
    __syncthreads();

    {
        float bv = -3.402823466e38f; int bi = tid * 32;
        for (int j = 0; j < 32; j++) {
            float v = vals[tid*32 + j];
            if (v > bv) { bv = v; bi = tid*32 + j; }
        }
        pmax[tid] = bv; pidx[tid] = bi;
    }
    __syncthreads();

    for (int r = 0; r < MSEL - 1; r++) {
        if (tid < 32) {
            float bv = -3.402823466e38f; int bi = NTOK;
            for (int k = tid; k < 256; k += 32) {
                float v = pmax[k]; int ix = pidx[k];
                if (v > bv || (v == bv && ix < bi)) { bv = v; bi = ix; }
            }
#pragma unroll
            for (int o = 16; o > 0; o >>= 1) {
                float ov = __shfl_down_sync(0xffffffffu, bv, o);
                int   oi = __shfl_down_sync(0xffffffffu, bi, o);
                if (ov > bv || (ov == bv && oi < bi)) { bv = ov; bi = oi; }
            }
            if (tid == 0) { sel[r] = bi; vals[bi] = -3.402823466e38f; bcast = bi; }
        }
        __syncthreads();
        int win = bcast;
        if (tid == (win >> 5)) {
            float bv = -3.402823466e38f; int bi = tid * 32;
            for (int j = 0; j < 32; j++) {
                float v = vals[tid*32 + j];
                if (v > bv) { bv = v; bi = tid*32 + j; }
            }
            pmax[tid] = bv; pidx[tid] = bi;
        }
        __syncthreads();
    }
    if (tid == 0) sel[MSEL - 1] = 0;
    __syncthreads();

    if (tid < MSEL) {
        int my = sel[tid], rank = 0;
        for (int j = 0; j < MSEL; j++) rank += (sel[j] < my);
        sorted[rank] = my;
    }
    __syncthreads();

    float* dst = (which == 0 ? d_nc : d_nr) + (size_t)hh * MSEL * DIMX;
    for (int i = tid; i < MSEL * DIMX; i += 256) {
        int p = i >> 6, d = i & 63;
        dst[i] = src[(size_t)sorted[p] * DIMX + d];
    }
}

// ======================= kernel 2: kernel_2 = softmax(nr @ nc^T), colsum max =======================
__global__ __launch_bounds__(256) void mker() {
    extern __shared__ float sm[];
    float* As = sm;
    float* Bs = sm + DIMX * PITCH;
    float* cs = sm + 2 * DIMX * PITCH;
    int hh = blockIdx.x, tid = threadIdx.x;
    int ty = tid >> 4, tx = tid & 15;
    load_tileT(As, d_nr + (size_t)hh * MSEL * DIMX, tid);
    load_tileT(Bs, d_nc + (size_t)hh * MSEL * DIMX, tid);
    if (tid < MSEL) cs[tid] = 0.f;
    __syncthreads();

    float acc[8][8] = {};
    mm128(As, Bs, acc, ty, tx);

    float* K2h = d_K2m + (size_t)hh * MSEL * MSEL;
    float colp[8] = {};
#pragma unroll
    for (int i = 0; i < 8; i++) {
        float mx = acc[i][0];
#pragma unroll
        for (int j = 1; j < 8; j++) mx = fmaxf(mx, acc[i][j]);
        mx = grp_max(mx);
        float s = 0.f;
#pragma unroll
        for (int j = 0; j < 8; j++) { acc[i][j] = __expf(acc[i][j] - mx); s += acc[i][j]; }
        s = grp_sum(s);
        float inv = 1.f / s;
#pragma unroll
        for (int j = 0; j < 8; j++) {
            float p = acc[i][j] * inv;
            K2h[(ty*8 + i) * MSEL + tx*8 + j] = p;
            colp[j] += p;
        }
    }
#pragma unroll
    for (int j = 0; j < 8; j++) atomicAdd(&cs[tx*8 + j], colp[j]);
    __syncthreads();
    if (tid < MSEL) atomicMax(&d_gmax_bits, __float_as_uint(cs[tid]));
}

// ======================= MMA1 + online softmax + MMA2 tile body (swizzled) =======================
// caller stages A/B/V + __syncthreads before entry; no trailing barrier.
__device__ __forceinline__ void attn_tile_online(char* smem, uint32_t sb, int wid, int lane,
                                                 int aOff, int bOff, int vOff, int pOff,
                                                 float C2[8][4],
                                                 float& m0, float& m1, float& s0, float& s1) {
    float C1[16][4] = {};
    int aRow = wid*16 + (lane & 15);
    int aq = lane >> 4, arb = aRow & 7;
    uint32_t aBase = sb + aOff + aRow*128;
    int bRow0 = (lane & 7) + ((lane >> 4) << 3);
    int bq = (lane >> 3) & 1, brb = bRow0 & 7;
    uint32_t bBase = sb + bOff + bRow0*128;

#pragma unroll
    for (int ks = 0; ks < 4; ks++) {
        uint32_t aA = aBase + ((uint32_t)(((2*ks) | aq) ^ arb) << 4);
        uint32_t ah0, ah1, ah2, ah3, al0, al1, al2, al3;
        LDSM_X4(ah0, ah1, ah2, ah3, aA);
        LDSM_X4(al0, al1, al2, al3, aA + 16384);
#pragma unroll
        for (int p = 0; p < 8; p++) {
            uint32_t bA = bBase + p*2048 + ((uint32_t)(((2*ks) | bq) ^ brb) << 4);
            uint32_t bh0, bh1, bh2, bh3, bl0, bl1, bl2, bl3;
            LDSM_X4(bh0, bh1, bh2, bh3, bA);
            LDSM_X4(bl0, bl1, bl2, bl3, bA + 16384);
            mma_bf16(C1[2*p],   ah0, ah1, ah2, ah3, bh0, bh1);
            mma_bf16(C1[2*p+1], ah0, ah1, ah2, ah3, bh2, bh3);
            mma_bf16(C1[2*p],   ah0, ah1, ah2, ah3, bl0, bl1);
            mma_bf16(C1[2*p+1], ah0, ah1, ah2, ah3, bl2, bl3);
            mma_bf16(C1[2*p],   al0, al1, al2, al3, bh0, bh1);
            mma_bf16(C1[2*p+1], al0, al1, al2, al3, bh2, bh3);
        }
    }

    float cx0 = -3.402823466e38f, cx1 = -3.402823466e38f;
#pragma unroll
    for (int t = 0; t < 16; t++) {
        cx0 = fmaxf(cx0, fmaxf(C1[t][0], C1[t][1]));
        cx1 = fmaxf(cx1, fmaxf(C1[t][2], C1[t][3]));
    }
    cx0 = fmaxf(cx0, __shfl_xor_sync(0xffffffffu, cx0, 1));
    cx0 = fmaxf(cx0, __shfl_xor_sync(0xffffffffu, cx0, 2));
    cx1 = fmaxf(cx1, __shfl_xor_sync(0xffffffffu, cx1, 1));
    cx1 = fmaxf(cx1, __shfl_xor_sync(0xffffffffu, cx1, 2));

    float mn0 = fmaxf(m0, cx0), mn1 = fmaxf(m1, cx1);
    float f0 = __expf(m0 - mn0), f1 = __expf(m1 - mn1);
    float su0 = 0.f, su1 = 0.f;
#pragma unroll
    for (int t = 0; t < 16; t++) {
        C1[t][0] = __expf(C1[t][0] - mn0); C1[t][1] = __expf(C1[t][1] - mn0);
        C1[t][2] = __expf(C1[t][2] - mn1); C1[t][3] = __expf(C1[t][3] - mn1);
        su0 += C1[t][0] + C1[t][1];
        su1 += C1[t][2] + C1[t][3];
    }
    su0 += __shfl_xor_sync(0xffffffffu, su0, 1);
    su0 += __shfl_xor_sync(0xffffffffu, su0, 2);
    su1 += __shfl_xor_sync(0xffffffffu, su1, 1);
    su1 += __shfl_xor_sync(0xffffffffu, su1, 2);
    s0 = s0 * f0 + su0;  s1 = s1 * f1 + su1;
    m0 = mn0;            m1 = mn1;
#pragma unroll
    for (int t = 0; t < 8; t++) {
        C2[t][0] *= f0; C2[t][1] *= f0;
        C2[t][2] *= f1; C2[t][3] *= f1;
    }

    // P rows wid*16..+15 produced AND consumed by warp wid only -> warp-local sync.
    int prow0 = wid*16 + (lane >> 2);
    int prb2 = prow0 & 7;
    char* pSt = smem + pOff + prow0*256 + ((lane & 3) << 2);
#pragma unroll
    for (int t = 0; t < 16; t++) {
        uint32_t off = (uint32_t)((t ^ prb2) << 4);
        __nv_bfloat16 h0, l0, h1, l1;
        bf16split(C1[t][0], h0, l0); bf16split(C1[t][1], h1, l1);
        *(__nv_bfloat162*)(pSt + off)         = __halves2bfloat162(h0, h1);
        *(__nv_bfloat162*)(pSt + 32768 + off) = __halves2bfloat162(l0, l1);
        bf16split(C1[t][2], h0, l0); bf16split(C1[t][3], h1, l1);
        *(__nv_bfloat162*)(pSt + 2048 + off)         = __halves2bfloat162(h0, h1);
        *(__nv_bfloat162*)(pSt + 32768 + 2048 + off) = __halves2bfloat162(l0, l1);
    }
    __syncwarp();

    int pRow = wid*16 + (lane & 15);
    int pq = lane >> 4, prb = pRow & 7;
    uint32_t pBase = sb + pOff + pRow*256;
    int vRow0 = lane & 15;
    int vq = lane >> 4, vrb = vRow0 & 7;
    uint32_t vBase = sb + vOff + vRow0*128;
#pragma unroll
    for (int ks = 0; ks < 8; ks++) {
        uint32_t pA = pBase + ((uint32_t)(((2*ks) | pq) ^ prb) << 4);
        uint32_t ph0, ph1, ph2, ph3, pl0, pl1, pl2, pl3;
        LDSM_X4(ph0, ph1, ph2, ph3, pA);
        LDSM_X4(pl0, pl1, pl2, pl3, pA + 32768);
#pragma unroll
        for (int p = 0; p < 4; p++) {
            uint32_t vA = vBase + ks*2048 + ((uint32_t)(((2*p) | vq) ^ vrb) << 4);
            uint32_t vh0, vh1, vh2, vh3, vl0, vl1, vl2, vl3;
            LDSM_X4_T(vh0, vh1, vh2, vh3, vA);
            LDSM_X4_T(vl0, vl1, vl2, vl3, vA + 16384);
            mma_bf16(C2[2*p],   ph0, ph1, ph2, ph3, vh0, vh1);
            mma_bf16(C2[2*p+1], ph0, ph1, ph2, ph3, vh2, vh3);
            mma_bf16(C2[2*p],   ph0, ph1, ph2, ph3, vl0, vl1);
            mma_bf16(C2[2*p+1], ph0, ph1, ph2, ph3, vl2, vl3);
            mma_bf16(C2[2*p],   pl0, pl1, pl2, pl3, vh0, vh1);
            mma_bf16(C2[2*p+1], pl0, pl1, pl2, pl3, vh2, vh3);
        }
    }
}

// ======================= kernel 3: flash over 8 chunks, double-buffered B/V ==========
__global__ __launch_bounds__(256) void r1ker(const float* __restrict__ Kg,
                                             const float* __restrict__ Vg) {
    extern __shared__ char smem[];
    uint32_t sb = smem_to_u32(smem);
    int hh = blockIdx.x, s = blockIdx.y, tid = threadIdx.x;
    int wid = tid >> 5, lane = tid & 31;

    const float* Kbase = Kg + ((size_t)hh * NTOK + (size_t)s * CHUNKS * MSEL) * DIMX;
    const float* Vbase = Vg + ((size_t)hh * NTOK + (size_t)s * CHUNKS * MSEL) * DIMX;

    stage_sw(smem, R_A, d_nr + (size_t)hh * MSEL * DIMX, tid);
    stage_sw(smem, R_B0, Kbase, tid);
    stage_sw(smem, R_V0, Vbase, tid);
    __syncthreads();

    float C2[8][4] = {};
    float m0 = -3.402823466e38f, m1 = -3.402823466e38f, s0 = 0.f, s1 = 0.f;

#pragma unroll 1
    for (int c = 0; c < CHUNKS; c++) {
        if (c + 1 < CHUNKS) {   // prefetch next chunk into the other buffer
            stage_sw(smem, (c & 1) ? R_B0 : R_B1, Kbase + (size_t)(c+1) * MSEL * DIMX, tid);
            stage_sw(smem, (c & 1) ? R_V0 : R_V1, Vbase + (size_t)(c+1) * MSEL * DIMX, tid);
        }
        attn_tile_online(smem, sb, wid, lane,
                         R_A, (c & 1) ? R_B1 : R_B0, (c & 1) ? R_V1 : R_V0, R_P,
                         C2, m0, m1, s0, s1);
        __syncthreads();
    }

    size_t base = (size_t)(hh * SPLITS + s) * MSEL;
    int grow0 = wid*16 + (lane >> 2);
    int pcol = (lane & 3) * 2;
    if ((lane & 3) == 0) {
        d_pmax[base + grow0]     = m0;  d_psum[base + grow0]     = s0;
        d_pmax[base + grow0 + 8] = m1;  d_psum[base + grow0 + 8] = s1;
    }
    float* z0 = d_pZ + (base + grow0) * DIMX;
    float* z1 = z0 + 8 * DIMX;
#pragma unroll
    for (int t = 0; t < 8; t++) {
        *reinterpret_cast<float2*>(&z0[t*8 + pcol]) = make_float2(C2[t][0], C2[t][1]);
        *reinterpret_cast<float2*>(&z1[t*8 + pcol]) = make_float2(C2[t][2], C2[t][3]);
    }
}

// ======================= kernel 4: combine splits =======================
__global__ void combiner() {
    int hh = blockIdx.x;
    int r  = blockIdx.y * 16 + threadIdx.y;
    int d  = threadIdx.x * 4;
    const float* pm = d_pmax + (size_t)hh * SPLITS * MSEL;
    const float* ps = d_psum + (size_t)hh * SPLITS * MSEL;
    float M = -3.402823466e38f;
#pragma unroll
    for (int s = 0; s < SPLITS; s++) M = fmaxf(M, pm[s * MSEL + r]);
    float l = 0.f;
    float4 z = make_float4(0.f, 0.f, 0.f, 0.f);
#pragma unroll
    for (int s = 0; s < SPLITS; s++) {
        float w = __expf(pm[s * MSEL + r] - M);
        l += ps[s * MSEL + r] * w;
        float4 pz = *reinterpret_cast<const float4*>(
            &d_pZ[((size_t)(hh * SPLITS + s) * MSEL + r) * DIMX + d]);
        z.x += w * pz.x; z.y += w * pz.y; z.z += w * pz.z; z.w += w * pz.w;
    }
    float inv = 1.f / l;
    *reinterpret_cast<float4*>(&d_Zm[((size_t)hh * MSEL + r) * DIMX + d]) =
        make_float4(z.x * inv, z.y * inv, z.z * inv, z.w * inv);
}

// ======================= Newton-Schulz (fused per-iteration TC kernel) =======================
__global__ __launch_bounds__(256) void vminit() {
    int hh = blockIdx.x;
    float inv = 1.f / __uint_as_float(d_gmax_bits);
    const float* K2h = d_K2m + (size_t)hh * MSEL * MSEL;
    float* Vh = d_Vm0 + (size_t)hh * MSEL * MSEL;
    for (int i = threadIdx.x; i < MSEL * MSEL; i += 256) {
        int r = i >> 7, c = i & 127;
        Vh[i] = K2h[c * MSEL + r] * inv;
    }
}

__device__ __forceinline__ void stage_split128(char* smem, int off,
                                               const float* __restrict__ g, int tid) {
    for (int i = tid; i < 8192; i += 256) {
        int r = i >> 6, c2 = (i & 63) * 2;
        float2 v = *reinterpret_cast<const float2*>(&g[r*128 + c2]);
        __nv_bfloat16 h0, l0, h1, l1;
        bf16split(v.x, h0, l0); bf16split(v.y, h1, l1);
        int ob = r*272 + c2*2;
        *(__nv_bfloat162*)(smem + off + ob)         = __halves2bfloat162(h0, h1);
        *(__nv_bfloat162*)(smem + off + 34816 + ob) = __halves2bfloat162(l0, l1);
    }
}

__device__ __forceinline__ void mm_tc(uint32_t sb, int offA, int offB,
                                      int wid, int lane, float C[16][4]) {
#pragma unroll
    for (int t = 0; t < 16; t++) { C[t][0] = 0.f; C[t][1] = 0.f; C[t][2] = 0.f; C[t][3] = 0.f; }
    uint32_t aH = sb + offA + (wid*16 + (lane & 15))*272 + ((lane >> 4) << 4);
    uint32_t aL = aH + 34816;
    uint32_t bH = sb + offB + (lane & 15)*272 + ((lane >> 4) << 4);
    uint32_t bL = bH + 34816;
#pragma unroll
    for (int ks = 0; ks < 8; ks++) {
        uint32_t ah0, ah1, ah2, ah3, al0, al1, al2, al3;
        LDSM_X4(ah0, ah1, ah2, ah3, aH + ks*32);
        LDSM_X4(al0, al1, al2, al3, aL + ks*32);
#pragma unroll
        for (int p = 0; p < 8; p++) {
            uint32_t bh0, bh1, bh2, bh3, bl0, bl1, bl2, bl3;
            LDSM_X4_T(bh0, bh1, bh2, bh3, bH + ks*4352 + p*32);
            LDSM_X4_T(bl0, bl1, bl2, bl3, bL + ks*4352 + p*32);
            mma_bf16(C[2*p],   ah0, ah1, ah2, ah3, bh0, bh1);
            mma_bf16(C[2*p+1], ah0, ah1, ah2, ah3, bh2, bh3);
            mma_bf16(C[2*p],   ah0, ah1, ah2, ah3, bl0, bl1);
            mma_bf16(C[2*p+1], ah0, ah1, ah2, ah3, bl2, bl3);
            mma_bf16(C[2*p],   al0, al1, al2, al3, bh0, bh1);
            mma_bf16(C[2*p+1], al0, al1, al2, al3, bh2, bh3);
        }
    }
}

__device__ __forceinline__ void store_split(char* smem, int off, int wid, int lane,
                                            const float C[16][4]) {
    int r0 = wid*16 + (lane >> 2);
    int cb0 = (lane & 3) * 2;
#pragma unroll
    for (int t = 0; t < 16; t++) {
        int cb = (t*8 + cb0) * 2;
        __nv_bfloat16 h0, l0, h1, l1;
        bf16split(C[t][0], h0, l0); bf16split(C[t][1], h1, l1);
        *(__nv_bfloat162*)(smem + off + r0*272 + cb)         = __halves2bfloat162(h0, h1);
        *(__nv_bfloat162*)(smem + off + 34816 + r0*272 + cb) = __halves2bfloat162(l0, l1);
        bf16split(C[t][2], h0, l0); bf16split(C[t][3], h1, l1);
        *(__nv_bfloat162*)(smem + off + (r0+8)*272 + cb)         = __halves2bfloat162(h0, h1);
        *(__nv_bfloat162*)(smem + off + 34816 + (r0+8)*272 + cb) = __halves2bfloat162(l0, l1);
    }
}
__device__ __forceinline__ float read_split(const char* smem, int off, int r, int c) {
    float h = __bfloat162float(*(const __nv_bfloat16*)(smem + off + r*272 + c*2));
    float l = __bfloat162float(*(const __nv_bfloat16*)(smem + off + 34816 + r*272 + c*2));
    return h + l;
}

__global__ __launch_bounds__(256) void newton_iter() {
    extern __shared__ char smem[];
    uint32_t sb = smem_to_u32(smem);
    int hh = blockIdx.x, tid = threadIdx.x;
    int wid = tid >> 5, lane = tid & 31;
    float R[16][4];

    stage_split128(smem, NB_K, d_K2m + (size_t)hh * MSEL * MSEL, tid);
    stage_split128(smem, NB_V, d_Vm0 + (size_t)hh * MSEL * MSEL, tid);
    __syncthreads();

    mm_tc(sb, NB_K, NB_V, wid, lane, R);          // KV = Km @ Vm
    __syncthreads();
    store_split(smem, NB_K, wid, lane, R);        // BK <- KV
    __syncthreads();

    mm_tc(sb, NB_K, NB_K, wid, lane, R);          // P2 = KV @ KV
    __syncthreads();
    store_split(smem, NB_T, wid, lane, R);        // BT <- P2
    __syncthreads();

    mm_tc(sb, NB_K, NB_T, wid, lane, R);          // P3 = KV @ P2
    {
        int r0 = wid*16 + (lane >> 2);
        int cb0 = (lane & 3) * 2;
#pragma unroll
        for (int t = 0; t < 16; t++) {
            int c = t*8 + cb0;
#pragma unroll
            for (int j = 0; j < 4; j++) {
                int rr = r0 + ((j >> 1) << 3);
                int cc = c + (j & 1);
                float kv = read_split(smem, NB_K, rr, cc);
                float p2 = read_split(smem, NB_T, rr, cc);
                float e = -15.f*kv + 7.f*p2 - R[t][j];
                if (rr == cc) e += 13.f;
                R[t][j] = e;
            }
        }
    }
    __syncthreads();
    store_split(smem, NB_T, wid, lane, R);        // BT <- E
    __syncthreads();

    mm_tc(sb, NB_V, NB_T, wid, lane, R);          // Vm @ E
    {
        float* out = d_Vm0 + (size_t)hh * MSEL * MSEL;
        int r0 = wid*16 + (lane >> 2);
        int cb0 = (lane & 3) * 2;
#pragma unroll
        for (int t = 0; t < 16; t++) {
            int c = t*8 + cb0;
            *reinterpret_cast<float2*>(&out[r0*128 + c]) =
                make_float2(0.25f*R[t][0], 0.25f*R[t][1]);
            *reinterpret_cast<float2*>(&out[(r0+8)*128 + c]) =
                make_float2(0.25f*R[t][2], 0.25f*R[t][3]);
        }
    }
}

// W = Vm_final @ Z  (128x64), grid (48, 2)
__global__ __launch_bounds__(256) void wker() {
    __shared__ float As[32][65];
    __shared__ float Bs[32][65];
    int hh = blockIdx.x;
    const float* Vm = d_Vm0 + (size_t)hh * MSEL * MSEL;
    const float* Z  = d_Zm + (size_t)hh * MSEL * DIMX;
    int r0 = blockIdx.y * 64;
    int tid = threadIdx.x, ty = tid >> 4, tx = tid & 15;
    float acc[4][4] = {};
    for (int kc = 0; kc < MSEL; kc += 32) {
        for (int i = tid; i < 2048; i += 256) {
            int m = i >> 5, k = i & 31;
            As[k][m] = Vm[(r0 + m) * MSEL + kc + k];
        }
        for (int i = tid; i < 2048; i += 256) {
            int k = i >> 6, n = i & 63;
            Bs[k][n] = Z[(kc + k) * DIMX + n];
        }
        __syncthreads();
#pragma unroll 8
        for (int k = 0; k < 32; k++) {
            float a[4], b[4];
#pragma unroll
            for (int i = 0; i < 4; i++) a[i] = As[k][ty*4 + i];
#pragma unroll
            for (int j = 0; j < 4; j++) b[j] = Bs[k][tx*4 + j];
#pragma unroll
            for (int i = 0; i < 4; i++)
#pragma unroll
                for (int j = 0; j < 4; j++)
                    acc[i][j] += a[i] * b[j];
        }
        __syncthreads();
    }
#pragma unroll
    for (int i = 0; i < 4; i++)
#pragma unroll
        for (int j = 0; j < 4; j++)
            d_Wm[(size_t)hh * MSEL * DIMX + (r0 + ty*4 + i) * DIMX + tx*4 + j] = acc[i][j];
}

// ======================= final: X = softmax(Q @ nc^T) @ W, A double-buffered ==========
__global__ __launch_bounds__(256) void eker(const float* __restrict__ Qg,
                                            float* __restrict__ Xg) {
    extern __shared__ char smem[];
    uint32_t sb = smem_to_u32(smem);
    int hh = blockIdx.x, tid = threadIdx.x;
    int wid = tid >> 5, lane = tid & 31;

    const float* Qbase = Qg + ((size_t)hh * NTOK + (size_t)blockIdx.y * EQC * MSEL) * DIMX;

    stage_sw(smem, E_B, d_nc + (size_t)hh * MSEL * DIMX, tid);
    stage_sw(smem, E_V, d_Wm + (size_t)hh * MSEL * DIMX, tid);
    stage_sw(smem, E_A0, Qbase, tid);
    __syncthreads();

    int grow0 = wid*16 + (lane >> 2);
    int pcol = (lane & 3) * 2;

#pragma unroll 1
    for (int c = 0; c < EQC; c++) {
        if (c + 1 < EQC)
            stage_sw(smem, (c & 1) ? E_A0 : E_A1, Qbase + (size_t)(c+1) * MSEL * DIMX, tid);

        float C2[8][4] = {};
        float m0 = -3.402823466e38f, m1 = -3.402823466e38f, s0 = 0.f, s1 = 0.f;
        attn_tile_online(smem, sb, wid, lane,
                         (c & 1) ? E_A1 : E_A0, E_B, E_V, E_P,
                         C2, m0, m1, s0, s1);

        float rinv0 = 1.f / s0, rinv1 = 1.f / s1;
        float* x0 = Xg + ((size_t)hh * NTOK + (size_t)(blockIdx.y * EQC + c) * MSEL + grow0) * DIMX;
        float* x1 = x0 + 8 * DIMX;
#pragma unroll
        for (int t = 0; t < 8; t++) {
            *reinterpret_cast<float2*>(&x0[t*8 + pcol]) =
                make_float2(C2[t][0] * rinv0, C2[t][1] * rinv0);
            *reinterpret_cast<float2*>(&x1[t*8 + pcol]) =
                make_float2(C2[t][2] * rinv1, C2[t][3] * rinv1);
        }
        __syncthreads();
    }
}

// ======================= launch (two-stream fork/join DAG) =======================
extern "C" void kernel_launch(void* const* d_in, const int* in_sizes, int n_in,
                              void* d_out, int out_size) {
    const float* Q = (const float*)d_in[0];
    const float* K = (const float*)d_in[1];
    const float* V = (const float*)d_in[2];
    float* X = (float*)d_out;

    const int SMEM_MK = (2 * DIMX * PITCH + MSEL) * 4;
    cudaFuncSetAttribute(mker,        cudaFuncAttributeMaxDynamicSharedMemorySize, SMEM_MK);
    cudaFuncSetAttribute(r1ker,       cudaFuncAttributeMaxDynamicSharedMemorySize, R_SMEM);
    cudaFuncSetAttribute(eker,        cudaFuncAttributeMaxDynamicSharedMemorySize, E_SMEM);
    cudaFuncSetAttribute(newton_iter, cudaFuncAttributeMaxDynamicSharedMemorySize, NB_SZ);

    bool fork = g_streams_ok;
    cudaStream_t sB = fork ? g_s2 : (cudaStream_t)0;

    topk_gather<<<dim3(BHX, 2), 256>>>(Q, K);

    if (fork) {
        cudaEventRecord(g_eA, 0);
        cudaStreamWaitEvent(sB, g_eA, 0);
    }
    // branch B: mker -> vminit -> 6x newton (small-grid chain)
    mker<<<BHX, 256, SMEM_MK, sB>>>();
    vminit<<<BHX, 256, 0, sB>>>();
    for (int it = 0; it < 6; it++)
        newton_iter<<<BHX, 256, NB_SZ, sB>>>();
    if (fork) cudaEventRecord(g_eB, sB);

    // branch A: r1ker -> combiner (big grid), concurrent with branch B
    r1ker<<<dim3(BHX, SPLITS), 256, R_SMEM>>>(K, V);
    combiner<<<dim3(BHX, 8), dim3(16, 16)>>>();

    if (fork) cudaStreamWaitEvent(0, g_eB, 0);
    wker<<<dim3(BHX, 2), 256>>>();
    eker<<<dim3(BHX, NTOK / MSEL / EQC), 256, E_SMEM>>>(Q, X);
}

// round 12
// speedup vs baseline: 2.6037x; 1.0889x over previous
#include <cuda_runtime.h>
#include <cuda_bf16.h>
#include <cstdint>
#include <cstddef>

#define BHX    48
#define NTOK   8192
#define DIMX   64
#define MSEL   128
#define SPLITS 8
#define CHUNKS 8
#define EQC    8
#define PITCH  132

// ======================= mma.sync / ldmatrix helpers =======================
__device__ __forceinline__ uint32_t smem_to_u32(const void* p) {
    uint32_t a;
    asm("{ .reg .u64 t; cvta.to.shared.u64 t, %1; cvt.u32.u64 %0, t; }" : "=r"(a) : "l"(p));
    return a;
}
#define LDSM_X4(r0, r1, r2, r3, addr) \
    asm volatile("ldmatrix.sync.aligned.m8n8.x4.shared.b16 {%0,%1,%2,%3}, [%4];" \
                 : "=r"(r0), "=r"(r1), "=r"(r2), "=r"(r3) : "r"(addr))
#define LDSM_X4_T(r0, r1, r2, r3, addr) \
    asm volatile("ldmatrix.sync.aligned.m8n8.x4.trans.shared.b16 {%0,%1,%2,%3}, [%4];" \
                 : "=r"(r0), "=r"(r1), "=r"(r2), "=r"(r3) : "r"(addr))
__device__ __forceinline__ void mma_bf16(float* c, uint32_t a0, uint32_t a1, uint32_t a2, uint32_t a3,
                                         uint32_t b0, uint32_t b1) {
    asm volatile("mma.sync.aligned.m16n8k16.row.col.f32.bf16.bf16.f32 "
                 "{%0,%1,%2,%3}, {%4,%5,%6,%7}, {%8,%9}, {%0,%1,%2,%3};"
                 : "+f"(c[0]), "+f"(c[1]), "+f"(c[2]), "+f"(c[3])
                 : "r"(a0), "r"(a1), "r"(a2), "r"(a3), "r"(b0), "r"(b1));
}
__device__ __forceinline__ void bf16split(float v, __nv_bfloat16& h, __nv_bfloat16& l) {
    h = __float2bfloat16(v);
    l = __float2bfloat16(v - __bfloat162float(h));
}

// ---- swizzled (pad-free) layouts; 96KB/CTA -> 2 CTAs/SM ----
// A/B/V tile: 128 rows x 128B (hi), lo plane at +16384. P: 128 x 256B hi at 0 (over A), lo at +32768 (over B).
#define T_A    0
#define T_B    32768
#define T_V    65536
#define T_SMEM 98304

// newton smem: 3 matrices [128 x 136 halves] (272B pitch), hi then lo (+34816)
#define NB_K   0
#define NB_V   69632
#define NB_T   139264
#define NB_SZ  208896

// ======================= scratch =======================
__device__ float d_nc [BHX*MSEL*DIMX];
__device__ float d_nr [BHX*MSEL*DIMX];
__device__ float d_K2m[BHX*MSEL*MSEL];
__device__ float d_Vm0[BHX*MSEL*MSEL];
__device__ float d_Zm [BHX*MSEL*DIMX];
__device__ float d_Wm [BHX*MSEL*DIMX];
__device__ unsigned int d_gmax_bits;
__device__ float d_pmax[BHX*SPLITS*MSEL];
__device__ float d_psum[BHX*SPLITS*MSEL];
__device__ float d_pZ  [(size_t)BHX*SPLITS*MSEL*DIMX];

// ======================= streams/events (created at load, before capture) ==========
static cudaStream_t g_s2;
static cudaEvent_t  g_eA, g_eB;
static bool g_streams_ok = false;
namespace {
struct StreamInit {
    StreamInit() {
        g_streams_ok =
            (cudaStreamCreateWithFlags(&g_s2, cudaStreamNonBlocking) == cudaSuccess) &&
            (cudaEventCreateWithFlags(&g_eA, cudaEventDisableTiming) == cudaSuccess) &&
            (cudaEventCreateWithFlags(&g_eB, cudaEventDisableTiming) == cudaSuccess);
    }
};
static StreamInit g_stream_init;
}

// ======================= SIMT helpers =======================
__device__ __forceinline__ float grp_max(float v) {
    v = fmaxf(v, __shfl_xor_sync(0xffffffffu, v, 8));
    v = fmaxf(v, __shfl_xor_sync(0xffffffffu, v, 4));
    v = fmaxf(v, __shfl_xor_sync(0xffffffffu, v, 2));
    v = fmaxf(v, __shfl_xor_sync(0xffffffffu, v, 1));
    return v;
}
__device__ __forceinline__ float grp_sum(float v) {
    v += __shfl_xor_sync(0xffffffffu, v, 8);
    v += __shfl_xor_sync(0xffffffffu, v, 4);
    v += __shfl_xor_sync(0xffffffffu, v, 2);
    v += __shfl_xor_sync(0xffffffffu, v, 1);
    return v;
}
__device__ __forceinline__ void load_tileT(float* dst, const float* __restrict__ g, int tid) {
    for (int i = tid; i < MSEL*DIMX; i += 256) {
        int m = i >> 6, k = i & 63;
        dst[k*PITCH + m] = g[i];
    }
}
__device__ __forceinline__ void mm128(const float* As, const float* Bs,
                                      float acc[8][8], int ty, int tx) {
#pragma unroll 8
    for (int k = 0; k < DIMX; k++) {
        float4 a0 = *reinterpret_cast<const float4*>(&As[k*PITCH + ty*8]);
        float4 a1 = *reinterpret_cast<const float4*>(&As[k*PITCH + ty*8 + 4]);
        float4 b0 = *reinterpret_cast<const float4*>(&Bs[k*PITCH + tx*8]);
        float4 b1 = *reinterpret_cast<const float4*>(&Bs[k*PITCH + tx*8 + 4]);
        float a[8] = {a0.x,a0.y,a0.z,a0.w,a1.x,a1.y,a1.z,a1.w};
        float b[8] = {b0.x,b0.y,b0.z,b0.w,b1.x,b1.y,b1.z,b1.w};
#pragma unroll
        for (int i = 0; i < 8; i++)
#pragma unroll
            for (int j = 0; j < 8; j++)
                acc[i][j] += a[i] * b[j];
    }
}

// stage [128x64] fp32 -> split bf16 swizzled tile (128B rows, lo at +16384)
__device__ __forceinline__ void stage_sw(char* smem, int offH,
                                         const float* __restrict__ g, int tid) {
#pragma unroll
    for (int k = 0; k < 16; k++) {
        int i = tid + k * 256;
        int r = i >> 5, j = i & 31;
        float2 v = *reinterpret_cast<const float2*>(&g[r*64 + j*2]);
        __nv_bfloat16 h0, l0, h1, l1;
        bf16split(v.x, h0, l0); bf16split(v.y, h1, l1);
        uint32_t b = (uint32_t)(r*128) + (uint32_t)(((((j>>2) ^ (r&7)) << 4)) + ((j&3) << 2));
        *(__nv_bfloat162*)(smem + offH + b)         = __halves2bfloat162(h0, h1);
        *(__nv_bfloat162*)(smem + offH + 16384 + b) = __halves2bfloat162(l0, l1);
    }
}

// ======================= kernel 1: segmented top-k + sort + gather =======================
__global__ __launch_bounds__(256) void topk_gather(const float* __restrict__ Qg,
                                                   const float* __restrict__ Kg) {
    __shared__ float vals[NTOK];
    __shared__ float pmax[256];
    __shared__ int   pidx[256];
    __shared__ int   sel[MSEL];
    __shared__ int   sorted[MSEL];
    __shared__ int   bcast;
    int hh = blockIdx.x, which = blockIdx.y, tid = threadIdx.x;
    const float* src = (which == 0 ? Kg : Qg) + (size_t)hh * NTOK * DIMX;

    if (hh == 0 && which == 0 && tid == 0) d_gmax_bits = 0u;

    for (int i = tid; i < NTOK; i += 256) vals[i] = src[(size_t)i * DIMX];
    if (tid == 0) vals[0] = -3.402823466e38f;
    __syncthreads();

    {
        float bv = -3.402823466e38f; int bi = tid * 32;
        for (int j = 0; j < 32; j++) {
            float v = vals[tid*32 + j];
            if (v > bv) { bv = v; bi = tid*32 + j; }
        }
        pmax[tid] = bv; pidx[tid] = bi;
    }
    __syncthreads();

    for (int r = 0; r < MSEL - 1; r++) {
        if (tid < 32) {
            float bv = -3.402823466e38f; int bi = NTOK;
            for (int k = tid; k < 256; k += 32) {
                float v = pmax[k]; int ix = pidx[k];
                if (v > bv || (v == bv && ix < bi)) { bv = v; bi = ix; }
            }
#pragma unroll
            for (int o = 16; o > 0; o >>= 1) {
                float ov = __shfl_down_sync(0xffffffffu, bv, o);
                int   oi = __shfl_down_sync(0xffffffffu, bi, o);
                if (ov > bv || (ov == bv && oi < bi)) { bv = ov; bi = oi; }
            }
            if (tid == 0) { sel[r] = bi; vals[bi] = -3.402823466e38f; bcast = bi; }
        }
        __syncthreads();
        int win = bcast;
        if (tid == (win >> 5)) {
            float bv = -3.402823466e38f; int bi = tid * 32;
            for (int j = 0; j < 32; j++) {
                float v = vals[tid*32 + j];
                if (v > bv) { bv = v; bi = tid*32 + j; }
            }
            pmax[tid] = bv; pidx[tid] = bi;
        }
        __syncthreads();
    }
    if (tid == 0) sel[MSEL - 1] = 0;
    __syncthreads();

    if (tid < MSEL) {
        int my = sel[tid], rank = 0;
        for (int j = 0; j < MSEL; j++) rank += (sel[j] < my);
        sorted[rank] = my;
    }
    __syncthreads();

    float* dst = (which == 0 ? d_nc : d_nr) + (size_t)hh * MSEL * DIMX;
    for (int i = tid; i < MSEL * DIMX; i += 256) {
        int p = i >> 6, d = i & 63;
        dst[i] = src[(size_t)sorted[p] * DIMX + d];
    }
}

// ======================= kernel 2: kernel_2 = softmax(nr @ nc^T), colsum max =======================
__global__ __launch_bounds__(256) void mker() {
    extern __shared__ float sm[];
    float* As = sm;
    float* Bs = sm + DIMX * PITCH;
    float* cs = sm + 2 * DIMX * PITCH;
    int hh = blockIdx.x, tid = threadIdx.x;
    int ty = tid >> 4, tx = tid & 15;
    load_tileT(As, d_nr + (size_t)hh * MSEL * DIMX, tid);
    load_tileT(Bs, d_nc + (size_t)hh * MSEL * DIMX, tid);
    if (tid < MSEL) cs[tid] = 0.f;
    __syncthreads();

    float acc[8][8] = {};
    mm128(As, Bs, acc, ty, tx);

    float* K2h = d_K2m + (size_t)hh * MSEL * MSEL;
    float colp[8] = {};
#pragma unroll
    for (int i = 0; i < 8; i++) {
        float mx = acc[i][0];
#pragma unroll
        for (int j = 1; j < 8; j++) mx = fmaxf(mx, acc[i][j]);
        mx = grp_max(mx);
        float s = 0.f;
#pragma unroll
        for (int j = 0; j < 8; j++) { acc[i][j] = __expf(acc[i][j] - mx); s += acc[i][j]; }
        s = grp_sum(s);
        float inv = 1.f / s;
#pragma unroll
        for (int j = 0; j < 8; j++) {
            float p = acc[i][j] * inv;
            K2h[(ty*8 + i) * MSEL + tx*8 + j] = p;
            colp[j] += p;
        }
    }
#pragma unroll
    for (int j = 0; j < 8; j++) atomicAdd(&cs[tx*8 + j], colp[j]);
    __syncthreads();
    if (tid < MSEL) atomicMax(&d_gmax_bits, __float_as_uint(cs[tid]));
}

// ======================= MMA1 + online softmax + MMA2 tile body (P aliases A+B) ==========
// caller stages A/B/V + __syncthreads before entry; trailing barrier owned by caller.
__device__ __forceinline__ void attn_tile_online(char* smem, uint32_t sb, int wid, int lane,
                                                 float C2[8][4],
                                                 float& m0, float& m1, float& s0, float& s1) {
    float C1[16][4] = {};
    int aRow = wid*16 + (lane & 15);
    int aq = lane >> 4, arb = aRow & 7;
    uint32_t aBase = sb + T_A + aRow*128;
    int bRow0 = (lane & 7) + ((lane >> 4) << 3);
    int bq = (lane >> 3) & 1, brb = bRow0 & 7;
    uint32_t bBase = sb + T_B + bRow0*128;

#pragma unroll
    for (int ks = 0; ks < 4; ks++) {
        uint32_t aA = aBase + ((uint32_t)(((2*ks) | aq) ^ arb) << 4);
        uint32_t ah0, ah1, ah2, ah3, al0, al1, al2, al3;
        LDSM_X4(ah0, ah1, ah2, ah3, aA);
        LDSM_X4(al0, al1, al2, al3, aA + 16384);
#pragma unroll
        for (int p = 0; p < 8; p++) {
            uint32_t bA = bBase + p*2048 + ((uint32_t)(((2*ks) | bq) ^ brb) << 4);
            uint32_t bh0, bh1, bh2, bh3, bl0, bl1, bl2, bl3;
            LDSM_X4(bh0, bh1, bh2, bh3, bA);
            LDSM_X4(bl0, bl1, bl2, bl3, bA + 16384);
            mma_bf16(C1[2*p],   ah0, ah1, ah2, ah3, bh0, bh1);
            mma_bf16(C1[2*p+1], ah0, ah1, ah2, ah3, bh2, bh3);
            mma_bf16(C1[2*p],   ah0, ah1, ah2, ah3, bl0, bl1);
            mma_bf16(C1[2*p+1], ah0, ah1, ah2, ah3, bl2, bl3);
            mma_bf16(C1[2*p],   al0, al1, al2, al3, bh0, bh1);
            mma_bf16(C1[2*p+1], al0, al1, al2, al3, bh2, bh3);
        }
    }

    float cx0 = -3.402823466e38f, cx1 = -3.402823466e38f;
#pragma unroll
    for (int t = 0; t < 16; t++) {
        cx0 = fmaxf(cx0, fmaxf(C1[t][0], C1[t][1]));
        cx1 = fmaxf(cx1, fmaxf(C1[t][2], C1[t][3]));
    }
    cx0 = fmaxf(cx0, __shfl_xor_sync(0xffffffffu, cx0, 1));
    cx0 = fmaxf(cx0, __shfl_xor_sync(0xffffffffu, cx0, 2));
    cx1 = fmaxf(cx1, __shfl_xor_sync(0xffffffffu, cx1, 1));
    cx1 = fmaxf(cx1, __shfl_xor_sync(0xffffffffu, cx1, 2));

    float mn0 = fmaxf(m0, cx0), mn1 = fmaxf(m1, cx1);
    float f0 = __expf(m0 - mn0), f1 = __expf(m1 - mn1);
    float su0 = 0.f, su1 = 0.f;
#pragma unroll
    for (int t = 0; t < 16; t++) {
        C1[t][0] = __expf(C1[t][0] - mn0); C1[t][1] = __expf(C1[t][1] - mn0);
        C1[t][2] = __expf(C1[t][2] - mn1); C1[t][3] = __expf(C1[t][3] - mn1);
        su0 += C1[t][0] + C1[t][1];
        su1 += C1[t][2] + C1[t][3];
    }
    su0 += __shfl_xor_sync(0xffffffffu, su0, 1);
    su0 += __shfl_xor_sync(0xffffffffu, su0, 2);
    su1 += __shfl_xor_sync(0xffffffffu, su1, 1);
    su1 += __shfl_xor_sync(0xffffffffu, su1, 2);
    s0 = s0 * f0 + su0;  s1 = s1 * f1 + su1;
    m0 = mn0;            m1 = mn1;
#pragma unroll
    for (int t = 0; t < 8; t++) {
        C2[t][0] *= f0; C2[t][1] *= f0;
        C2[t][2] *= f1; C2[t][3] *= f1;
    }

    __syncthreads();   // all warps done reading A/B before P (aliased) is written
    int prow0 = wid*16 + (lane >> 2);
    int prb2 = prow0 & 7;
    char* pSt = smem + prow0*256 + ((lane & 3) << 2);
#pragma unroll
    for (int t = 0; t < 16; t++) {
        uint32_t off = (uint32_t)((t ^ prb2) << 4);
        __nv_bfloat16 h0, l0, h1, l1;
        bf16split(C1[t][0], h0, l0); bf16split(C1[t][1], h1, l1);
        *(__nv_bfloat162*)(pSt + off)         = __halves2bfloat162(h0, h1);
        *(__nv_bfloat162*)(pSt + 32768 + off) = __halves2bfloat162(l0, l1);
        bf16split(C1[t][2], h0, l0); bf16split(C1[t][3], h1, l1);
        *(__nv_bfloat162*)(pSt + 2048 + off)         = __halves2bfloat162(h0, h1);
        *(__nv_bfloat162*)(pSt + 32768 + 2048 + off) = __halves2bfloat162(l0, l1);
    }
    __syncwarp();      // warp reads only its own P rows

    int pRow = wid*16 + (lane & 15);
    int pq = lane >> 4, prb = pRow & 7;
    uint32_t pBase = sb + pRow*256;
    int vRow0 = lane & 15;
    int vq = lane >> 4, vrb = vRow0 & 7;
    uint32_t vBase = sb + T_V + vRow0*128;
#pragma unroll
    for (int ks = 0; ks < 8; ks++) {
        uint32_t pA = pBase + ((uint32_t)(((2*ks) | pq) ^ prb) << 4);
        uint32_t ph0, ph1, ph2, ph3, pl0, pl1, pl2, pl3;
        LDSM_X4(ph0, ph1, ph2, ph3, pA);
        LDSM_X4(pl0, pl1, pl2, pl3, pA + 32768);
#pragma unroll
        for (int p = 0; p < 4; p++) {
            uint32_t vA = vBase + ks*2048 + ((uint32_t)(((2*p) | vq) ^ vrb) << 4);
            uint32_t vh0, vh1, vh2, vh3, vl0, vl1, vl2, vl3;
            LDSM_X4_T(vh0, vh1, vh2, vh3, vA);
            LDSM_X4_T(vl0, vl1, vl2, vl3, vA + 16384);
            mma_bf16(C2[2*p],   ph0, ph1, ph2, ph3, vh0, vh1);
            mma_bf16(C2[2*p+1], ph0, ph1, ph2, ph3, vh2, vh3);
            mma_bf16(C2[2*p],   ph0, ph1, ph2, ph3, vl0, vl1);
            mma_bf16(C2[2*p+1], ph0, ph1, ph2, ph3, vl2, vl3);
            mma_bf16(C2[2*p],   pl0, pl1, pl2, pl3, vh0, vh1);
            mma_bf16(C2[2*p+1], pl0, pl1, pl2, pl3, vh2, vh3);
        }
    }
}

// ======================= kernel 3: flash over 8 chunks, 2 CTAs/SM ==========
__global__ __launch_bounds__(256, 2) void r1ker(const float* __restrict__ Kg,
                                                const float* __restrict__ Vg) {
    extern __shared__ char smem[];
    uint32_t sb = smem_to_u32(smem);
    int hh = blockIdx.x, s = blockIdx.y, tid = threadIdx.x;
    int wid = tid >> 5, lane = tid & 31;

    const float* Kbase = Kg + ((size_t)hh * NTOK + (size_t)s * CHUNKS * MSEL) * DIMX;
    const float* Vbase = Vg + ((size_t)hh * NTOK + (size_t)s * CHUNKS * MSEL) * DIMX;

    float C2[8][4] = {};
    float m0 = -3.402823466e38f, m1 = -3.402823466e38f, s0 = 0.f, s1 = 0.f;

#pragma unroll 1
    for (int c = 0; c < CHUNKS; c++) {
        if (c) __syncthreads();     // prior MMA2 done reading P/V before restaging
        stage_sw(smem, T_A, d_nr + (size_t)hh * MSEL * DIMX, tid);
        stage_sw(smem, T_B, Kbase + (size_t)c * MSEL * DIMX, tid);
        stage_sw(smem, T_V, Vbase + (size_t)c * MSEL * DIMX, tid);
        __syncthreads();
        attn_tile_online(smem, sb, wid, lane, C2, m0, m1, s0, s1);
    }

    size_t base = (size_t)(hh * SPLITS + s) * MSEL;
    int grow0 = wid*16 + (lane >> 2);
    int pcol = (lane & 3) * 2;
    if ((lane & 3) == 0) {
        d_pmax[base + grow0]     = m0;  d_psum[base + grow0]     = s0;
        d_pmax[base + grow0 + 8] = m1;  d_psum[base + grow0 + 8] = s1;
    }
    float* z0 = d_pZ + (base + grow0) * DIMX;
    float* z1 = z0 + 8 * DIMX;
#pragma unroll
    for (int t = 0; t < 8; t++) {
        *reinterpret_cast<float2*>(&z0[t*8 + pcol]) = make_float2(C2[t][0], C2[t][1]);
        *reinterpret_cast<float2*>(&z1[t*8 + pcol]) = make_float2(C2[t][2], C2[t][3]);
    }
}

// ======================= kernel 4: combine splits =======================
__global__ void combiner() {
    int hh = blockIdx.x;
    int r  = blockIdx.y * 16 + threadIdx.y;
    int d  = threadIdx.x * 4;
    const float* pm = d_pmax + (size_t)hh * SPLITS * MSEL;
    const float* ps = d_psum + (size_t)hh * SPLITS * MSEL;
    float M = -3.402823466e38f;
#pragma unroll
    for (int s = 0; s < SPLITS; s++) M = fmaxf(M, pm[s * MSEL + r]);
    float l = 0.f;
    float4 z = make_float4(0.f, 0.f, 0.f, 0.f);
#pragma unroll
    for (int s = 0; s < SPLITS; s++) {
        float w = __expf(pm[s * MSEL + r] - M);
        l += ps[s * MSEL + r] * w;
        float4 pz = *reinterpret_cast<const float4*>(
            &d_pZ[((size_t)(hh * SPLITS + s) * MSEL + r) * DIMX + d]);
        z.x += w * pz.x; z.y += w * pz.y; z.z += w * pz.z; z.w += w * pz.w;
    }
    float inv = 1.f / l;
    *reinterpret_cast<float4*>(&d_Zm[((size_t)hh * MSEL + r) * DIMX + d]) =
        make_float4(z.x * inv, z.y * inv, z.z * inv, z.w * inv);
}

// ======================= Newton-Schulz: 512-thread fused TC kernel =======================
__global__ __launch_bounds__(256) void vminit() {
    int hh = blockIdx.x;
    float inv = 1.f / __uint_as_float(d_gmax_bits);
    const float* K2h = d_K2m + (size_t)hh * MSEL * MSEL;
    float* Vh = d_Vm0 + (size_t)hh * MSEL * MSEL;
    for (int i = threadIdx.x; i < MSEL * MSEL; i += 256) {
        int r = i >> 7, c = i & 127;
        Vh[i] = K2h[c * MSEL + r] * inv;
    }
}

__device__ __forceinline__ void stage_split128_512(char* smem, int off,
                                                   const float* __restrict__ g, int tid) {
#pragma unroll
    for (int k = 0; k < 16; k++) {
        int i = tid + k * 512;
        int r = i >> 6, c2 = (i & 63) * 2;
        float2 v = *reinterpret_cast<const float2*>(&g[r*128 + c2]);
        __nv_bfloat16 h0, l0, h1, l1;
        bf16split(v.x, h0, l0); bf16split(v.y, h1, l1);
        int ob = r*272 + c2*2;
        *(__nv_bfloat162*)(smem + off + ob)         = __halves2bfloat162(h0, h1);
        *(__nv_bfloat162*)(smem + off + 34816 + ob) = __halves2bfloat162(l0, l1);
    }
}

// C[16x64 fragment] = A(rows rg*16..+15) @ B(cols cg*64..+63); 3-product split
__device__ __forceinline__ void mm_tc512(uint32_t sb, int offA, int offB,
                                         int rg, int cg, int lane, float C[8][4]) {
#pragma unroll
    for (int t = 0; t < 8; t++) { C[t][0] = 0.f; C[t][1] = 0.f; C[t][2] = 0.f; C[t][3] = 0.f; }
    uint32_t aH = sb + offA + (rg*16 + (lane & 15))*272 + ((lane >> 4) << 4);
    uint32_t aL = aH + 34816;
    uint32_t bH = sb + offB + (lane & 15)*272 + ((lane >> 4) << 4) + cg*128;
    uint32_t bL = bH + 34816;
#pragma unroll
    for (int ks = 0; ks < 8; ks++) {
        uint32_t ah0, ah1, ah2, ah3, al0, al1, al2, al3;
        LDSM_X4(ah0, ah1, ah2, ah3, aH + ks*32);
        LDSM_X4(al0, al1, al2, al3, aL + ks*32);
#pragma unroll
        for (int p = 0; p < 4; p++) {
            uint32_t bh0, bh1, bh2, bh3, bl0, bl1, bl2, bl3;
            LDSM_X4_T(bh0, bh1, bh2, bh3, bH + ks*4352 + p*32);
            LDSM_X4_T(bl0, bl1, bl2, bl3, bL + ks*4352 + p*32);
            mma_bf16(C[2*p],   ah0, ah1, ah2, ah3, bh0, bh1);
            mma_bf16(C[2*p+1], ah0, ah1, ah2, ah3, bh2, bh3);
            mma_bf16(C[2*p],   ah0, ah1, ah2, ah3, bl0, bl1);
            mma_bf16(C[2*p+1], ah0, ah1, ah2, ah3, bl2, bl3);
            mma_bf16(C[2*p],   al0, al1, al2, al3, bh0, bh1);
            mma_bf16(C[2*p+1], al0, al1, al2, al3, bh2, bh3);
        }
    }
}

__device__ __forceinline__ void store_split512(char* smem, int off, int rg, int cg, int lane,
                                               const float C[8][4]) {
    int r0 = rg*16 + (lane >> 2);
    int cb0 = (lane & 3) * 2;
#pragma unroll
    for (int t = 0; t < 8; t++) {
        int cb = (cg*64 + t*8 + cb0) * 2;
        __nv_bfloat16 h0, l0, h1, l1;
        bf16split(C[t][0], h0, l0); bf16split(C[t][1], h1, l1);
        *(__nv_bfloat162*)(smem + off + r0*272 + cb)         = __halves2bfloat162(h0, h1);
        *(__nv_bfloat162*)(smem + off + 34816 + r0*272 + cb) = __halves2bfloat162(l0, l1);
        bf16split(C[t][2], h0, l0); bf16split(C[t][3], h1, l1);
        *(__nv_bfloat162*)(smem + off + (r0+8)*272 + cb)         = __halves2bfloat162(h0, h1);
        *(__nv_bfloat162*)(smem + off + 34816 + (r0+8)*272 + cb) = __halves2bfloat162(l0, l1);
    }
}
__device__ __forceinline__ float read_split(const char* smem, int off, int r, int c) {
    float h = __bfloat162float(*(const __nv_bfloat16*)(smem + off + r*272 + c*2));
    float l = __bfloat162float(*(const __nv_bfloat16*)(smem + off + 34816 + r*272 + c*2));
    return h + l;
}

__global__ __launch_bounds__(512) void newton_iter() {
    extern __shared__ char smem[];
    uint32_t sb = smem_to_u32(smem);
    int hh = blockIdx.x, tid = threadIdx.x;
    int wid = tid >> 5, lane = tid & 31;
    int rg = wid & 7, cg = wid >> 3;
    float R[8][4];

    stage_split128_512(smem, NB_K, d_K2m + (size_t)hh * MSEL * MSEL, tid);
    stage_split128_512(smem, NB_V, d_Vm0 + (size_t)hh * MSEL * MSEL, tid);
    __syncthreads();

    mm_tc512(sb, NB_K, NB_V, rg, cg, lane, R);    // KV = Km @ Vm
    __syncthreads();
    store_split512(smem, NB_K, rg, cg, lane, R);  // BK <- KV
    __syncthreads();

    mm_tc512(sb, NB_K, NB_K, rg, cg, lane, R);    // P2 = KV @ KV
    __syncthreads();
    store_split512(smem, NB_T, rg, cg, lane, R);  // BT <- P2
    __syncthreads();

    mm_tc512(sb, NB_K, NB_T, rg, cg, lane, R);    // P3 = KV @ P2
    {                                              // E = 13I -15KV +7P2 -P3
        int r0 = rg*16 + (lane >> 2);
        int cb0 = (lane & 3) * 2;
#pragma unroll
        for (int t = 0; t < 8; t++) {
            int c = cg*64 + t*8 + cb0;
#pragma unroll
            for (int j = 0; j < 4; j++) {
                int rr = r0 + ((j >> 1) << 3);
                int cc = c + (j & 1);
                float kv = read_split(smem, NB_K, rr, cc);
                float p2 = read_split(smem, NB_T, rr, cc);
                float e = -15.f*kv + 7.f*p2 - R[t][j];
                if (rr == cc) e += 13.f;
                R[t][j] = e;
            }
        }
    }
    __syncthreads();
    store_split512(smem, NB_T, rg, cg, lane, R);  // BT <- E
    __syncthreads();

    mm_tc512(sb, NB_V, NB_T, rg, cg, lane, R);    // Vm @ E
    {
        float* out = d_Vm0 + (size_t)hh * MSEL * MSEL;
        int r0 = rg*16 + (lane >> 2);
        int cb0 = (lane & 3) * 2;
#pragma unroll
        for (int t = 0; t < 8; t++) {
            int c = cg*64 + t*8 + cb0;
            *reinterpret_cast<float2*>(&out[r0*128 + c]) =
                make_float2(0.25f*R[t][0], 0.25f*R[t][1]);
            *reinterpret_cast<float2*>(&out[(r0+8)*128 + c]) =
                make_float2(0.25f*R[t][2], 0.25f*R[t][3]);
        }
    }
}

// W = Vm_final @ Z  (128x64), grid (48, 2)
__global__ __launch_bounds__(256) void wker() {
    __shared__ float As[32][65];
    __shared__ float Bs[32][65];
    int hh = blockIdx.x;
    const float* Vm = d_Vm0 + (size_t)hh * MSEL * MSEL;
    const float* Z  = d_Zm + (size_t)hh * MSEL * DIMX;
    int r0 = blockIdx.y * 64;
    int tid = threadIdx.x, ty = tid >> 4, tx = tid & 15;
    float acc[4][4] = {};
    for (int kc = 0; kc < MSEL; kc += 32) {
        for (int i = tid; i < 2048; i += 256) {
            int m = i >> 5, k = i & 31;
            As[k][m] = Vm[(r0 + m) * MSEL + kc + k];
        }
        for (int i = tid; i < 2048; i += 256) {
            int k = i >> 6, n = i & 63;
            Bs[k][n] = Z[(kc + k) * DIMX + n];
        }
        __syncthreads();
#pragma unroll 8
        for (int k = 0; k < 32; k++) {
            float a[4], b[4];
#pragma unroll
            for (int i = 0; i < 4; i++) a[i] = As[k][ty*4 + i];
#pragma unroll
            for (int j = 0; j < 4; j++) b[j] = Bs[k][tx*4 + j];
#pragma unroll
            for (int i = 0; i < 4; i++)
#pragma unroll
                for (int j = 0; j < 4; j++)
                    acc[i][j] += a[i] * b[j];
        }
        __syncthreads();
    }
#pragma unroll
    for (int i = 0; i < 4; i++)
#pragma unroll
        for (int j = 0; j < 4; j++)
            d_Wm[(size_t)hh * MSEL * DIMX + (r0 + ty*4 + i) * DIMX + tx*4 + j] = acc[i][j];
}

// ======================= final: X = softmax(Q @ nc^T) @ W, 2 CTAs/SM ==========
__global__ __launch_bounds__(256, 2) void eker(const float* __restrict__ Qg,
                                               float* __restrict__ Xg) {
    extern __shared__ char smem[];
    uint32_t sb = smem_to_u32(smem);
    int hh = blockIdx.x, tid = threadIdx.x;
    int wid = tid >> 5, lane = tid & 31;

    const float* Qbase = Qg + ((size_t)hh * NTOK + (size_t)blockIdx.y * EQC * MSEL) * DIMX;

    stage_sw(smem, T_V, d_Wm + (size_t)hh * MSEL * DIMX, tid);   // W once (not aliased by P)

    int grow0 = wid*16 + (lane >> 2);
    int pcol = (lane & 3) * 2;

#pragma unroll 1
    for (int c = 0; c < EQC; c++) {
        if (c) __syncthreads();     // prior MMA2 done reading P before restaging A/B
        stage_sw(smem, T_A, Qbase + (size_t)c * MSEL * DIMX, tid);
        stage_sw(smem, T_B, d_nc + (size_t)hh * MSEL * DIMX, tid);
        __syncthreads();            // also orders the one-time V staging (c==0)

        float C2[8][4] = {};
        float m0 = -3.402823466e38f, m1 = -3.402823466e38f, s0 = 0.f, s1 = 0.f;
        attn_tile_online(smem, sb, wid, lane, C2, m0, m1, s0, s1);

        float rinv0 = 1.f / s0, rinv1 = 1.f / s1;
        float* x0 = Xg + ((size_t)hh * NTOK + (size_t)(blockIdx.y * EQC + c) * MSEL + grow0) * DIMX;
        float* x1 = x0 + 8 * DIMX;
#pragma unroll
        for (int t = 0; t < 8; t++) {
            *reinterpret_cast<float2*>(&x0[t*8 + pcol]) =
                make_float2(C2[t][0] * rinv0, C2[t][1] * rinv0);
            *reinterpret_cast<float2*>(&x1[t*8 + pcol]) =
                make_float2(C2[t][2] * rinv1, C2[t][3] * rinv1);
        }
    }
}

// ======================= launch (two-stream fork/join DAG) =======================
extern "C" void kernel_launch(void* const* d_in, const int* in_sizes, int n_in,
                              void* d_out, int out_size) {
    const float* Q = (const float*)d_in[0];
    const float* K = (const float*)d_in[1];
    const float* V = (const float*)d_in[2];
    float* X = (float*)d_out;

    const int SMEM_MK = (2 * DIMX * PITCH + MSEL) * 4;
    cudaFuncSetAttribute(mker,        cudaFuncAttributeMaxDynamicSharedMemorySize, SMEM_MK);
    cudaFuncSetAttribute(r1ker,       cudaFuncAttributeMaxDynamicSharedMemorySize, T_SMEM);
    cudaFuncSetAttribute(eker,        cudaFuncAttributeMaxDynamicSharedMemorySize, T_SMEM);
    cudaFuncSetAttribute(newton_iter, cudaFuncAttributeMaxDynamicSharedMemorySize, NB_SZ);

    bool fork = g_streams_ok;
    cudaStream_t sB = fork ? g_s2 : (cudaStream_t)0;

    topk_gather<<<dim3(BHX, 2), 256>>>(Q, K);

    if (fork) {
        cudaEventRecord(g_eA, 0);
        cudaStreamWaitEvent(sB, g_eA, 0);
    }
    // branch B: mker -> vminit -> 6x newton (small-grid chain)
    mker<<<BHX, 256, SMEM_MK, sB>>>();
    vminit<<<BHX, 256, 0, sB>>>();
    for (int it = 0; it < 6; it++)
        newton_iter<<<BHX, 512, NB_SZ, sB>>>();
    if (fork) cudaEventRecord(g_eB, sB);

    // branch A: r1ker -> combiner (big grid), concurrent with branch B
    r1ker<<<dim3(BHX, SPLITS), 256, T_SMEM>>>(K, V);
    combiner<<<dim3(BHX, 8), dim3(16, 16)>>>();

    if (fork) cudaStreamWaitEvent(0, g_eB, 0);
    wker<<<dim3(BHX, 2), 256>>>();
    eker<<<dim3(BHX, NTOK / MSEL / EQC), 256, T_SMEM>>>(Q, X);
}

// round 14
// speedup vs baseline: 2.6757x; 1.0277x over previous
#include <cuda_runtime.h>
#include <cuda_bf16.h>
#include <cstdint>
#include <cstddef>

#define BHX    48
#define NTOK   8192
#define DIMX   64
#define MSEL   128
#define SPLITS 8
#define CHUNKS 8
#define EQC    8
#define PITCH  132

// ======================= mma.sync / ldmatrix helpers =======================
__device__ __forceinline__ uint32_t smem_to_u32(const void* p) {
    uint32_t a;
    asm("{ .reg .u64 t; cvta.to.shared.u64 t, %1; cvt.u32.u64 %0, t; }" : "=r"(a) : "l"(p));
    return a;
}
#define LDSM_X4(r0, r1, r2, r3, addr) \
    asm volatile("ldmatrix.sync.aligned.m8n8.x4.shared.b16 {%0,%1,%2,%3}, [%4];" \
                 : "=r"(r0), "=r"(r1), "=r"(r2), "=r"(r3) : "r"(addr))
#define LDSM_X4_T(r0, r1, r2, r3, addr) \
    asm volatile("ldmatrix.sync.aligned.m8n8.x4.trans.shared.b16 {%0,%1,%2,%3}, [%4];" \
                 : "=r"(r0), "=r"(r1), "=r"(r2), "=r"(r3) : "r"(addr))
__device__ __forceinline__ void mma_bf16(float* c, uint32_t a0, uint32_t a1, uint32_t a2, uint32_t a3,
                                         uint32_t b0, uint32_t b1) {
    asm volatile("mma.sync.aligned.m16n8k16.row.col.f32.bf16.bf16.f32 "
                 "{%0,%1,%2,%3}, {%4,%5,%6,%7}, {%8,%9}, {%0,%1,%2,%3};"
                 : "+f"(c[0]), "+f"(c[1]), "+f"(c[2]), "+f"(c[3])
                 : "r"(a0), "r"(a1), "r"(a2), "r"(a3), "r"(b0), "r"(b1));
}
__device__ __forceinline__ void bf16split(float v, __nv_bfloat16& h, __nv_bfloat16& l) {
    h = __float2bfloat16(v);
    l = __float2bfloat16(v - __bfloat162float(h));
}
// pack (x,y) into hi/lo bf16x2 register images
__device__ __forceinline__ void pack_split2(float x, float y, uint32_t& h, uint32_t& l) {
    __nv_bfloat16 hx, lx, hy, ly;
    bf16split(x, hx, lx); bf16split(y, hy, ly);
    __nv_bfloat162 hb = __halves2bfloat162(hx, hy);
    __nv_bfloat162 lb = __halves2bfloat162(lx, ly);
    h = *reinterpret_cast<uint32_t*>(&hb);
    l = *reinterpret_cast<uint32_t*>(&lb);
}

// ---- swizzled (pad-free) layouts; 96KB/CTA -> 2 CTAs/SM; P lives in registers ----
#define T_A    0
#define T_B    32768
#define T_V    65536
#define T_SMEM 98304

// newton smem: 3 matrices [128 x 136 halves] (272B pitch), hi then lo (+34816)
#define NB_K   0
#define NB_V   69632
#define NB_T   139264
#define NB_SZ  208896

// ======================= scratch =======================
__device__ float d_nc [BHX*MSEL*DIMX];
__device__ float d_nr [BHX*MSEL*DIMX];
__device__ float d_K2m[BHX*MSEL*MSEL];
__device__ float d_Vm0[BHX*MSEL*MSEL];
__device__ float d_Zm [BHX*MSEL*DIMX];
__device__ float d_Wm [BHX*MSEL*DIMX];
__device__ unsigned int d_gmax_bits;
__device__ float d_pmax[BHX*SPLITS*MSEL];
__device__ float d_psum[BHX*SPLITS*MSEL];
__device__ float d_pZ  [(size_t)BHX*SPLITS*MSEL*DIMX];

// ======================= streams/events (created at load, before capture) ==========
static cudaStream_t g_s2;
static cudaEvent_t  g_eA, g_eB;
static bool g_streams_ok = false;
namespace {
struct StreamInit {
    StreamInit() {
        g_streams_ok =
            (cudaStreamCreateWithFlags(&g_s2, cudaStreamNonBlocking) == cudaSuccess) &&
            (cudaEventCreateWithFlags(&g_eA, cudaEventDisableTiming) == cudaSuccess) &&
            (cudaEventCreateWithFlags(&g_eB, cudaEventDisableTiming) == cudaSuccess);
    }
};
static StreamInit g_stream_init;
}

// ======================= SIMT helpers =======================
__device__ __forceinline__ float grp_max(float v) {
    v = fmaxf(v, __shfl_xor_sync(0xffffffffu, v, 8));
    v = fmaxf(v, __shfl_xor_sync(0xffffffffu, v, 4));
    v = fmaxf(v, __shfl_xor_sync(0xffffffffu, v, 2));
    v = fmaxf(v, __shfl_xor_sync(0xffffffffu, v, 1));
    return v;
}
__device__ __forceinline__ float grp_sum(float v) {
    v += __shfl_xor_sync(0xffffffffu, v, 8);
    v += __shfl_xor_sync(0xffffffffu, v, 4);
    v += __shfl_xor_sync(0xffffffffu, v, 2);
    v += __shfl_xor_sync(0xffffffffu, v, 1);
    return v;
}
__device__ __forceinline__ void load_tileT(float* dst, const float* __restrict__ g, int tid) {
    for (int i = tid; i < MSEL*DIMX; i += 256) {
        int m = i >> 6, k = i & 63;
        dst[k*PITCH + m] = g[i];
    }
}
__device__ __forceinline__ void mm128(const float* As, const float* Bs,
                                      float acc[8][8], int ty, int tx) {
#pragma unroll 8
    for (int k = 0; k < DIMX; k++) {
        float4 a0 = *reinterpret_cast<const float4*>(&As[k*PITCH + ty*8]);
        float4 a1 = *reinterpret_cast<const float4*>(&As[k*PITCH + ty*8 + 4]);
        float4 b0 = *reinterpret_cast<const float4*>(&Bs[k*PITCH + tx*8]);
        float4 b1 = *reinterpret_cast<const float4*>(&Bs[k*PITCH + tx*8 + 4]);
        float a[8] = {a0.x,a0.y,a0.z,a0.w,a1.x,a1.y,a1.z,a1.w};
        float b[8] = {b0.x,b0.y,b0.z,b0.w,b1.x,b1.y,b1.z,b1.w};
#pragma unroll
        for (int i = 0; i < 8; i++)
#pragma unroll
            for (int j = 0; j < 8; j++)
                acc[i][j] += a[i] * b[j];
    }
}

// stage [128x64] fp32 -> split bf16 swizzled tile (128B rows, lo at +16384)
__device__ __forceinline__ void stage_sw(char* smem, int offH,
                                         const float* __restrict__ g, int tid) {
#pragma unroll
    for (int k = 0; k < 16; k++) {
        int i = tid + k * 256;
        int r = i >> 5, j = i & 31;
        float2 v = *reinterpret_cast<const float2*>(&g[r*64 + j*2]);
        __nv_bfloat16 h0, l0, h1, l1;
        bf16split(v.x, h0, l0); bf16split(v.y, h1, l1);
        uint32_t b = (uint32_t)(r*128) + (uint32_t)(((((j>>2) ^ (r&7)) << 4)) + ((j&3) << 2));
        *(__nv_bfloat162*)(smem + offH + b)         = __halves2bfloat162(h0, h1);
        *(__nv_bfloat162*)(smem + offH + 16384 + b) = __halves2bfloat162(l0, l1);
    }
}

// ======================= kernel 1: segmented top-k + sort + gather =======================
__global__ __launch_bounds__(256) void topk_gather(const float* __restrict__ Qg,
                                                   const float* __restrict__ Kg) {
    __shared__ float vals[NTOK];
    __shared__ float pmax[256];
    __shared__ int   pidx[256];
    __shared__ int   sel[MSEL];
    __shared__ int   sorted[MSEL];
    __shared__ int   bcast;
    int hh = blockIdx.x, which = blockIdx.y, tid = threadIdx.x;
    const float* src = (which == 0 ? Kg : Qg) + (size_t)hh * NTOK * DIMX;

    if (hh == 0 && which == 0 && tid == 0) d_gmax_bits = 0u;

    for (int i = tid; i < NTOK; i += 256) vals[i] = src[(size_t)i * DIMX];
    if (tid == 0) vals[0] = -3.402823466e38f;
    __syncthreads();

    {
        float bv = -3.402823466e38f; int bi = tid * 32;
        for (int j = 0; j < 32; j++) {
            float v = vals[tid*32 + j];
            if (v > bv) { bv = v; bi = tid*32 + j; }
        }
        pmax[tid] = bv; pidx[tid] = bi;
    }
    __syncthreads();

    for (int r = 0; r < MSEL - 1; r++) {
        if (tid < 32) {
            float bv = -3.402823466e38f; int bi = NTOK;
            for (int k = tid; k < 256; k += 32) {
                float v = pmax[k]; int ix = pidx[k];
                if (v > bv || (v == bv && ix < bi)) { bv = v; bi = ix; }
            }
#pragma unroll
            for (int o = 16; o > 0; o >>= 1) {
                float ov = __shfl_down_sync(0xffffffffu, bv, o);
                int   oi = __shfl_down_sync(0xffffffffu, bi, o);
                if (ov > bv || (ov == bv && oi < bi)) { bv = ov; bi = oi; }
            }
            if (tid == 0) { sel[r] = bi; vals[bi] = -3.402823466e38f; bcast = bi; }
        }
        __syncthreads();
        int win = bcast;
        if (tid == (win >> 5)) {
            float bv = -3.402823466e38f; int bi = tid * 32;
            for (int j = 0; j < 32; j++) {
                float v = vals[tid*32 + j];
                if (v > bv) { bv = v; bi = tid*32 + j; }
            }
            pmax[tid] = bv; pidx[tid] = bi;
        }
        __syncthreads();
    }
    if (tid == 0) sel[MSEL - 1] = 0;
    __syncthreads();

    if (tid < MSEL) {
        int my = sel[tid], rank = 0;
        for (int j = 0; j < MSEL; j++) rank += (sel[j] < my);
        sorted[rank] = my;
    }
    __syncthreads();

    float* dst = (which == 0 ? d_nc : d_nr) + (size_t)hh * MSEL * DIMX;
    for (int i = tid; i < MSEL * DIMX; i += 256) {
        int p = i >> 6, d = i & 63;
        dst[i] = src[(size_t)sorted[p] * DIMX + d];
    }
}

// ======================= kernel 2: kernel_2 = softmax(nr @ nc^T), colsum max =======================
__global__ __launch_bounds__(256) void mker() {
    extern __shared__ float sm[];
    float* As = sm;
    float* Bs = sm + DIMX * PITCH;
    float* cs = sm + 2 * DIMX * PITCH;
    int hh = blockIdx.x, tid = threadIdx.x;
    int ty = tid >> 4, tx = tid & 15;
    load_tileT(As, d_nr + (size_t)hh * MSEL * DIMX, tid);
    load_tileT(Bs, d_nc + (size_t)hh * MSEL * DIMX, tid);
    if (tid < MSEL) cs[tid] = 0.f;
    __syncthreads();

    float acc[8][8] = {};
    mm128(As, Bs, acc, ty, tx);

    float* K2h = d_K2m + (size_t)hh * MSEL * MSEL;
    float colp[8] = {};
#pragma unroll
    for (int i = 0; i < 8; i++) {
        float mx = acc[i][0];
#pragma unroll
        for (int j = 1; j < 8; j++) mx = fmaxf(mx, acc[i][j]);
        mx = grp_max(mx);
        float s = 0.f;
#pragma unroll
        for (int j = 0; j < 8; j++) { acc[i][j] = __expf(acc[i][j] - mx); s += acc[i][j]; }
        s = grp_sum(s);
        float inv = 1.f / s;
#pragma unroll
        for (int j = 0; j < 8; j++) {
            float p = acc[i][j] * inv;
            K2h[(ty*8 + i) * MSEL + tx*8 + j] = p;
            colp[j] += p;
        }
    }
#pragma unroll
    for (int j = 0; j < 8; j++) atomicAdd(&cs[tx*8 + j], colp[j]);
    __syncthreads();
    if (tid < MSEL) atomicMax(&d_gmax_bits, __float_as_uint(cs[tid]));
}

// ======================= MMA1 + online softmax + MMA2 tile body (P in registers) ==========
// caller stages A/B/V + __syncthreads before entry; NO smem writes inside, NO barriers.
__device__ __forceinline__ void attn_tile_reg(uint32_t sb, int wid, int lane,
                                              float C2[8][4],
                                              float& m0, float& m1, float& s0, float& s1) {
    float C1[16][4] = {};
    int aRow = wid*16 + (lane & 15);
    int aq = lane >> 4, arb = aRow & 7;
    uint32_t aBase = sb + T_A + aRow*128;
    int bRow0 = (lane & 7) + ((lane >> 4) << 3);
    int bq = (lane >> 3) & 1, brb = bRow0 & 7;
    uint32_t bBase = sb + T_B + bRow0*128;

#pragma unroll
    for (int ks = 0; ks < 4; ks++) {
        uint32_t aA = aBase + ((uint32_t)(((2*ks) | aq) ^ arb) << 4);
        uint32_t ah0, ah1, ah2, ah3, al0, al1, al2, al3;
        LDSM_X4(ah0, ah1, ah2, ah3, aA);
        LDSM_X4(al0, al1, al2, al3, aA + 16384);
#pragma unroll
        for (int p = 0; p < 8; p++) {
            uint32_t bA = bBase + p*2048 + ((uint32_t)(((2*ks) | bq) ^ brb) << 4);
            uint32_t bh0, bh1, bh2, bh3, bl0, bl1, bl2, bl3;
            LDSM_X4(bh0, bh1, bh2, bh3, bA);
            LDSM_X4(bl0, bl1, bl2, bl3, bA + 16384);
            mma_bf16(C1[2*p],   ah0, ah1, ah2, ah3, bh0, bh1);
            mma_bf16(C1[2*p+1], ah0, ah1, ah2, ah3, bh2, bh3);
            mma_bf16(C1[2*p],   ah0, ah1, ah2, ah3, bl0, bl1);
            mma_bf16(C1[2*p+1], ah0, ah1, ah2, ah3, bl2, bl3);
            mma_bf16(C1[2*p],   al0, al1, al2, al3, bh0, bh1);
            mma_bf16(C1[2*p+1], al0, al1, al2, al3, bh2, bh3);
        }
    }

    float cx0 = -3.402823466e38f, cx1 = -3.402823466e38f;
#pragma unroll
    for (int t = 0; t < 16; t++) {
        cx0 = fmaxf(cx0, fmaxf(C1[t][0], C1[t][1]));
        cx1 = fmaxf(cx1, fmaxf(C1[t][2], C1[t][3]));
    }
    cx0 = fmaxf(cx0, __shfl_xor_sync(0xffffffffu, cx0, 1));
    cx0 = fmaxf(cx0, __shfl_xor_sync(0xffffffffu, cx0, 2));
    cx1 = fmaxf(cx1, __shfl_xor_sync(0xffffffffu, cx1, 1));
    cx1 = fmaxf(cx1, __shfl_xor_sync(0xffffffffu, cx1, 2));

    float mn0 = fmaxf(m0, cx0), mn1 = fmaxf(m1, cx1);
    float f0 = __expf(m0 - mn0), f1 = __expf(m1 - mn1);
    float su0 = 0.f, su1 = 0.f;
#pragma unroll
    for (int t = 0; t < 16; t++) {
        C1[t][0] = __expf(C1[t][0] - mn0); C1[t][1] = __expf(C1[t][1] - mn0);
        C1[t][2] = __expf(C1[t][2] - mn1); C1[t][3] = __expf(C1[t][3] - mn1);
        su0 += C1[t][0] + C1[t][1];
        su1 += C1[t][2] + C1[t][3];
    }
    su0 += __shfl_xor_sync(0xffffffffu, su0, 1);
    su0 += __shfl_xor_sync(0xffffffffu, su0, 2);
    su1 += __shfl_xor_sync(0xffffffffu, su1, 1);
    su1 += __shfl_xor_sync(0xffffffffu, su1, 2);
    s0 = s0 * f0 + su0;  s1 = s1 * f1 + su1;
    m0 = mn0;            m1 = mn1;
#pragma unroll
    for (int t = 0; t < 8; t++) {
        C2[t][0] *= f0; C2[t][1] *= f0;
        C2[t][2] *= f1; C2[t][3] *= f1;
    }

    // FA2 register trick: C1 fragments == A fragments of MMA2 (n of MMA1 -> k of MMA2).
    // pA0[t]: row r, cols 2j,2j+1 of n-tile t; pA1[t]: row r+8. hi/lo split planes.
    uint32_t pA0[16], pA1[16], lA0[16], lA1[16];
#pragma unroll
    for (int t = 0; t < 16; t++) {
        pack_split2(C1[t][0], C1[t][1], pA0[t], lA0[t]);
        pack_split2(C1[t][2], C1[t][3], pA1[t], lA1[t]);
    }

    int vRow0 = lane & 15;
    int vq = lane >> 4, vrb = vRow0 & 7;
    uint32_t vBase = sb + T_V + vRow0*128;
#pragma unroll
    for (int ks = 0; ks < 8; ks++) {
        uint32_t ah0 = pA0[2*ks], ah1 = pA1[2*ks], ah2 = pA0[2*ks+1], ah3 = pA1[2*ks+1];
        uint32_t al0 = lA0[2*ks], al1 = lA1[2*ks], al2 = lA0[2*ks+1], al3 = lA1[2*ks+1];
#pragma unroll
        for (int p = 0; p < 4; p++) {
            uint32_t vA = vBase + ks*2048 + ((uint32_t)(((2*p) | vq) ^ vrb) << 4);
            uint32_t vh0, vh1, vh2, vh3, vl0, vl1, vl2, vl3;
            LDSM_X4_T(vh0, vh1, vh2, vh3, vA);
            LDSM_X4_T(vl0, vl1, vl2, vl3, vA + 16384);
            mma_bf16(C2[2*p],   ah0, ah1, ah2, ah3, vh0, vh1);
            mma_bf16(C2[2*p+1], ah0, ah1, ah2, ah3, vh2, vh3);
            mma_bf16(C2[2*p],   ah0, ah1, ah2, ah3, vl0, vl1);
            mma_bf16(C2[2*p+1], ah0, ah1, ah2, ah3, vl2, vl3);
            mma_bf16(C2[2*p],   al0, al1, al2, al3, vh0, vh1);
            mma_bf16(C2[2*p+1], al0, al1, al2, al3, vh2, vh3);
        }
    }
}

// ======================= kernel 3: flash over 8 chunks, nr staged once, 2 CTAs/SM ==========
__global__ __launch_bounds__(256, 2) void r1ker(const float* __restrict__ Kg,
                                                const float* __restrict__ Vg) {
    extern __shared__ char smem[];
    uint32_t sb = smem_to_u32(smem);
    int hh = blockIdx.x, s = blockIdx.y, tid = threadIdx.x;
    int wid = tid >> 5, lane = tid & 31;

    const float* Kbase = Kg + ((size_t)hh * NTOK + (size_t)s * CHUNKS * MSEL) * DIMX;
    const float* Vbase = Vg + ((size_t)hh * NTOK + (size_t)s * CHUNKS * MSEL) * DIMX;

    stage_sw(smem, T_A, d_nr + (size_t)hh * MSEL * DIMX, tid);   // once — never clobbered

    float C2[8][4] = {};
    float m0 = -3.402823466e38f, m1 = -3.402823466e38f, s0 = 0.f, s1 = 0.f;

#pragma unroll 1
    for (int c = 0; c < CHUNKS; c++) {
        if (c) __syncthreads();     // prior MMA1 B-reads + MMA2 V-reads complete
        stage_sw(smem, T_B, Kbase + (size_t)c * MSEL * DIMX, tid);
        stage_sw(smem, T_V, Vbase + (size_t)c * MSEL * DIMX, tid);
        __syncthreads();            // also covers the one-time A staging (c==0)
        attn_tile_reg(sb, wid, lane, C2, m0, m1, s0, s1);
    }

    size_t base = (size_t)(hh * SPLITS + s) * MSEL;
    int grow0 = wid*16 + (lane >> 2);
    int pcol = (lane & 3) * 2;
    if ((lane & 3) == 0) {
        d_pmax[base + grow0]     = m0;  d_psum[base + grow0]     = s0;
        d_pmax[base + grow0 + 8] = m1;  d_psum[base + grow0 + 8] = s1;
    }
    float* z0 = d_pZ + (base + grow0) * DIMX;
    float* z1 = z0 + 8 * DIMX;
#pragma unroll
    for (int t = 0; t < 8; t++) {
        *reinterpret_cast<float2*>(&z0[t*8 + pcol]) = make_float2(C2[t][0], C2[t][1]);
        *reinterpret_cast<float2*>(&z1[t*8 + pcol]) = make_float2(C2[t][2], C2[t][3]);
    }
}

// ======================= kernel 4: combine splits =======================
__global__ void combiner() {
    int hh = blockIdx.x;
    int r  = blockIdx.y * 16 + threadIdx.y;
    int d  = threadIdx.x * 4;
    const float* pm = d_pmax + (size_t)hh * SPLITS * MSEL;
    const float* ps = d_psum + (size_t)hh * SPLITS * MSEL;
    float M = -3.402823466e38f;
#pragma unroll
    for (int s = 0; s < SPLITS; s++) M = fmaxf(M, pm[s * MSEL + r]);
    float l = 0.f;
    float4 z = make_float4(0.f, 0.f, 0.f, 0.f);
#pragma unroll
    for (int s = 0; s < SPLITS; s++) {
        float w = __expf(pm[s * MSEL + r] - M);
        l += ps[s * MSEL + r] * w;
        float4 pz = *reinterpret_cast<const float4*>(
            &d_pZ[((size_t)(hh * SPLITS + s) * MSEL + r) * DIMX + d]);
        z.x += w * pz.x; z.y += w * pz.y; z.z += w * pz.z; z.w += w * pz.w;
    }
    float inv = 1.f / l;
    *reinterpret_cast<float4*>(&d_Zm[((size_t)hh * MSEL + r) * DIMX + d]) =
        make_float4(z.x * inv, z.y * inv, z.z * inv, z.w * inv);
}

// ======================= Newton-Schulz: 512-thread fused TC kernel =======================
__global__ __launch_bounds__(256) void vminit() {
    int hh = blockIdx.x;
    float inv = 1.f / __uint_as_float(d_gmax_bits);
    const float* K2h = d_K2m + (size_t)hh * MSEL * MSEL;
    float* Vh = d_Vm0 + (size_t)hh * MSEL * MSEL;
    for (int i = threadIdx.x; i < MSEL * MSEL; i += 256) {
        int r = i >> 7, c = i & 127;
        Vh[i] = K2h[c * MSEL + r] * inv;
    }
}

__device__ __forceinline__ void stage_split128_512(char* smem, int off,
                                                   const float* __restrict__ g, int tid) {
#pragma unroll
    for (int k = 0; k < 16; k++) {
        int i = tid + k * 512;
        int r = i >> 6, c2 = (i & 63) * 2;
        float2 v = *reinterpret_cast<const float2*>(&g[r*128 + c2]);
        __nv_bfloat16 h0, l0, h1, l1;
        bf16split(v.x, h0, l0); bf16split(v.y, h1, l1);
        int ob = r*272 + c2*2;
        *(__nv_bfloat162*)(smem + off + ob)         = __halves2bfloat162(h0, h1);
        *(__nv_bfloat162*)(smem + off + 34816 + ob) = __halves2bfloat162(l0, l1);
    }
}

__device__ __forceinline__ void mm_tc512(uint32_t sb, int offA, int offB,
                                         int rg, int cg, int lane, float C[8][4]) {
#pragma unroll
    for (int t = 0; t < 8; t++) { C[t][0] = 0.f; C[t][1] = 0.f; C[t][2] = 0.f; C[t][3] = 0.f; }
    uint32_t aH = sb + offA + (rg*16 + (lane & 15))*272 + ((lane >> 4) << 4);
    uint32_t aL = aH + 34816;
    uint32_t bH = sb + offB + (lane & 15)*272 + ((lane >> 4) << 4) + cg*128;
    uint32_t bL = bH + 34816;
#pragma unroll
    for (int ks = 0; ks < 8; ks++) {
        uint32_t ah0, ah1, ah2, ah3, al0, al1, al2, al3;
        LDSM_X4(ah0, ah1, ah2, ah3, aH + ks*32);
        LDSM_X4(al0, al1, al2, al3, aL + ks*32);
#pragma unroll
        for (int p = 0; p < 4; p++) {
            uint32_t bh0, bh1, bh2, bh3, bl0, bl1, bl2, bl3;
            LDSM_X4_T(bh0, bh1, bh2, bh3, bH + ks*4352 + p*32);
            LDSM_X4_T(bl0, bl1, bl2, bl3, bL + ks*4352 + p*32);
            mma_bf16(C[2*p],   ah0, ah1, ah2, ah3, bh0, bh1);
            mma_bf16(C[2*p+1], ah0, ah1, ah2, ah3, bh2, bh3);
            mma_bf16(C[2*p],   ah0, ah1, ah2, ah3, bl0, bl1);
            mma_bf16(C[2*p+1], ah0, ah1, ah2, ah3, bl2, bl3);
            mma_bf16(C[2*p],   al0, al1, al2, al3, bh0, bh1);
            mma_bf16(C[2*p+1], al0, al1, al2, al3, bh2, bh3);
        }
    }
}

__device__ __forceinline__ void store_split512(char* smem, int off, int rg, int cg, int lane,
                                               const float C[8][4]) {
    int r0 = rg*16 + (lane >> 2);
    int cb0 = (lane & 3) * 2;
#pragma unroll
    for (int t = 0; t < 8; t++) {
        int cb = (cg*64 + t*8 + cb0) * 2;
        __nv_bfloat16 h0, l0, h1, l1;
        bf16split(C[t][0], h0, l0); bf16split(C[t][1], h1, l1);
        *(__nv_bfloat162*)(smem + off + r0*272 + cb)         = __halves2bfloat162(h0, h1);
        *(__nv_bfloat162*)(smem + off + 34816 + r0*272 + cb) = __halves2bfloat162(l0, l1);
        bf16split(C[t][2], h0, l0); bf16split(C[t][3], h1, l1);
        *(__nv_bfloat162*)(smem + off + (r0+8)*272 + cb)         = __halves2bfloat162(h0, h1);
        *(__nv_bfloat162*)(smem + off + 34816 + (r0+8)*272 + cb) = __halves2bfloat162(l0, l1);
    }
}
__device__ __forceinline__ float read_split(const char* smem, int off, int r, int c) {
    float h = __bfloat162float(*(const __nv_bfloat16*)(smem + off + r*272 + c*2));
    float l = __bfloat162float(*(const __nv_bfloat16*)(smem + off + 34816 + r*272 + c*2));
    return h + l;
}

__global__ __launch_bounds__(512) void newton_iter() {
    extern __shared__ char smem[];
    uint32_t sb = smem_to_u32(smem);
    int hh = blockIdx.x, tid = threadIdx.x;
    int wid = tid >> 5, lane = tid & 31;
    int rg = wid & 7, cg = wid >> 3;
    float R[8][4];

    stage_split128_512(smem, NB_K, d_K2m + (size_t)hh * MSEL * MSEL, tid);
    stage_split128_512(smem, NB_V, d_Vm0 + (size_t)hh * MSEL * MSEL, tid);
    __syncthreads();

    mm_tc512(sb, NB_K, NB_V, rg, cg, lane, R);    // KV = Km @ Vm
    __syncthreads();
    store_split512(smem, NB_K, rg, cg, lane, R);  // BK <- KV
    __syncthreads();

    mm_tc512(sb, NB_K, NB_K, rg, cg, lane, R);    // P2 = KV @ KV
    __syncthreads();
    store_split512(smem, NB_T, rg, cg, lane, R);  // BT <- P2
    __syncthreads();

    mm_tc512(sb, NB_K, NB_T, rg, cg, lane, R);    // P3 = KV @ P2
    {                                              // E = 13I -15KV +7P2 -P3
        int r0 = rg*16 + (lane >> 2);
        int cb0 = (lane & 3) * 2;
#pragma unroll
        for (int t = 0; t < 8; t++) {
            int c = cg*64 + t*8 + cb0;
#pragma unroll
            for (int j = 0; j < 4; j++) {
                int rr = r0 + ((j >> 1) << 3);
                int cc = c + (j & 1);
                float kv = read_split(smem, NB_K, rr, cc);
                float p2 = read_split(smem, NB_T, rr, cc);
                float e = -15.f*kv + 7.f*p2 - R[t][j];
                if (rr == cc) e += 13.f;
                R[t][j] = e;
            }
        }
    }
    __syncthreads();
    store_split512(smem, NB_T, rg, cg, lane, R);  // BT <- E
    __syncthreads();

    mm_tc512(sb, NB_V, NB_T, rg, cg, lane, R);    // Vm @ E
    {
        float* out = d_Vm0 + (size_t)hh * MSEL * MSEL;
        int r0 = rg*16 + (lane >> 2);
        int cb0 = (lane & 3) * 2;
#pragma unroll
        for (int t = 0; t < 8; t++) {
            int c = cg*64 + t*8 + cb0;
            *reinterpret_cast<float2*>(&out[r0*128 + c]) =
                make_float2(0.25f*R[t][0], 0.25f*R[t][1]);
            *reinterpret_cast<float2*>(&out[(r0+8)*128 + c]) =
                make_float2(0.25f*R[t][2], 0.25f*R[t][3]);
        }
    }
}

// W = Vm_final @ Z  (128x64), grid (48, 2)
__global__ __launch_bounds__(256) void wker() {
    __shared__ float As[32][65];
    __shared__ float Bs[32][65];
    int hh = blockIdx.x;
    const float* Vm = d_Vm0 + (size_t)hh * MSEL * MSEL;
    const float* Z  = d_Zm + (size_t)hh * MSEL * DIMX;
    int r0 = blockIdx.y * 64;
    int tid = threadIdx.x, ty = tid >> 4, tx = tid & 15;
    float acc[4][4] = {};
    for (int kc = 0; kc < MSEL; kc += 32) {
        for (int i = tid; i < 2048; i += 256) {
            int m = i >> 5, k = i & 31;
            As[k][m] = Vm[(r0 + m) * MSEL + kc + k];
        }
        for (int i = tid; i < 2048; i += 256) {
            int k = i >> 6, n = i & 63;
            Bs[k][n] = Z[(kc + k) * DIMX + n];
        }
        __syncthreads();
#pragma unroll 8
        for (int k = 0; k < 32; k++) {
            float a[4], b[4];
#pragma unroll
            for (int i = 0; i < 4; i++) a[i] = As[k][ty*4 + i];
#pragma unroll
            for (int j = 0; j < 4; j++) b[j] = Bs[k][tx*4 + j];
#pragma unroll
            for (int i = 0; i < 4; i++)
#pragma unroll
                for (int j = 0; j < 4; j++)
                    acc[i][j] += a[i] * b[j];
        }
        __syncthreads();
    }
#pragma unroll
    for (int i = 0; i < 4; i++)
#pragma unroll
        for (int j = 0; j < 4; j++)
            d_Wm[(size_t)hh * MSEL * DIMX + (r0 + ty*4 + i) * DIMX + tx*4 + j] = acc[i][j];
}

// ======================= final: X = softmax(Q @ nc^T) @ W, nc/W staged once ==========
__global__ __launch_bounds__(256, 2) void eker(const float* __restrict__ Qg,
                                               float* __restrict__ Xg) {
    extern __shared__ char smem[];
    uint32_t sb = smem_to_u32(smem);
    int hh = blockIdx.x, tid = threadIdx.x;
    int wid = tid >> 5, lane = tid & 31;

    const float* Qbase = Qg + ((size_t)hh * NTOK + (size_t)blockIdx.y * EQC * MSEL) * DIMX;

    stage_sw(smem, T_B, d_nc + (size_t)hh * MSEL * DIMX, tid);   // once
    stage_sw(smem, T_V, d_Wm + (size_t)hh * MSEL * DIMX, tid);   // once

    int grow0 = wid*16 + (lane >> 2);
    int pcol = (lane & 3) * 2;

#pragma unroll 1
    for (int c = 0; c < EQC; c++) {
        if (c) __syncthreads();     // prior MMA1 A-reads complete before restaging A
        stage_sw(smem, T_A, Qbase + (size_t)c * MSEL * DIMX, tid);
        __syncthreads();            // also covers one-time B/V staging (c==0)

        float C2[8][4] = {};
        float m0 = -3.402823466e38f, m1 = -3.402823466e38f, s0 = 0.f, s1 = 0.f;
        attn_tile_reg(sb, wid, lane, C2, m0, m1, s0, s1);

        float rinv0 = 1.f / s0, rinv1 = 1.f / s1;
        float* x0 = Xg + ((size_t)hh * NTOK + (size_t)(blockIdx.y * EQC + c) * MSEL + grow0) * DIMX;
        float* x1 = x0 + 8 * DIMX;
#pragma unroll
        for (int t = 0; t < 8; t++) {
            *reinterpret_cast<float2*>(&x0[t*8 + pcol]) =
                make_float2(C2[t][0] * rinv0, C2[t][1] * rinv0);
            *reinterpret_cast<float2*>(&x1[t*8 + pcol]) =
                make_float2(C2[t][2] * rinv1, C2[t][3] * rinv1);
        }
    }
}

// ======================= launch (two-stream fork/join DAG) =======================
extern "C" void kernel_launch(void* const* d_in, const int* in_sizes, int n_in,
                              void* d_out, int out_size) {
    const float* Q = (const float*)d_in[0];
    const float* K = (const float*)d_in[1];
    const float* V = (const float*)d_in[2];
    float* X = (float*)d_out;

    const int SMEM_MK = (2 * DIMX * PITCH + MSEL) * 4;
    cudaFuncSetAttribute(mker,        cudaFuncAttributeMaxDynamicSharedMemorySize, SMEM_MK);
    cudaFuncSetAttribute(r1ker,       cudaFuncAttributeMaxDynamicSharedMemorySize, T_SMEM);
    cudaFuncSetAttribute(eker,        cudaFuncAttributeMaxDynamicSharedMemorySize, T_SMEM);
    cudaFuncSetAttribute(newton_iter, cudaFuncAttributeMaxDynamicSharedMemorySize, NB_SZ);

    bool fork = g_streams_ok;
    cudaStream_t sB = fork ? g_s2 : (cudaStream_t)0;

    topk_gather<<<dim3(BHX, 2), 256>>>(Q, K);

    if (fork) {
        cudaEventRecord(g_eA, 0);
        cudaStreamWaitEvent(sB, g_eA, 0);
    }
    // branch B: mker -> vminit -> 6x newton (small-grid chain)
    mker<<<BHX, 256, SMEM_MK, sB>>>();
    vminit<<<BHX, 256, 0, sB>>>();
    for (int it = 0; it < 6; it++)
        newton_iter<<<BHX, 512, NB_SZ, sB>>>();
    if (fork) cudaEventRecord(g_eB, sB);

    // branch A: r1ker -> combiner (big grid), concurrent with branch B
    r1ker<<<dim3(BHX, SPLITS), 256, T_SMEM>>>(K, V);
    combiner<<<dim3(BHX, 8), dim3(16, 16)>>>();

    if (fork) cudaStreamWaitEvent(0, g_eB, 0);
    wker<<<dim3(BHX, 2), 256>>>();
    eker<<<dim3(BHX, NTOK / MSEL / EQC), 256, T_SMEM>>>(Q, X);
}

// round 15
// speedup vs baseline: 3.0880x; 1.1541x over previous
#include <cuda_runtime.h>
#include <cuda_bf16.h>
#include <cstdint>
#include <cstddef>

#define BHX    48
#define NTOK   8192
#define DIMX   64
#define MSEL   128
#define SPLITS 8
#define CHUNKS 8
#define EQC    8
#define PITCH  132

// ======================= mma.sync / ldmatrix helpers =======================
__device__ __forceinline__ uint32_t smem_to_u32(const void* p) {
    uint32_t a;
    asm("{ .reg .u64 t; cvta.to.shared.u64 t, %1; cvt.u32.u64 %0, t; }" : "=r"(a) : "l"(p));
    return a;
}
#define LDSM_X4(r0, r1, r2, r3, addr) \
    asm volatile("ldmatrix.sync.aligned.m8n8.x4.shared.b16 {%0,%1,%2,%3}, [%4];" \
                 : "=r"(r0), "=r"(r1), "=r"(r2), "=r"(r3) : "r"(addr))
#define LDSM_X4_T(r0, r1, r2, r3, addr) \
    asm volatile("ldmatrix.sync.aligned.m8n8.x4.trans.shared.b16 {%0,%1,%2,%3}, [%4];" \
                 : "=r"(r0), "=r"(r1), "=r"(r2), "=r"(r3) : "r"(addr))
__device__ __forceinline__ void mma_bf16(float* c, uint32_t a0, uint32_t a1, uint32_t a2, uint32_t a3,
                                         uint32_t b0, uint32_t b1) {
    asm volatile("mma.sync.aligned.m16n8k16.row.col.f32.bf16.bf16.f32 "
                 "{%0,%1,%2,%3}, {%4,%5,%6,%7}, {%8,%9}, {%0,%1,%2,%3};"
                 : "+f"(c[0]), "+f"(c[1]), "+f"(c[2]), "+f"(c[3])
                 : "r"(a0), "r"(a1), "r"(a2), "r"(a3), "r"(b0), "r"(b1));
}
__device__ __forceinline__ void bf16split(float v, __nv_bfloat16& h, __nv_bfloat16& l) {
    h = __float2bfloat16(v);
    l = __float2bfloat16(v - __bfloat162float(h));
}
__device__ __forceinline__ void pack_split2(float x, float y, uint32_t& h, uint32_t& l) {
    __nv_bfloat16 hx, lx, hy, ly;
    bf16split(x, hx, lx); bf16split(y, hy, ly);
    __nv_bfloat162 hb = __halves2bfloat162(hx, hy);
    __nv_bfloat162 lb = __halves2bfloat162(lx, ly);
    h = *reinterpret_cast<uint32_t*>(&hb);
    l = *reinterpret_cast<uint32_t*>(&lb);
}

// ---- swizzled (pad-free) layouts; 96KB/CTA -> 2 CTAs/SM; P lives in registers ----
#define T_A    0
#define T_B    32768
#define T_V    65536
#define T_SMEM 98304

// newton smem: 3 matrices [128 x 136 halves] (272B pitch), hi then lo (+34816)
#define NB_K   0
#define NB_V   69632
#define NB_T   139264
#define NB_SZ  208896

// ======================= scratch =======================
__device__ float d_nc [BHX*MSEL*DIMX];
__device__ float d_nr [BHX*MSEL*DIMX];
__device__ float d_K2m[BHX*MSEL*MSEL];
__device__ float d_Vm0[BHX*MSEL*MSEL];
__device__ float d_Zm [BHX*MSEL*DIMX];
__device__ float d_Wm [BHX*MSEL*DIMX];
__device__ unsigned int d_gmax_bits;
__device__ float d_pmax[BHX*SPLITS*MSEL];
__device__ float d_psum[BHX*SPLITS*MSEL];
__device__ float d_pZ  [(size_t)BHX*SPLITS*MSEL*DIMX];

// ======================= streams/events (created at load, before capture) ==========
static cudaStream_t g_s2;
static cudaEvent_t  g_eA, g_eB;
static bool g_streams_ok = false;
namespace {
struct StreamInit {
    StreamInit() {
        g_streams_ok =
            (cudaStreamCreateWithFlags(&g_s2, cudaStreamNonBlocking) == cudaSuccess) &&
            (cudaEventCreateWithFlags(&g_eA, cudaEventDisableTiming) == cudaSuccess) &&
            (cudaEventCreateWithFlags(&g_eB, cudaEventDisableTiming) == cudaSuccess);
    }
};
static StreamInit g_stream_init;
}

// ======================= SIMT helpers =======================
__device__ __forceinline__ float grp_max(float v) {
    v = fmaxf(v, __shfl_xor_sync(0xffffffffu, v, 8));
    v = fmaxf(v, __shfl_xor_sync(0xffffffffu, v, 4));
    v = fmaxf(v, __shfl_xor_sync(0xffffffffu, v, 2));
    v = fmaxf(v, __shfl_xor_sync(0xffffffffu, v, 1));
    return v;
}
__device__ __forceinline__ float grp_sum(float v) {
    v += __shfl_xor_sync(0xffffffffu, v, 8);
    v += __shfl_xor_sync(0xffffffffu, v, 4);
    v += __shfl_xor_sync(0xffffffffu, v, 2);
    v += __shfl_xor_sync(0xffffffffu, v, 1);
    return v;
}
__device__ __forceinline__ void load_tileT(float* dst, const float* __restrict__ g, int tid) {
    for (int i = tid; i < MSEL*DIMX; i += 256) {
        int m = i >> 6, k = i & 63;
        dst[k*PITCH + m] = g[i];
    }
}
__device__ __forceinline__ void mm128(const float* As, const float* Bs,
                                      float acc[8][8], int ty, int tx) {
#pragma unroll 8
    for (int k = 0; k < DIMX; k++) {
        float4 a0 = *reinterpret_cast<const float4*>(&As[k*PITCH + ty*8]);
        float4 a1 = *reinterpret_cast<const float4*>(&As[k*PITCH + ty*8 + 4]);
        float4 b0 = *reinterpret_cast<const float4*>(&Bs[k*PITCH + tx*8]);
        float4 b1 = *reinterpret_cast<const float4*>(&Bs[k*PITCH + tx*8 + 4]);
        float a[8] = {a0.x,a0.y,a0.z,a0.w,a1.x,a1.y,a1.z,a1.w};
        float b[8] = {b0.x,b0.y,b0.z,b0.w,b1.x,b1.y,b1.z,b1.w};
#pragma unroll
        for (int i = 0; i < 8; i++)
#pragma unroll
            for (int j = 0; j < 8; j++)
                acc[i][j] += a[i] * b[j];
    }
}

// stage [128x64] fp32 -> split bf16 swizzled tile (128B rows, lo at +16384)
__device__ __forceinline__ void stage_sw(char* smem, int offH,
                                         const float* __restrict__ g, int tid) {
#pragma unroll
    for (int k = 0; k < 16; k++) {
        int i = tid + k * 256;
        int r = i >> 5, j = i & 31;
        float2 v = *reinterpret_cast<const float2*>(&g[r*64 + j*2]);
        __nv_bfloat16 h0, l0, h1, l1;
        bf16split(v.x, h0, l0); bf16split(v.y, h1, l1);
        uint32_t b = (uint32_t)(r*128) + (uint32_t)(((((j>>2) ^ (r&7)) << 4)) + ((j&3) << 2));
        *(__nv_bfloat162*)(smem + offH + b)         = __halves2bfloat162(h0, h1);
        *(__nv_bfloat162*)(smem + offH + 16384 + b) = __halves2bfloat162(l0, l1);
    }
}

// ======================= kernel 1: radix-select top-k + sort + gather =======================
// composite key c = (orderable(val) << 16) | (65535 - idx): distinct, jax top_k tie order.
__global__ __launch_bounds__(256) void topk_gather(const float* __restrict__ Qg,
                                                   const float* __restrict__ Kg) {
    __shared__ uint32_t uk[NTOK];          // 32 KB
    __shared__ unsigned int hist[256];
    __shared__ int sel[MSEL];
    __shared__ int sorted[MSEL];
    __shared__ int sh_b, sh_need, scnt;
    int hh = blockIdx.x, which = blockIdx.y, tid = threadIdx.x;
    const float* src = (which == 0 ? Kg : Qg) + (size_t)hh * NTOK * DIMX;

    if (hh == 0 && which == 0 && tid == 0) d_gmax_bits = 0u;

    for (int i = tid; i < NTOK; i += 256) {
        uint32_t b = __float_as_uint(src[(size_t)i * DIMX]);
        uk[i] = (b & 0x80000000u) ? ~b : (b | 0x80000000u);
    }
    __syncthreads();
    if (tid == 0) uk[0] = 0u;              // index 0 excluded from top-k, re-added below
    __syncthreads();

    uint64_t pref = 0;
    int need = MSEL - 1;                   // 127
#pragma unroll 1
    for (int L = 0; L < 6; L++) {
        int shift = 40 - 8 * L;
        hist[tid] = 0u;                    // 256 threads == 256 bins
        __syncthreads();
        for (int i = tid; i < NTOK; i += 256) {
            uint64_t c = ((uint64_t)uk[i] << 16) | (uint32_t)(65535 - i);
            if ((c >> (shift + 8)) == pref)
                atomicAdd(&hist[(uint32_t)(c >> shift) & 0xFFu], 1u);
        }
        __syncthreads();
        if (tid == 0) {
            int acc = 0, b = 255;
            for (; b >= 0; b--) {
                int nb = acc + (int)hist[b];
                if (nb >= need) break;
                acc = nb;
            }
            sh_b = b; sh_need = need - acc;
        }
        __syncthreads();
        pref = (pref << 8) | (uint32_t)sh_b;
        need = sh_need;
        __syncthreads();
    }
    uint64_t T = pref;                     // exact 127th-largest composite

    if (tid == 0) scnt = 0;
    __syncthreads();
    for (int i = tid; i < NTOK; i += 256) {
        uint64_t c = ((uint64_t)uk[i] << 16) | (uint32_t)(65535 - i);
        if (c >= T) { int p = atomicAdd(&scnt, 1); sel[p] = i; }
    }
    __syncthreads();
    if (tid == 0) sel[MSEL - 1] = 0;
    __syncthreads();

    if (tid < MSEL) {                      // rank sort (128 distinct indices)
        int my = sel[tid], rank = 0;
        for (int j = 0; j < MSEL; j++) rank += (sel[j] < my);
        sorted[rank] = my;
    }
    __syncthreads();

    float* dst = (which == 0 ? d_nc : d_nr) + (size_t)hh * MSEL * DIMX;
    for (int i = tid; i < MSEL * DIMX; i += 256) {
        int p = i >> 6, d = i & 63;
        dst[i] = src[(size_t)sorted[p] * DIMX + d];
    }
}

// ======================= kernel 2: kernel_2 = softmax(nr @ nc^T), colsum max =======================
__global__ __launch_bounds__(256) void mker() {
    extern __shared__ float sm[];
    float* As = sm;
    float* Bs = sm + DIMX * PITCH;
    float* cs = sm + 2 * DIMX * PITCH;
    int hh = blockIdx.x, tid = threadIdx.x;
    int ty = tid >> 4, tx = tid & 15;
    load_tileT(As, d_nr + (size_t)hh * MSEL * DIMX, tid);
    load_tileT(Bs, d_nc + (size_t)hh * MSEL * DIMX, tid);
    if (tid < MSEL) cs[tid] = 0.f;
    __syncthreads();

    float acc[8][8] = {};
    mm128(As, Bs, acc, ty, tx);

    float* K2h = d_K2m + (size_t)hh * MSEL * MSEL;
    float colp[8] = {};
#pragma unroll
    for (int i = 0; i < 8; i++) {
        float mx = acc[i][0];
#pragma unroll
        for (int j = 1; j < 8; j++) mx = fmaxf(mx, acc[i][j]);
        mx = grp_max(mx);
        float s = 0.f;
#pragma unroll
        for (int j = 0; j < 8; j++) { acc[i][j] = __expf(acc[i][j] - mx); s += acc[i][j]; }
        s = grp_sum(s);
        float inv = 1.f / s;
#pragma unroll
        for (int j = 0; j < 8; j++) {
            float p = acc[i][j] * inv;
            K2h[(ty*8 + i) * MSEL + tx*8 + j] = p;
            colp[j] += p;
        }
    }
#pragma unroll
    for (int j = 0; j < 8; j++) atomicAdd(&cs[tx*8 + j], colp[j]);
    __syncthreads();
    if (tid < MSEL) atomicMax(&d_gmax_bits, __float_as_uint(cs[tid]));
}

// ======================= MMA1 + online softmax + MMA2 tile body (P in registers) ==========
__device__ __forceinline__ void attn_tile_reg(uint32_t sb, int wid, int lane,
                                              float C2[8][4],
                                              float& m0, float& m1, float& s0, float& s1) {
    float C1[16][4] = {};
    int aRow = wid*16 + (lane & 15);
    int aq = lane >> 4, arb = aRow & 7;
    uint32_t aBase = sb + T_A + aRow*128;
    int bRow0 = (lane & 7) + ((lane >> 4) << 3);
    int bq = (lane >> 3) & 1, brb = bRow0 & 7;
    uint32_t bBase = sb + T_B + bRow0*128;

#pragma unroll
    for (int ks = 0; ks < 4; ks++) {
        uint32_t aA = aBase + ((uint32_t)(((2*ks) | aq) ^ arb) << 4);
        uint32_t ah0, ah1, ah2, ah3, al0, al1, al2, al3;
        LDSM_X4(ah0, ah1, ah2, ah3, aA);
        LDSM_X4(al0, al1, al2, al3, aA + 16384);
#pragma unroll
        for (int p = 0; p < 8; p++) {
            uint32_t bA = bBase + p*2048 + ((uint32_t)(((2*ks) | bq) ^ brb) << 4);
            uint32_t bh0, bh1, bh2, bh3, bl0, bl1, bl2, bl3;
            LDSM_X4(bh0, bh1, bh2, bh3, bA);
            LDSM_X4(bl0, bl1, bl2, bl3, bA + 16384);
            mma_bf16(C1[2*p],   ah0, ah1, ah2, ah3, bh0, bh1);
            mma_bf16(C1[2*p+1], ah0, ah1, ah2, ah3, bh2, bh3);
            mma_bf16(C1[2*p],   ah0, ah1, ah2, ah3, bl0, bl1);
            mma_bf16(C1[2*p+1], ah0, ah1, ah2, ah3, bl2, bl3);
            mma_bf16(C1[2*p],   al0, al1, al2, al3, bh0, bh1);
            mma_bf16(C1[2*p+1], al0, al1, al2, al3, bh2, bh3);
        }
    }

    float cx0 = -3.402823466e38f, cx1 = -3.402823466e38f;
#pragma unroll
    for (int t = 0; t < 16; t++) {
        cx0 = fmaxf(cx0, fmaxf(C1[t][0], C1[t][1]));
        cx1 = fmaxf(cx1, fmaxf(C1[t][2], C1[t][3]));
    }
    cx0 = fmaxf(cx0, __shfl_xor_sync(0xffffffffu, cx0, 1));
    cx0 = fmaxf(cx0, __shfl_xor_sync(0xffffffffu, cx0, 2));
    cx1 = fmaxf(cx1, __shfl_xor_sync(0xffffffffu, cx1, 1));
    cx1 = fmaxf(cx1, __shfl_xor_sync(0xffffffffu, cx1, 2));

    float mn0 = fmaxf(m0, cx0), mn1 = fmaxf(m1, cx1);
    float f0 = __expf(m0 - mn0), f1 = __expf(m1 - mn1);
    float su0 = 0.f, su1 = 0.f;
#pragma unroll
    for (int t = 0; t < 16; t++) {
        C1[t][0] = __expf(C1[t][0] - mn0); C1[t][1] = __expf(C1[t][1] - mn0);
        C1[t][2] = __expf(C1[t][2] - mn1); C1[t][3] = __expf(C1[t][3] - mn1);
        su0 += C1[t][0] + C1[t][1];
        su1 += C1[t][2] + C1[t][3];
    }
    su0 += __shfl_xor_sync(0xffffffffu, su0, 1);
    su0 += __shfl_xor_sync(0xffffffffu, su0, 2);
    su1 += __shfl_xor_sync(0xffffffffu, su1, 1);
    su1 += __shfl_xor_sync(0xffffffffu, su1, 2);
    s0 = s0 * f0 + su0;  s1 = s1 * f1 + su1;
    m0 = mn0;            m1 = mn1;
#pragma unroll
    for (int t = 0; t < 8; t++) {
        C2[t][0] *= f0; C2[t][1] *= f0;
        C2[t][2] *= f1; C2[t][3] *= f1;
    }

    // FA2 register trick: C1 fragments are MMA2 A-fragments directly.
    uint32_t pA0[16], pA1[16], lA0[16], lA1[16];
#pragma unroll
    for (int t = 0; t < 16; t++) {
        pack_split2(C1[t][0], C1[t][1], pA0[t], lA0[t]);
        pack_split2(C1[t][2], C1[t][3], pA1[t], lA1[t]);
    }

    int vRow0 = lane & 15;
    int vq = lane >> 4, vrb = vRow0 & 7;
    uint32_t vBase = sb + T_V + vRow0*128;
#pragma unroll
    for (int ks = 0; ks < 8; ks++) {
        uint32_t ah0 = pA0[2*ks], ah1 = pA1[2*ks], ah2 = pA0[2*ks+1], ah3 = pA1[2*ks+1];
        uint32_t al0 = lA0[2*ks], al1 = lA1[2*ks], al2 = lA0[2*ks+1], al3 = lA1[2*ks+1];
#pragma unroll
        for (int p = 0; p < 4; p++) {
            uint32_t vA = vBase + ks*2048 + ((uint32_t)(((2*p) | vq) ^ vrb) << 4);
            uint32_t vh0, vh1, vh2, vh3, vl0, vl1, vl2, vl3;
            LDSM_X4_T(vh0, vh1, vh2, vh3, vA);
            LDSM_X4_T(vl0, vl1, vl2, vl3, vA + 16384);
            mma_bf16(C2[2*p],   ah0, ah1, ah2, ah3, vh0, vh1);
            mma_bf16(C2[2*p+1], ah0, ah1, ah2, ah3, vh2, vh3);
            mma_bf16(C2[2*p],   ah0, ah1, ah2, ah3, vl0, vl1);
            mma_bf16(C2[2*p+1], ah0, ah1, ah2, ah3, vl2, vl3);
            mma_bf16(C2[2*p],   al0, al1, al2, al3, vh0, vh1);
            mma_bf16(C2[2*p+1], al0, al1, al2, al3, vh2, vh3);
        }
    }
}

// ======================= kernel 3: flash over 8 chunks, nr staged once, 2 CTAs/SM ==========
__global__ __launch_bounds__(256, 2) void r1ker(const float* __restrict__ Kg,
                                                const float* __restrict__ Vg) {
    extern __shared__ char smem[];
    uint32_t sb = smem_to_u32(smem);
    int hh = blockIdx.x, s = blockIdx.y, tid = threadIdx.x;
    int wid = tid >> 5, lane = tid & 31;

    const float* Kbase = Kg + ((size_t)hh * NTOK + (size_t)s * CHUNKS * MSEL) * DIMX;
    const float* Vbase = Vg + ((size_t)hh * NTOK + (size_t)s * CHUNKS * MSEL) * DIMX;

    stage_sw(smem, T_A, d_nr + (size_t)hh * MSEL * DIMX, tid);   // once — never clobbered

    float C2[8][4] = {};
    float m0 = -3.402823466e38f, m1 = -3.402823466e38f, s0 = 0.f, s1 = 0.f;

#pragma unroll 1
    for (int c = 0; c < CHUNKS; c++) {
        if (c) __syncthreads();
        stage_sw(smem, T_B, Kbase + (size_t)c * MSEL * DIMX, tid);
        stage_sw(smem, T_V, Vbase + (size_t)c * MSEL * DIMX, tid);
        __syncthreads();
        attn_tile_reg(sb, wid, lane, C2, m0, m1, s0, s1);
    }

    size_t base = (size_t)(hh * SPLITS + s) * MSEL;
    int grow0 = wid*16 + (lane >> 2);
    int pcol = (lane & 3) * 2;
    if ((lane & 3) == 0) {
        d_pmax[base + grow0]     = m0;  d_psum[base + grow0]     = s0;
        d_pmax[base + grow0 + 8] = m1;  d_psum[base + grow0 + 8] = s1;
    }
    float* z0 = d_pZ + (base + grow0) * DIMX;
    float* z1 = z0 + 8 * DIMX;
#pragma unroll
    for (int t = 0; t < 8; t++) {
        *reinterpret_cast<float2*>(&z0[t*8 + pcol]) = make_float2(C2[t][0], C2[t][1]);
        *reinterpret_cast<float2*>(&z1[t*8 + pcol]) = make_float2(C2[t][2], C2[t][3]);
    }
}

// ======================= kernel 4: combine splits =======================
__global__ void combiner() {
    int hh = blockIdx.x;
    int r  = blockIdx.y * 16 + threadIdx.y;
    int d  = threadIdx.x * 4;
    const float* pm = d_pmax + (size_t)hh * SPLITS * MSEL;
    const float* ps = d_psum + (size_t)hh * SPLITS * MSEL;
    float M = -3.402823466e38f;
#pragma unroll
    for (int s = 0; s < SPLITS; s++) M = fmaxf(M, pm[s * MSEL + r]);
    float l = 0.f;
    float4 z = make_float4(0.f, 0.f, 0.f, 0.f);
#pragma unroll
    for (int s = 0; s < SPLITS; s++) {
        float w = __expf(pm[s * MSEL + r] - M);
        l += ps[s * MSEL + r] * w;
        float4 pz = *reinterpret_cast<const float4*>(
            &d_pZ[((size_t)(hh * SPLITS + s) * MSEL + r) * DIMX + d]);
        z.x += w * pz.x; z.y += w * pz.y; z.z += w * pz.z; z.w += w * pz.w;
    }
    float inv = 1.f / l;
    *reinterpret_cast<float4*>(&d_Zm[((size_t)hh * MSEL + r) * DIMX + d]) =
        make_float4(z.x * inv, z.y * inv, z.z * inv, z.w * inv);
}

// ======================= Newton-Schulz: single persistent 512-thread TC kernel ==========
__device__ __forceinline__ void stage_split128_512(char* smem, int off,
                                                   const float* __restrict__ g, int tid) {
#pragma unroll
    for (int k = 0; k < 16; k++) {
        int i = tid + k * 512;
        int r = i >> 6, c2 = (i & 63) * 2;
        float2 v = *reinterpret_cast<const float2*>(&g[r*128 + c2]);
        __nv_bfloat16 h0, l0, h1, l1;
        bf16split(v.x, h0, l0); bf16split(v.y, h1, l1);
        int ob = r*272 + c2*2;
        *(__nv_bfloat162*)(smem + off + ob)         = __halves2bfloat162(h0, h1);
        *(__nv_bfloat162*)(smem + off + 34816 + ob) = __halves2bfloat162(l0, l1);
    }
}
// stage transposed+scaled: buf[r][c] = g[c][r]*inv  (vminit fused)
__device__ __forceinline__ void stage_split128T(char* smem, int off,
                                                const float* __restrict__ g, float inv, int tid) {
#pragma unroll
    for (int k = 0; k < 16; k++) {
        int i = tid + k * 512;
        int r = i >> 6, c2 = (i & 63) * 2;
        float vx = g[c2*128 + r] * inv;
        float vy = g[(c2+1)*128 + r] * inv;
        __nv_bfloat16 h0, l0, h1, l1;
        bf16split(vx, h0, l0); bf16split(vy, h1, l1);
        int ob = r*272 + c2*2;
        *(__nv_bfloat162*)(smem + off + ob)         = __halves2bfloat162(h0, h1);
        *(__nv_bfloat162*)(smem + off + 34816 + ob) = __halves2bfloat162(l0, l1);
    }
}

__device__ __forceinline__ void mm_tc512(uint32_t sb, int offA, int offB,
                                         int rg, int cg, int lane, float C[8][4]) {
#pragma unroll
    for (int t = 0; t < 8; t++) { C[t][0] = 0.f; C[t][1] = 0.f; C[t][2] = 0.f; C[t][3] = 0.f; }
    uint32_t aH = sb + offA + (rg*16 + (lane & 15))*272 + ((lane >> 4) << 4);
    uint32_t aL = aH + 34816;
    uint32_t bH = sb + offB + (lane & 15)*272 + ((lane >> 4) << 4) + cg*128;
    uint32_t bL = bH + 34816;
#pragma unroll
    for (int ks = 0; ks < 8; ks++) {
        uint32_t ah0, ah1, ah2, ah3, al0, al1, al2, al3;
        LDSM_X4(ah0, ah1, ah2, ah3, aH + ks*32);
        LDSM_X4(al0, al1, al2, al3, aL + ks*32);
#pragma unroll
        for (int p = 0; p < 4; p++) {
            uint32_t bh0, bh1, bh2, bh3, bl0, bl1, bl2, bl3;
            LDSM_X4_T(bh0, bh1, bh2, bh3, bH + ks*4352 + p*32);
            LDSM_X4_T(bl0, bl1, bl2, bl3, bL + ks*4352 + p*32);
            mma_bf16(C[2*p],   ah0, ah1, ah2, ah3, bh0, bh1);
            mma_bf16(C[2*p+1], ah0, ah1, ah2, ah3, bh2, bh3);
            mma_bf16(C[2*p],   ah0, ah1, ah2, ah3, bl0, bl1);
            mma_bf16(C[2*p+1], ah0, ah1, ah2, ah3, bl2, bl3);
            mma_bf16(C[2*p],   al0, al1, al2, al3, bh0, bh1);
            mma_bf16(C[2*p+1], al0, al1, al2, al3, bh2, bh3);
        }
    }
}

__device__ __forceinline__ void store_split512(char* smem, int off, int rg, int cg, int lane,
                                               const float C[8][4]) {
    int r0 = rg*16 + (lane >> 2);
    int cb0 = (lane & 3) * 2;
#pragma unroll
    for (int t = 0; t < 8; t++) {
        int cb = (cg*64 + t*8 + cb0) * 2;
        __nv_bfloat16 h0, l0, h1, l1;
        bf16split(C[t][0], h0, l0); bf16split(C[t][1], h1, l1);
        *(__nv_bfloat162*)(smem + off + r0*272 + cb)         = __halves2bfloat162(h0, h1);
        *(__nv_bfloat162*)(smem + off + 34816 + r0*272 + cb) = __halves2bfloat162(l0, l1);
        bf16split(C[t][2], h0, l0); bf16split(C[t][3], h1, l1);
        *(__nv_bfloat162*)(smem + off + (r0+8)*272 + cb)         = __halves2bfloat162(h0, h1);
        *(__nv_bfloat162*)(smem + off + 34816 + (r0+8)*272 + cb) = __halves2bfloat162(l0, l1);
    }
}
__device__ __forceinline__ float read_split(const char* smem, int off, int r, int c) {
    float h = __bfloat162float(*(const __nv_bfloat16*)(smem + off + r*272 + c*2));
    float l = __bfloat162float(*(const __nv_bfloat16*)(smem + off + 34816 + r*272 + c*2));
    return h + l;
}

__global__ __launch_bounds__(512) void newton_persist() {
    extern __shared__ char smem[];
    uint32_t sb = smem_to_u32(smem);
    int hh = blockIdx.x, tid = threadIdx.x;
    int wid = tid >> 5, lane = tid & 31;
    int rg = wid & 7, cg = wid >> 3;
    float R[8][4];
    const float* K2g = d_K2m + (size_t)hh * MSEL * MSEL;
    float inv = 1.f / __uint_as_float(d_gmax_bits);

    // Vm0 = K2^T / gmax, staged straight into NB_V (vminit fused)
    stage_split128T(smem, NB_V, K2g, inv, tid);

#pragma unroll 1
    for (int it = 0; it < 6; it++) {
        stage_split128_512(smem, NB_K, K2g, tid);   // NB_K <- K2 (fresh each iter)
        __syncthreads();

        mm_tc512(sb, NB_K, NB_V, rg, cg, lane, R);  // KV = K2 @ Vm
        __syncthreads();
        store_split512(smem, NB_K, rg, cg, lane, R);
        __syncthreads();

        mm_tc512(sb, NB_K, NB_K, rg, cg, lane, R);  // P2 = KV @ KV
        __syncthreads();
        store_split512(smem, NB_T, rg, cg, lane, R);
        __syncthreads();

        mm_tc512(sb, NB_K, NB_T, rg, cg, lane, R);  // P3 = KV @ P2
        {                                            // E = 13I -15KV +7P2 -P3
            int r0 = rg*16 + (lane >> 2);
            int cb0 = (lane & 3) * 2;
#pragma unroll
            for (int t = 0; t < 8; t++) {
                int c = cg*64 + t*8 + cb0;
#pragma unroll
                for (int j = 0; j < 4; j++) {
                    int rr = r0 + ((j >> 1) << 3);
                    int cc = c + (j & 1);
                    float kv = read_split(smem, NB_K, rr, cc);
                    float p2 = read_split(smem, NB_T, rr, cc);
                    float e = -15.f*kv + 7.f*p2 - R[t][j];
                    if (rr == cc) e += 13.f;
                    R[t][j] = e;
                }
            }
        }
        __syncthreads();
        store_split512(smem, NB_T, rg, cg, lane, R); // NB_T <- E
        __syncthreads();

        mm_tc512(sb, NB_V, NB_T, rg, cg, lane, R);   // Vm @ E
        __syncthreads();                             // NB_V reads done before overwrite
#pragma unroll
        for (int t = 0; t < 8; t++) {
            R[t][0] *= 0.25f; R[t][1] *= 0.25f; R[t][2] *= 0.25f; R[t][3] *= 0.25f;
        }
        store_split512(smem, NB_V, rg, cg, lane, R); // Vm_next (split, as before via gmem)
        if (it == 5) {
            float* out = d_Vm0 + (size_t)hh * MSEL * MSEL;
            int r0 = rg*16 + (lane >> 2);
            int cb0 = (lane & 3) * 2;
#pragma unroll
            for (int t = 0; t < 8; t++) {
                int c = cg*64 + t*8 + cb0;
                *reinterpret_cast<float2*>(&out[r0*128 + c]) = make_float2(R[t][0], R[t][1]);
                *reinterpret_cast<float2*>(&out[(r0+8)*128 + c]) = make_float2(R[t][2], R[t][3]);
            }
        }
        __syncthreads();
    }
}

// W = Vm_final @ Z  (128x64), grid (48, 2)
__global__ __launch_bounds__(256) void wker() {
    __shared__ float As[32][65];
    __shared__ float Bs[32][65];
    int hh = blockIdx.x;
    const float* Vm = d_Vm0 + (size_t)hh * MSEL * MSEL;
    const float* Z  = d_Zm + (size_t)hh * MSEL * DIMX;
    int r0 = blockIdx.y * 64;
    int tid = threadIdx.x, ty = tid >> 4, tx = tid & 15;
    float acc[4][4] = {};
    for (int kc = 0; kc < MSEL; kc += 32) {
        for (int i = tid; i < 2048; i += 256) {
            int m = i >> 5, k = i & 31;
            As[k][m] = Vm[(r0 + m) * MSEL + kc + k];
        }
        for (int i = tid; i < 2048; i += 256) {
            int k = i >> 6, n = i & 63;
            Bs[k][n] = Z[(kc + k) * DIMX + n];
        }
        __syncthreads();
#pragma unroll 8
        for (int k = 0; k < 32; k++) {
            float a[4], b[4];
#pragma unroll
            for (int i = 0; i < 4; i++) a[i] = As[k][ty*4 + i];
#pragma unroll
            for (int j = 0; j < 4; j++) b[j] = Bs[k][tx*4 + j];
#pragma unroll
            for (int i = 0; i < 4; i++)
#pragma unroll
                for (int j = 0; j < 4; j++)
                    acc[i][j] += a[i] * b[j];
        }
        __syncthreads();
    }
#pragma unroll
    for (int i = 0; i < 4; i++)
#pragma unroll
        for (int j = 0; j < 4; j++)
            d_Wm[(size_t)hh * MSEL * DIMX + (r0 + ty*4 + i) * DIMX + tx*4 + j] = acc[i][j];
}

// ======================= final: X = softmax(Q @ nc^T) @ W, nc/W staged once ==========
__global__ __launch_bounds__(256, 2) void eker(const float* __restrict__ Qg,
                                               float* __restrict__ Xg) {
    extern __shared__ char smem[];
    uint32_t sb = smem_to_u32(smem);
    int hh = blockIdx.x, tid = threadIdx.x;
    int wid = tid >> 5, lane = tid & 31;

    const float* Qbase = Qg + ((size_t)hh * NTOK + (size_t)blockIdx.y * EQC * MSEL) * DIMX;

    stage_sw(smem, T_B, d_nc + (size_t)hh * MSEL * DIMX, tid);   // once
    stage_sw(smem, T_V, d_Wm + (size_t)hh * MSEL * DIMX, tid);   // once

    int grow0 = wid*16 + (lane >> 2);
    int pcol = (lane & 3) * 2;

#pragma unroll 1
    for (int c = 0; c < EQC; c++) {
        if (c) __syncthreads();
        stage_sw(smem, T_A, Qbase + (size_t)c * MSEL * DIMX, tid);
        __syncthreads();

        float C2[8][4] = {};
        float m0 = -3.402823466e38f, m1 = -3.402823466e38f, s0 = 0.f, s1 = 0.f;
        attn_tile_reg(sb, wid, lane, C2, m0, m1, s0, s1);

        float rinv0 = 1.f / s0, rinv1 = 1.f / s1;
        float* x0 = Xg + ((size_t)hh * NTOK + (size_t)(blockIdx.y * EQC + c) * MSEL + grow0) * DIMX;
        float* x1 = x0 + 8 * DIMX;
#pragma unroll
        for (int t = 0; t < 8; t++) {
            *reinterpret_cast<float2*>(&x0[t*8 + pcol]) =
                make_float2(C2[t][0] * rinv0, C2[t][1] * rinv0);
            *reinterpret_cast<float2*>(&x1[t*8 + pcol]) =
                make_float2(C2[t][2] * rinv1, C2[t][3] * rinv1);
        }
    }
}

// ======================= launch (two-stream fork/join DAG) =======================
extern "C" void kernel_launch(void* const* d_in, const int* in_sizes, int n_in,
                              void* d_out, int out_size) {
    const float* Q = (const float*)d_in[0];
    const float* K = (const float*)d_in[1];
    const float* V = (const float*)d_in[2];
    float* X = (float*)d_out;

    const int SMEM_MK = (2 * DIMX * PITCH + MSEL) * 4;
    cudaFuncSetAttribute(mker,           cudaFuncAttributeMaxDynamicSharedMemorySize, SMEM_MK);
    cudaFuncSetAttribute(r1ker,          cudaFuncAttributeMaxDynamicSharedMemorySize, T_SMEM);
    cudaFuncSetAttribute(eker,           cudaFuncAttributeMaxDynamicSharedMemorySize, T_SMEM);
    cudaFuncSetAttribute(newton_persist, cudaFuncAttributeMaxDynamicSharedMemorySize, NB_SZ);

    bool fork = g_streams_ok;
    cudaStream_t sB = fork ? g_s2 : (cudaStream_t)0;

    topk_gather<<<dim3(BHX, 2), 256>>>(Q, K);

    if (fork) {
        cudaEventRecord(g_eA, 0);
        cudaStreamWaitEvent(sB, g_eA, 0);
    }
    // branch B: mker -> persistent newton
    mker<<<BHX, 256, SMEM_MK, sB>>>();
    newton_persist<<<BHX, 512, NB_SZ, sB>>>();
    if (fork) cudaEventRecord(g_eB, sB);

    // branch A: r1ker -> combiner, concurrent with branch B
    r1ker<<<dim3(BHX, SPLITS), 256, T_SMEM>>>(K, V);
    combiner<<<dim3(BHX, 8), dim3(16, 16)>>>();

    if (fork) cudaStreamWaitEvent(0, g_eB, 0);
    wker<<<dim3(BHX, 2), 256>>>();
    eker<<<dim3(BHX, NTOK / MSEL / EQC), 256, T_SMEM>>>(Q, X);
}